// round 1
// baseline (speedup 1.0000x reference)
#include <cuda_runtime.h>
#include <cuda_bf16.h>
#include <math.h>

// ---------------- problem constants ----------------
#define NH    22501           // rows of h (cls + 22500)
#define NF    22500           // feature tokens after square-pad
#define NFEAT 22400           // original features
#define HW    150             // 150x150 grid
#define C     512
#define NP    22528           // padded seq len inside nystrom
#define PADN  27
#define HEADS 8
#define DH    64
#define MM    256             // landmarks
#define LL    88              // tokens per landmark
#define QKVW  1536

// ---------------- scratch (device globals; no allocation allowed) ----------------
__device__ float g_h    [(long)NH*C];
__device__ float g_h2   [(long)NH*C];
__device__ float g_xp   [(long)NP*C];
__device__ float g_qkv  [(long)NP*QKVW];
__device__ float g_ql   [HEADS*MM*DH];
__device__ float g_kl   [HEADS*MM*DH];
__device__ float g_S    [(long)HEADS*NP*MM];   // reused: S3 then S1
__device__ float g_a2   [HEADS*MM*MM];
__device__ float g_z    [HEADS*MM*MM];
__device__ float g_z2   [HEADS*MM*MM];
__device__ float g_xz   [HEADS*MM*MM];
__device__ float g_t    [HEADS*MM*MM];
__device__ float g_u    [HEADS*MM*MM];
__device__ float g_a3v  [HEADS*MM*DH];
__device__ float g_W    [HEADS*MM*DH];
__device__ float g_attn [(long)NP*C];
__device__ float g_outl [(long)NH*C];
__device__ float g_rowsum[HEADS*MM];
__device__ float g_colsum[HEADS*MM];
__device__ float g_scale[1];

// ---------------- generic batched SGEMM: C = alpha * A @ op(B) ----------------
// TB=false: B is [K,N] (ldb row stride). TB=true: B is [N,K].
template<bool TB>
__global__ __launch_bounds__(256)
void sgemm_k(const float* __restrict__ A, const float* __restrict__ B,
             float* __restrict__ Cm,
             int M, int N, int K, int lda, int ldb, int ldc,
             long sA, long sB, long sC, float alpha)
{
    A  += (long)blockIdx.z * sA;
    B  += (long)blockIdx.z * sB;
    Cm += (long)blockIdx.z * sC;

    __shared__ float As[16][65];
    __shared__ float Bs[16][65];

    const int tx = threadIdx.x;          // 0..15
    const int ty = threadIdx.y;          // 0..15
    const int tid = ty * 16 + tx;
    const int row0 = blockIdx.y * 64;
    const int col0 = blockIdx.x * 64;

    float acc[4][4];
    #pragma unroll
    for (int i = 0; i < 4; i++)
        #pragma unroll
        for (int j = 0; j < 4; j++) acc[i][j] = 0.f;

    for (int k0 = 0; k0 < K; k0 += 16) {
        // A tile: 64 rows x 16 k
        #pragma unroll
        for (int i = 0; i < 4; i++) {
            int r  = (tid >> 4) + i * 16;   // 0..63
            int kk = tid & 15;
            int gr = row0 + r, gk = k0 + kk;
            float v = 0.f;
            if (gr < M && gk < K) v = A[(long)gr * lda + gk];
            As[kk][r] = v;
        }
        // B tile: 16 k x 64 cols
        if (TB) {
            #pragma unroll
            for (int i = 0; i < 4; i++) {
                int kk = tid & 15;
                int c  = (tid >> 4) + i * 16;
                int gc = col0 + c, gk = k0 + kk;
                float v = 0.f;
                if (gc < N && gk < K) v = B[(long)gc * ldb + gk];
                Bs[kk][c] = v;
            }
        } else {
            #pragma unroll
            for (int i = 0; i < 4; i++) {
                int c  = tid & 63;
                int kk = (tid >> 6) + i * 4;
                int gc = col0 + c, gk = k0 + kk;
                float v = 0.f;
                if (gc < N && gk < K) v = B[(long)gk * ldb + gc];
                Bs[kk][c] = v;
            }
        }
        __syncthreads();

        #pragma unroll
        for (int kk = 0; kk < 16; kk++) {
            float a[4], b[4];
            #pragma unroll
            for (int i = 0; i < 4; i++) a[i] = As[kk][ty * 4 + i];
            #pragma unroll
            for (int j = 0; j < 4; j++) b[j] = Bs[kk][tx * 4 + j];
            #pragma unroll
            for (int i = 0; i < 4; i++)
                #pragma unroll
                for (int j = 0; j < 4; j++) acc[i][j] += a[i] * b[j];
        }
        __syncthreads();
    }

    #pragma unroll
    for (int i = 0; i < 4; i++) {
        int gr = row0 + ty * 4 + i;
        if (gr >= M) continue;
        #pragma unroll
        for (int j = 0; j < 4; j++) {
            int gc = col0 + tx * 4 + j;
            if (gc < N) Cm[(long)gr * ldc + gc] = alpha * acc[i][j];
        }
    }
}

static inline void launch_gemm(bool tb, const float* A, const float* B, float* Cm,
                               int M, int N, int K, int lda, int ldb, int ldc,
                               long sA, long sB, long sC, int batch, float alpha)
{
    dim3 g((N + 63) / 64, (M + 63) / 64, batch), b(16, 16);
    if (tb) sgemm_k<true ><<<g, b>>>(A, B, Cm, M, N, K, lda, ldb, ldc, sA, sB, sC, alpha);
    else    sgemm_k<false><<<g, b>>>(A, B, Cm, M, N, K, lda, ldb, ldc, sA, sB, sC, alpha);
}

// ---------------- build h = [cls ; features ; features[:100]] ----------------
__global__ void build_h_k(const float* __restrict__ feat, const float* __restrict__ cls,
                          float* __restrict__ h)
{
    long i = (long)blockIdx.x * 256 + threadIdx.x;
    if (i >= (long)NH * C) return;
    long t = i >> 9;
    int  c = (int)(i & 511);
    float v;
    if (t == 0) v = cls[c];
    else {
        long r = t - 1;
        if (r >= NFEAT) r -= NFEAT;
        v = feat[r * C + c];
    }
    h[i] = v;
}

// ---------------- layernorm of h rows into front-padded xp ----------------
__global__ void ln_pad_k(const float* __restrict__ h, float* __restrict__ xp,
                         const float* __restrict__ g, const float* __restrict__ b)
{
    int t = blockIdx.x, c = threadIdx.x;     // 256 threads, 2 cols each
    float* out = xp + (long)t * C;
    if (t < PADN) { out[c] = 0.f; out[c + 256] = 0.f; return; }
    const float* row = h + (long)(t - PADN) * C;
    float a1 = row[c], a2 = row[c + 256];
    __shared__ float red[256];
    red[c] = a1 + a2; __syncthreads();
    for (int s = 128; s > 0; s >>= 1) { if (c < s) red[c] += red[c + s]; __syncthreads(); }
    float mu = red[0] * (1.f / 512.f);
    __syncthreads();
    float d1 = a1 - mu, d2 = a2 - mu;
    red[c] = d1 * d1 + d2 * d2; __syncthreads();
    for (int s = 128; s > 0; s >>= 1) { if (c < s) red[c] += red[c + s]; __syncthreads(); }
    float inv = rsqrtf(red[0] * (1.f / 512.f) + 1e-5f);
    out[c]       = d1 * inv * g[c]       + b[c];
    out[c + 256] = d2 * inv * g[c + 256] + b[c + 256];
}

// ---------------- landmarks: mean over 88-token groups (q pre-scaled) ----------------
__global__ void landmarks_k(const float* __restrict__ qkv,
                            float* __restrict__ ql, float* __restrict__ kl)
{
    int d = threadIdx.x;                       // 0..63
    int m = blockIdx.x & 255;
    int hh = blockIdx.x >> 8;
    const float* base = qkv + (long)(m * LL) * QKVW + hh * DH + d;
    float sq = 0.f, sk = 0.f;
    for (int j = 0; j < LL; j++) {
        sq += base[(long)j * QKVW];
        sk += base[(long)j * QKVW + 512];
    }
    ql[(hh * MM + m) * DH + d] = sq * (0.125f / (float)LL);   // * DH^-0.5 / l
    kl[(hh * MM + m) * DH + d] = sk * (1.f / (float)LL);
}

// ---------------- softmax, 256 cols, one warp per row ----------------
__global__ void softmax256_k(float* __restrict__ S, long nrows)
{
    long row = (long)blockIdx.x * 8 + threadIdx.y;
    if (row >= nrows) return;
    float* r = S + row * 256;
    int lane = threadIdx.x;
    float v[8], m = -1e30f;
    #pragma unroll
    for (int i = 0; i < 8; i++) { v[i] = r[lane + 32 * i]; m = fmaxf(m, v[i]); }
    #pragma unroll
    for (int o = 16; o; o >>= 1) m = fmaxf(m, __shfl_xor_sync(0xffffffffu, m, o));
    float s = 0.f;
    #pragma unroll
    for (int i = 0; i < 8; i++) { v[i] = __expf(v[i] - m); s += v[i]; }
    #pragma unroll
    for (int o = 16; o; o >>= 1) s += __shfl_xor_sync(0xffffffffu, s, o);
    float inv = 1.f / s;
    #pragma unroll
    for (int i = 0; i < 8; i++) r[lane + 32 * i] = v[i] * inv;
}

// ---------------- softmax, long rows (NP cols), one block per row ----------------
__global__ void softmax_long_k(float* __restrict__ S, int cols)
{
    float* row = S + (long)blockIdx.x * cols;
    __shared__ float red[256];
    int tid = threadIdx.x;
    float m = -1e30f;
    for (int i = tid; i < cols; i += 256) m = fmaxf(m, row[i]);
    red[tid] = m; __syncthreads();
    for (int s = 128; s > 0; s >>= 1) { if (tid < s) red[tid] = fmaxf(red[tid], red[tid + s]); __syncthreads(); }
    m = red[0]; __syncthreads();
    float sum = 0.f;
    for (int i = tid; i < cols; i += 256) { float e = __expf(row[i] - m); row[i] = e; sum += e; }
    red[tid] = sum; __syncthreads();
    for (int s = 128; s > 0; s >>= 1) { if (tid < s) red[tid] += red[tid + s]; __syncthreads(); }
    float inv = 1.f / red[0];
    for (int i = tid; i < cols; i += 256) row[i] *= inv;
}

// ---------------- pinv init helpers ----------------
__global__ void pinv_sums_k(const float* __restrict__ a2,
                            float* __restrict__ rs, float* __restrict__ cs)
{
    int hh = blockIdx.x, j = threadIdx.x;
    const float* X = a2 + (long)hh * MM * MM;
    float r = 0.f, c = 0.f;
    for (int k = 0; k < MM; k++) { r += fabsf(X[j * MM + k]); c += fabsf(X[k * MM + j]); }
    rs[hh * MM + j] = r; cs[hh * MM + j] = c;
}
__global__ void pinv_scale_k(const float* __restrict__ rs, const float* __restrict__ cs,
                             float* __restrict__ scale)
{
    __shared__ float m1[256], m2[256];
    float a = -1e30f, b = -1e30f;
    for (int i = threadIdx.x; i < HEADS * MM; i += 256) { a = fmaxf(a, rs[i]); b = fmaxf(b, cs[i]); }
    m1[threadIdx.x] = a; m2[threadIdx.x] = b; __syncthreads();
    for (int s = 128; s > 0; s >>= 1) {
        if (threadIdx.x < s) {
            m1[threadIdx.x] = fmaxf(m1[threadIdx.x], m1[threadIdx.x + s]);
            m2[threadIdx.x] = fmaxf(m2[threadIdx.x], m2[threadIdx.x + s]);
        }
        __syncthreads();
    }
    if (threadIdx.x == 0) scale[0] = 1.f / (m1[0] * m2[0]);
}
__global__ void pinv_init_k(const float* __restrict__ a2, float* __restrict__ z,
                            const float* __restrict__ scale)
{
    long i = (long)blockIdx.x * 256 + threadIdx.x;
    if (i >= (long)HEADS * MM * MM) return;
    long hh = i >> 16; int r = (int)((i >> 8) & 255), c = (int)(i & 255);
    z[i] = a2[(hh << 16) + ((long)c << 8) + r] * scale[0];
}
// out = alpha*I - in
__global__ void axpyI_k(const float* __restrict__ in, float* __restrict__ out, float alpha)
{
    long i = (long)blockIdx.x * 256 + threadIdx.x;
    if (i >= (long)HEADS * MM * MM) return;
    int r = (int)((i >> 8) & 255), c = (int)(i & 255);
    out[i] = (r == c ? alpha : 0.f) - in[i];
}

// ---------------- depthwise 33-tap conv over sequence of v, added into attn ----------------
__global__ void conv_add_k(const float* __restrict__ qkv, const float* __restrict__ rw,
                           float* __restrict__ attn)
{
    int t = blockIdx.x, c = threadIdx.x;   // 512 threads
    int hh = c >> 6;
    float acc = 0.f;
    #pragma unroll
    for (int k = 0; k < 33; k++) {
        int tt = t + k - 16;
        if ((unsigned)tt < (unsigned)NP)
            acc += qkv[(long)tt * QKVW + 1024 + c] * rw[hh * 33 + k];
    }
    attn[(long)t * C + c] += acc;
}

// ---------------- residual: h += lin + bias ----------------
__global__ void resid_add_k(float* __restrict__ h, const float* __restrict__ lin,
                            const float* __restrict__ bias)
{
    long i = (long)blockIdx.x * 256 + threadIdx.x;
    if (i >= (long)NH * C) return;
    h[i] += lin[i] + bias[i & 511];
}

// ---------------- PPEG: identity + dw7 + dw5 + dw3 + biases ----------------
__global__ void ppeg_k(const float* __restrict__ h, float* __restrict__ h2,
                       const float* __restrict__ w7, const float* __restrict__ b7,
                       const float* __restrict__ w5, const float* __restrict__ b5,
                       const float* __restrict__ w3, const float* __restrict__ b3)
{
    int x = blockIdx.x, y = blockIdx.y, c = threadIdx.x;  // 512 threads
    if (x == 0 && y == 0) h2[c] = h[c];                    // cls passthrough
    float acc = h[(long)(1 + y * HW + x) * C + c];         // identity
    #pragma unroll
    for (int ky = 0; ky < 7; ky++) {
        int yy = y + ky - 3; if (yy < 0 || yy >= HW) continue;
        #pragma unroll
        for (int kx = 0; kx < 7; kx++) {
            int xx = x + kx - 3; if (xx < 0 || xx >= HW) continue;
            acc += h[(long)(1 + yy * HW + xx) * C + c] * w7[c * 49 + ky * 7 + kx];
        }
    }
    #pragma unroll
    for (int ky = 0; ky < 5; ky++) {
        int yy = y + ky - 2; if (yy < 0 || yy >= HW) continue;
        #pragma unroll
        for (int kx = 0; kx < 5; kx++) {
            int xx = x + kx - 2; if (xx < 0 || xx >= HW) continue;
            acc += h[(long)(1 + yy * HW + xx) * C + c] * w5[c * 25 + ky * 5 + kx];
        }
    }
    #pragma unroll
    for (int ky = 0; ky < 3; ky++) {
        int yy = y + ky - 1; if (yy < 0 || yy >= HW) continue;
        #pragma unroll
        for (int kx = 0; kx < 3; kx++) {
            int xx = x + kx - 1; if (xx < 0 || xx >= HW) continue;
            acc += h[(long)(1 + yy * HW + xx) * C + c] * w3[c * 9 + ky * 3 + kx];
        }
    }
    acc += b7[c] + b5[c] + b3[c];
    h2[(long)(1 + y * HW + x) * C + c] = acc;
}

// ================= host orchestration =================
struct Ptrs {
    float *h, *h2, *xp, *qkv, *ql, *kl, *S, *a2, *z, *z2, *xz, *t, *u,
          *a3v, *W, *attn, *outl, *rowsum, *colsum, *scale;
};

static void get_ptrs(Ptrs& p)
{
    cudaGetSymbolAddress((void**)&p.h,    g_h);
    cudaGetSymbolAddress((void**)&p.h2,   g_h2);
    cudaGetSymbolAddress((void**)&p.xp,   g_xp);
    cudaGetSymbolAddress((void**)&p.qkv,  g_qkv);
    cudaGetSymbolAddress((void**)&p.ql,   g_ql);
    cudaGetSymbolAddress((void**)&p.kl,   g_kl);
    cudaGetSymbolAddress((void**)&p.S,    g_S);
    cudaGetSymbolAddress((void**)&p.a2,   g_a2);
    cudaGetSymbolAddress((void**)&p.z,    g_z);
    cudaGetSymbolAddress((void**)&p.z2,   g_z2);
    cudaGetSymbolAddress((void**)&p.xz,   g_xz);
    cudaGetSymbolAddress((void**)&p.t,    g_t);
    cudaGetSymbolAddress((void**)&p.u,    g_u);
    cudaGetSymbolAddress((void**)&p.a3v,  g_a3v);
    cudaGetSymbolAddress((void**)&p.W,    g_W);
    cudaGetSymbolAddress((void**)&p.attn, g_attn);
    cudaGetSymbolAddress((void**)&p.outl, g_outl);
    cudaGetSymbolAddress((void**)&p.rowsum, g_rowsum);
    cudaGetSymbolAddress((void**)&p.colsum, g_colsum);
    cudaGetSymbolAddress((void**)&p.scale,  g_scale);
}

static void nystrom_layer(Ptrs& p, float* h_io,
                          const float* ln_g, const float* ln_b,
                          const float* w_qkv, const float* w_out, const float* b_out,
                          const float* res_w)
{
    const long MMh = (long)MM * MM;          // per-head 256x256
    const long Sst = (long)NP * MM;          // per-head S stride

    // 1) LN + front pad
    ln_pad_k<<<NP, 256>>>(h_io, p.xp, ln_g, ln_b);

    // 2) qkv = xp @ w_qkv   [NP x 1536]
    launch_gemm(false, p.xp, w_qkv, p.qkv, NP, QKVW, C, C, QKVW, QKVW, 0, 0, 0, 1, 1.f);

    // 3) landmarks
    landmarks_k<<<HEADS * MM, DH>>>(p.qkv, p.ql, p.kl);

    // 4) a2 = softmax(q_l @ k_l^T)
    launch_gemm(true, p.ql, p.kl, p.a2, MM, MM, DH, DH, DH, MM,
                (long)MM * DH, (long)MM * DH, MMh, HEADS, 1.f);
    softmax256_k<<<(HEADS * MM + 7) / 8, dim3(32, 8)>>>(p.a2, HEADS * MM);

    // 5) pinv_iter(a2) -> z
    pinv_sums_k<<<HEADS, 256>>>(p.a2, p.rowsum, p.colsum);
    pinv_scale_k<<<1, 256>>>(p.rowsum, p.colsum, p.scale);
    pinv_init_k<<<(int)((HEADS * MMh + 255) / 256), 256>>>(p.a2, p.z, p.scale);
    float* zc = p.z; float* zn = p.z2;
    int nblk = (int)((HEADS * MMh + 255) / 256);
    for (int it = 0; it < 6; it++) {
        launch_gemm(false, p.a2, zc, p.xz, MM, MM, MM, MM, MM, MM, MMh, MMh, MMh, HEADS, 1.f);
        axpyI_k<<<nblk, 256>>>(p.xz, p.t, 7.f);
        launch_gemm(false, p.xz, p.t, p.u, MM, MM, MM, MM, MM, MM, MMh, MMh, MMh, HEADS, 1.f);
        axpyI_k<<<nblk, 256>>>(p.u, p.t, 15.f);
        launch_gemm(false, p.xz, p.t, p.u, MM, MM, MM, MM, MM, MM, MMh, MMh, MMh, HEADS, 1.f);
        axpyI_k<<<nblk, 256>>>(p.u, p.t, 13.f);
        launch_gemm(false, zc, p.t, zn, MM, MM, MM, MM, MM, MM, MMh, MMh, MMh, HEADS, 0.25f);
        float* tmp = zc; zc = zn; zn = tmp;
    }

    // 6) S3 = q_l @ k^T  [8, 256, NP], softmax, a3v = S3 @ v  [8,256,64]
    launch_gemm(true, p.ql, p.qkv + 512, p.S, MM, NP, DH, DH, QKVW, NP,
                (long)MM * DH, 64, Sst, HEADS, 1.f);
    softmax_long_k<<<HEADS * MM, 256>>>(p.S, NP);
    launch_gemm(false, p.S, p.qkv + 1024, p.a3v, MM, DH, NP, NP, QKVW, DH,
                Sst, 64, (long)MM * DH, HEADS, 1.f);

    // 7) W = pinv @ a3v
    launch_gemm(false, zc, p.a3v, p.W, MM, DH, MM, MM, DH, DH,
                MMh, (long)MM * DH, (long)MM * DH, HEADS, 1.f);

    // 8) S1 = (q * dh^-.5) @ k_l^T  [8, NP, 256], softmax, O1 = S1 @ W -> attn cols
    launch_gemm(true, p.qkv, p.kl, p.S, NP, MM, DH, QKVW, DH, MM,
                64, (long)MM * DH, Sst, HEADS, 0.125f);
    softmax256_k<<<(int)(((long)HEADS * NP + 7) / 8), dim3(32, 8)>>>(p.S, (long)HEADS * NP);
    launch_gemm(false, p.S, p.W, p.attn, NP, DH, MM, MM, DH, C,
                Sst, (long)MM * DH, 64, HEADS, 1.f);

    // 9) += depthwise conv of v over sequence
    conv_add_k<<<NP, C>>>(p.qkv, res_w, p.attn);

    // 10) out = attn[PADN:] @ w_out ; h += out + b
    launch_gemm(false, p.attn + (long)PADN * C, w_out, p.outl, NH, C, C, C, C, C,
                0, 0, 0, 1, 1.f);
    resid_add_k<<<(int)(((long)NH * C + 255) / 256), 256>>>(h_io, p.outl, b_out);
}

extern "C" void kernel_launch(void* const* d_in, const int* in_sizes, int n_in,
                              void* d_out, int out_size)
{
    const float* features = (const float*)d_in[0];
    const float* cls      = (const float*)d_in[1];
    const float* ln1_g    = (const float*)d_in[2];
    const float* ln1_b    = (const float*)d_in[3];
    const float* qkv1_w   = (const float*)d_in[4];
    const float* out1_w   = (const float*)d_in[5];
    const float* out1_b   = (const float*)d_in[6];
    const float* res1_w   = (const float*)d_in[7];
    const float* pe_w7    = (const float*)d_in[8];
    const float* pe_b7    = (const float*)d_in[9];
    const float* pe_w5    = (const float*)d_in[10];
    const float* pe_b5    = (const float*)d_in[11];
    const float* pe_w3    = (const float*)d_in[12];
    const float* pe_b3    = (const float*)d_in[13];
    const float* ln2_g    = (const float*)d_in[14];
    const float* ln2_b    = (const float*)d_in[15];
    const float* qkv2_w   = (const float*)d_in[16];
    const float* out2_w   = (const float*)d_in[17];
    const float* out2_b   = (const float*)d_in[18];
    const float* res2_w   = (const float*)d_in[19];

    Ptrs p; get_ptrs(p);

    // h = [cls ; features ; features[:100]]
    build_h_k<<<(int)(((long)NH * C + 255) / 256), 256>>>(features, cls, p.h);

    // layer 1
    nystrom_layer(p, p.h, ln1_g, ln1_b, qkv1_w, out1_w, out1_b, res1_w);

    // PPEG: h -> h2
    ppeg_k<<<dim3(HW, HW), C>>>(p.h, p.h2, pe_w7, pe_b7, pe_w5, pe_b5, pe_w3, pe_b3);

    // layer 2 (in place on h2)
    nystrom_layer(p, p.h2, ln2_g, ln2_b, qkv2_w, out2_w, out2_b, res2_w);

    // output = h2 flattened: [cls(512) , features(22500*512)]
    cudaMemcpyAsync(d_out, p.h2, (size_t)out_size * sizeof(float),
                    cudaMemcpyDeviceToDevice);
}

// round 2
// speedup vs baseline: 1.0067x; 1.0067x over previous
#include <cuda_runtime.h>
#include <cuda_bf16.h>
#include <math.h>

// ---------------- problem constants ----------------
#define NH    22501           // rows of h (cls + 22500)
#define NFEAT 22400           // original features
#define HW    150             // 150x150 grid
#define C     512
#define NP    22528           // padded seq len inside nystrom
#define PADN  27
#define HEADS 8
#define DH    64
#define MM    256             // landmarks
#define LL    88              // tokens per landmark
#define QKVW  1536

// ---------------- scratch (device globals; no allocation allowed) ----------------
__device__ float g_h    [(long)NH*C];
__device__ float g_h2   [(long)NH*C];
__device__ float g_xp   [(long)NP*C];
__device__ float g_qkv  [(long)NP*QKVW];
__device__ float g_ql   [HEADS*MM*DH];
__device__ float g_kl   [HEADS*MM*DH];
__device__ float g_S    [(long)HEADS*NP*MM];   // reused: S3 then S1
__device__ float g_a2   [HEADS*MM*MM];
__device__ float g_z    [HEADS*MM*MM];
__device__ float g_z2   [HEADS*MM*MM];
__device__ float g_xz   [HEADS*MM*MM];
__device__ float g_t    [HEADS*MM*MM];
__device__ float g_u    [HEADS*MM*MM];
__device__ float g_a3v  [HEADS*MM*DH];
__device__ float g_W    [HEADS*MM*DH];
__device__ float g_attn [(long)NP*C];
__device__ float g_outl [(long)NH*C];
__device__ float g_rowsum[HEADS*MM];
__device__ float g_colsum[HEADS*MM];
__device__ float g_scale[1];

// ---------------- tf32 helpers ----------------
__device__ __forceinline__ unsigned hi_tf32(float x)
{
    unsigned u;
    asm("cvt.rna.tf32.f32 %0, %1;" : "=r"(u) : "f"(x));
    return u;
}
__device__ __forceinline__ void split_tf32(float x, unsigned& h, unsigned& l)
{
    h = hi_tf32(x);
    l = hi_tf32(x - __uint_as_float(h));
}

#define MMA_TF32(c, a0, a1, a2, a3, b0, b1)                                  \
    asm volatile("mma.sync.aligned.m16n8k8.row.col.f32.tf32.tf32.f32 "       \
                 "{%0,%1,%2,%3},{%4,%5,%6,%7},{%8,%9},{%0,%1,%2,%3};"        \
                 : "+f"(c[0]), "+f"(c[1]), "+f"(c[2]), "+f"(c[3])            \
                 : "r"(a0), "r"(a1), "r"(a2), "r"(a3), "r"(b0), "r"(b1))

// ---------------- batched GEMM via 3xTF32 tensor cores ----------------
// C = alpha * A @ op(B).  TB=false: B is [K,N]. TB=true: B is [N,K].
// Requirements (all call sites satisfy): K % 32 == 0, N % 64 == 0,
// lda/ldb multiples of 4, 16B-aligned base pointers. Only M may be ragged.
#define BM 64
#define BN 64
#define BK 32

template<bool TB>
__global__ __launch_bounds__(256)
void gemm_tc(const float* __restrict__ A, const float* __restrict__ B,
             float* __restrict__ Cm,
             int M, int N, int K, int lda, int ldb, int ldc,
             long sA, long sB, long sC, float alpha)
{
    __shared__ unsigned Ah[BM][44], Al[BM][44];   // [m][k]
    __shared__ unsigned Bh[BN][33], Bl[BN][33];   // [n][k]

    A  += (long)blockIdx.z * sA;
    B  += (long)blockIdx.z * sB;
    Cm += (long)blockIdx.z * sC;

    const int tid  = threadIdx.x;
    const int lane = tid & 31;
    const int warp = tid >> 5;
    const int wm   = warp >> 1;   // 0..3 -> 16-row slab
    const int wn   = warp & 1;    // 0..1 -> 32-col slab
    const int row0 = blockIdx.y * BM;
    const int col0 = blockIdx.x * BN;
    const int r = lane >> 2, q = lane & 3;

    float c[4][4];
    #pragma unroll
    for (int i = 0; i < 4; i++)
        #pragma unroll
        for (int j = 0; j < 4; j++) c[i][j] = 0.f;

    for (int k0 = 0; k0 < K; k0 += BK) {
        // ---- A tile: 64 rows x 32 k, store as [m][k] hi/lo ----
        #pragma unroll
        for (int i = 0; i < 2; i++) {
            int idx = tid + 256 * i;          // 0..511
            int m = idx >> 3, kq = idx & 7;
            float4 v = make_float4(0.f, 0.f, 0.f, 0.f);
            int gm = row0 + m;
            if (gm < M)
                v = *reinterpret_cast<const float4*>(A + (long)gm * lda + k0 + 4 * kq);
            unsigned h0, h1, h2, h3, l0, l1, l2, l3;
            split_tf32(v.x, h0, l0); split_tf32(v.y, h1, l1);
            split_tf32(v.z, h2, l2); split_tf32(v.w, h3, l3);
            *reinterpret_cast<uint4*>(&Ah[m][4 * kq]) = make_uint4(h0, h1, h2, h3);
            *reinterpret_cast<uint4*>(&Al[m][4 * kq]) = make_uint4(l0, l1, l2, l3);
        }
        // ---- B tile -> [n][k] hi/lo ----
        if (TB) {
            #pragma unroll
            for (int i = 0; i < 2; i++) {
                int idx = tid + 256 * i;
                int n = idx >> 3, kq = idx & 7;
                float4 v = *reinterpret_cast<const float4*>(
                    B + (long)(col0 + n) * ldb + k0 + 4 * kq);
                unsigned h, l;
                split_tf32(v.x, h, l); Bh[n][4*kq+0] = h; Bl[n][4*kq+0] = l;
                split_tf32(v.y, h, l); Bh[n][4*kq+1] = h; Bl[n][4*kq+1] = l;
                split_tf32(v.z, h, l); Bh[n][4*kq+2] = h; Bl[n][4*kq+2] = l;
                split_tf32(v.w, h, l); Bh[n][4*kq+3] = h; Bl[n][4*kq+3] = l;
            }
        } else {
            #pragma unroll
            for (int i = 0; i < 2; i++) {
                int idx = tid + 256 * i;
                int k = idx >> 4, nq = idx & 15;
                float4 v = *reinterpret_cast<const float4*>(
                    B + (long)(k0 + k) * ldb + col0 + 4 * nq);
                unsigned h, l;
                split_tf32(v.x, h, l); Bh[4*nq+0][k] = h; Bl[4*nq+0][k] = l;
                split_tf32(v.y, h, l); Bh[4*nq+1][k] = h; Bl[4*nq+1][k] = l;
                split_tf32(v.z, h, l); Bh[4*nq+2][k] = h; Bl[4*nq+2][k] = l;
                split_tf32(v.w, h, l); Bh[4*nq+3][k] = h; Bl[4*nq+3][k] = l;
            }
        }
        __syncthreads();

        #pragma unroll
        for (int k8 = 0; k8 < BK; k8 += 8) {
            const int mrow = wm * 16 + r;
            unsigned ah0 = Ah[mrow][k8+q],     ah1 = Ah[mrow+8][k8+q];
            unsigned ah2 = Ah[mrow][k8+q+4],   ah3 = Ah[mrow+8][k8+q+4];
            unsigned al0 = Al[mrow][k8+q],     al1 = Al[mrow+8][k8+q];
            unsigned al2 = Al[mrow][k8+q+4],   al3 = Al[mrow+8][k8+q+4];
            #pragma unroll
            for (int nt = 0; nt < 4; nt++) {
                int nb = wn * 32 + nt * 8;
                unsigned bh0 = Bh[nb + r][k8+q], bh1 = Bh[nb + r][k8+q+4];
                unsigned bl0 = Bl[nb + r][k8+q], bl1 = Bl[nb + r][k8+q+4];
                MMA_TF32(c[nt], ah0, ah1, ah2, ah3, bh0, bh1);
                MMA_TF32(c[nt], ah0, ah1, ah2, ah3, bl0, bl1);
                MMA_TF32(c[nt], al0, al1, al2, al3, bh0, bh1);
            }
        }
        __syncthreads();
    }

    // ---- epilogue ----
    #pragma unroll
    for (int nt = 0; nt < 4; nt++) {
        int gr = row0 + wm * 16 + r;
        int gc = col0 + wn * 32 + nt * 8 + 2 * q;
        if (gr < M) {
            Cm[(long)gr * ldc + gc]     = alpha * c[nt][0];
            Cm[(long)gr * ldc + gc + 1] = alpha * c[nt][1];
        }
        if (gr + 8 < M) {
            Cm[(long)(gr + 8) * ldc + gc]     = alpha * c[nt][2];
            Cm[(long)(gr + 8) * ldc + gc + 1] = alpha * c[nt][3];
        }
    }
}

static inline void launch_gemm(bool tb, const float* A, const float* B, float* Cm,
                               int M, int N, int K, int lda, int ldb, int ldc,
                               long sA, long sB, long sC, int batch, float alpha)
{
    dim3 g((N + BN - 1) / BN, (M + BM - 1) / BM, batch), b(256);
    if (tb) gemm_tc<true ><<<g, b>>>(A, B, Cm, M, N, K, lda, ldb, ldc, sA, sB, sC, alpha);
    else    gemm_tc<false><<<g, b>>>(A, B, Cm, M, N, K, lda, ldb, ldc, sA, sB, sC, alpha);
}

// ---------------- build h = [cls ; features ; features[:100]] ----------------
__global__ void build_h_k(const float* __restrict__ feat, const float* __restrict__ cls,
                          float* __restrict__ h)
{
    long i = (long)blockIdx.x * 256 + threadIdx.x;
    if (i >= (long)NH * C) return;
    long t = i >> 9;
    int  c = (int)(i & 511);
    float v;
    if (t == 0) v = cls[c];
    else {
        long r = t - 1;
        if (r >= NFEAT) r -= NFEAT;
        v = feat[r * C + c];
    }
    h[i] = v;
}

// ---------------- layernorm of h rows into front-padded xp ----------------
__global__ void ln_pad_k(const float* __restrict__ h, float* __restrict__ xp,
                         const float* __restrict__ g, const float* __restrict__ b)
{
    int t = blockIdx.x, c = threadIdx.x;     // 256 threads, 2 cols each
    float* out = xp + (long)t * C;
    if (t < PADN) { out[c] = 0.f; out[c + 256] = 0.f; return; }
    const float* row = h + (long)(t - PADN) * C;
    float a1 = row[c], a2 = row[c + 256];
    __shared__ float red[256];
    red[c] = a1 + a2; __syncthreads();
    for (int s = 128; s > 0; s >>= 1) { if (c < s) red[c] += red[c + s]; __syncthreads(); }
    float mu = red[0] * (1.f / 512.f);
    __syncthreads();
    float d1 = a1 - mu, d2 = a2 - mu;
    red[c] = d1 * d1 + d2 * d2; __syncthreads();
    for (int s = 128; s > 0; s >>= 1) { if (c < s) red[c] += red[c + s]; __syncthreads(); }
    float inv = rsqrtf(red[0] * (1.f / 512.f) + 1e-5f);
    out[c]       = d1 * inv * g[c]       + b[c];
    out[c + 256] = d2 * inv * g[c + 256] + b[c + 256];
}

// ---------------- landmarks: mean over 88-token groups (q pre-scaled) ----------------
__global__ void landmarks_k(const float* __restrict__ qkv,
                            float* __restrict__ ql, float* __restrict__ kl)
{
    int d = threadIdx.x;                       // 0..63
    int m = blockIdx.x & 255;
    int hh = blockIdx.x >> 8;
    const float* base = qkv + (long)(m * LL) * QKVW + hh * DH + d;
    float sq = 0.f, sk = 0.f;
    for (int j = 0; j < LL; j++) {
        sq += base[(long)j * QKVW];
        sk += base[(long)j * QKVW + 512];
    }
    ql[(hh * MM + m) * DH + d] = sq * (0.125f / (float)LL);   // * DH^-0.5 / l
    kl[(hh * MM + m) * DH + d] = sk * (1.f / (float)LL);
}

// ---------------- softmax, 256 cols, one warp per row ----------------
__global__ void softmax256_k(float* __restrict__ S, long nrows)
{
    long row = (long)blockIdx.x * 8 + threadIdx.y;
    if (row >= nrows) return;
    float* r = S + row * 256;
    int lane = threadIdx.x;
    float v[8], m = -1e30f;
    #pragma unroll
    for (int i = 0; i < 8; i++) { v[i] = r[lane + 32 * i]; m = fmaxf(m, v[i]); }
    #pragma unroll
    for (int o = 16; o; o >>= 1) m = fmaxf(m, __shfl_xor_sync(0xffffffffu, m, o));
    float s = 0.f;
    #pragma unroll
    for (int i = 0; i < 8; i++) { v[i] = __expf(v[i] - m); s += v[i]; }
    #pragma unroll
    for (int o = 16; o; o >>= 1) s += __shfl_xor_sync(0xffffffffu, s, o);
    float inv = 1.f / s;
    #pragma unroll
    for (int i = 0; i < 8; i++) r[lane + 32 * i] = v[i] * inv;
}

// ---------------- softmax, long rows (NP cols), one block per row ----------------
__global__ void softmax_long_k(float* __restrict__ S, int cols)
{
    float* row = S + (long)blockIdx.x * cols;
    __shared__ float red[256];
    int tid = threadIdx.x;
    float m = -1e30f;
    for (int i = tid; i < cols; i += 256) m = fmaxf(m, row[i]);
    red[tid] = m; __syncthreads();
    for (int s = 128; s > 0; s >>= 1) { if (tid < s) red[tid] = fmaxf(red[tid], red[tid + s]); __syncthreads(); }
    m = red[0]; __syncthreads();
    float sum = 0.f;
    for (int i = tid; i < cols; i += 256) { float e = __expf(row[i] - m); row[i] = e; sum += e; }
    red[tid] = sum; __syncthreads();
    for (int s = 128; s > 0; s >>= 1) { if (tid < s) red[tid] += red[tid + s]; __syncthreads(); }
    float inv = 1.f / red[0];
    for (int i = tid; i < cols; i += 256) row[i] *= inv;
}

// ---------------- pinv init helpers ----------------
__global__ void pinv_sums_k(const float* __restrict__ a2,
                            float* __restrict__ rs, float* __restrict__ cs)
{
    int hh = blockIdx.x, j = threadIdx.x;
    const float* X = a2 + (long)hh * MM * MM;
    float r = 0.f, c = 0.f;
    for (int k = 0; k < MM; k++) { r += fabsf(X[j * MM + k]); c += fabsf(X[k * MM + j]); }
    rs[hh * MM + j] = r; cs[hh * MM + j] = c;
}
__global__ void pinv_scale_k(const float* __restrict__ rs, const float* __restrict__ cs,
                             float* __restrict__ scale)
{
    __shared__ float m1[256], m2[256];
    float a = -1e30f, b = -1e30f;
    for (int i = threadIdx.x; i < HEADS * MM; i += 256) { a = fmaxf(a, rs[i]); b = fmaxf(b, cs[i]); }
    m1[threadIdx.x] = a; m2[threadIdx.x] = b; __syncthreads();
    for (int s = 128; s > 0; s >>= 1) {
        if (threadIdx.x < s) {
            m1[threadIdx.x] = fmaxf(m1[threadIdx.x], m1[threadIdx.x + s]);
            m2[threadIdx.x] = fmaxf(m2[threadIdx.x], m2[threadIdx.x + s]);
        }
        __syncthreads();
    }
    if (threadIdx.x == 0) scale[0] = 1.f / (m1[0] * m2[0]);
}
__global__ void pinv_init_k(const float* __restrict__ a2, float* __restrict__ z,
                            const float* __restrict__ scale)
{
    long i = (long)blockIdx.x * 256 + threadIdx.x;
    if (i >= (long)HEADS * MM * MM) return;
    long hh = i >> 16; int r = (int)((i >> 8) & 255), c = (int)(i & 255);
    z[i] = a2[(hh << 16) + ((long)c << 8) + r] * scale[0];
}
// out = alpha*I - in
__global__ void axpyI_k(const float* __restrict__ in, float* __restrict__ out, float alpha)
{
    long i = (long)blockIdx.x * 256 + threadIdx.x;
    if (i >= (long)HEADS * MM * MM) return;
    int r = (int)((i >> 8) & 255), c = (int)(i & 255);
    out[i] = (r == c ? alpha : 0.f) - in[i];
}

// ---------------- depthwise 33-tap conv over sequence of v, added into attn ----------------
__global__ void conv_add_k(const float* __restrict__ qkv, const float* __restrict__ rw,
                           float* __restrict__ attn)
{
    int t = blockIdx.x, c = threadIdx.x;   // 512 threads
    int hh = c >> 6;
    float acc = 0.f;
    #pragma unroll
    for (int k = 0; k < 33; k++) {
        int tt = t + k - 16;
        if ((unsigned)tt < (unsigned)NP)
            acc += qkv[(long)tt * QKVW + 1024 + c] * rw[hh * 33 + k];
    }
    attn[(long)t * C + c] += acc;
}

// ---------------- residual: h += lin + bias ----------------
__global__ void resid_add_k(float* __restrict__ h, const float* __restrict__ lin,
                            const float* __restrict__ bias)
{
    long i = (long)blockIdx.x * 256 + threadIdx.x;
    if (i >= (long)NH * C) return;
    h[i] += lin[i] + bias[i & 511];
}

// ---------------- PPEG: identity + dw7 + dw5 + dw3 + biases ----------------
__global__ void ppeg_k(const float* __restrict__ h, float* __restrict__ h2,
                       const float* __restrict__ w7, const float* __restrict__ b7,
                       const float* __restrict__ w5, const float* __restrict__ b5,
                       const float* __restrict__ w3, const float* __restrict__ b3)
{
    int x = blockIdx.x, y = blockIdx.y, c = threadIdx.x;  // 512 threads
    if (x == 0 && y == 0) h2[c] = h[c];                    // cls passthrough
    float acc = h[(long)(1 + y * HW + x) * C + c];         // identity
    #pragma unroll
    for (int ky = 0; ky < 7; ky++) {
        int yy = y + ky - 3; if (yy < 0 || yy >= HW) continue;
        #pragma unroll
        for (int kx = 0; kx < 7; kx++) {
            int xx = x + kx - 3; if (xx < 0 || xx >= HW) continue;
            acc += h[(long)(1 + yy * HW + xx) * C + c] * w7[c * 49 + ky * 7 + kx];
        }
    }
    #pragma unroll
    for (int ky = 0; ky < 5; ky++) {
        int yy = y + ky - 2; if (yy < 0 || yy >= HW) continue;
        #pragma unroll
        for (int kx = 0; kx < 5; kx++) {
            int xx = x + kx - 2; if (xx < 0 || xx >= HW) continue;
            acc += h[(long)(1 + yy * HW + xx) * C + c] * w5[c * 25 + ky * 5 + kx];
        }
    }
    #pragma unroll
    for (int ky = 0; ky < 3; ky++) {
        int yy = y + ky - 1; if (yy < 0 || yy >= HW) continue;
        #pragma unroll
        for (int kx = 0; kx < 3; kx++) {
            int xx = x + kx - 1; if (xx < 0 || xx >= HW) continue;
            acc += h[(long)(1 + yy * HW + xx) * C + c] * w3[c * 9 + ky * 3 + kx];
        }
    }
    acc += b7[c] + b5[c] + b3[c];
    h2[(long)(1 + y * HW + x) * C + c] = acc;
}

// ================= host orchestration =================
struct Ptrs {
    float *h, *h2, *xp, *qkv, *ql, *kl, *S, *a2, *z, *z2, *xz, *t, *u,
          *a3v, *W, *attn, *outl, *rowsum, *colsum, *scale;
};

static void get_ptrs(Ptrs& p)
{
    cudaGetSymbolAddress((void**)&p.h,    g_h);
    cudaGetSymbolAddress((void**)&p.h2,   g_h2);
    cudaGetSymbolAddress((void**)&p.xp,   g_xp);
    cudaGetSymbolAddress((void**)&p.qkv,  g_qkv);
    cudaGetSymbolAddress((void**)&p.ql,   g_ql);
    cudaGetSymbolAddress((void**)&p.kl,   g_kl);
    cudaGetSymbolAddress((void**)&p.S,    g_S);
    cudaGetSymbolAddress((void**)&p.a2,   g_a2);
    cudaGetSymbolAddress((void**)&p.z,    g_z);
    cudaGetSymbolAddress((void**)&p.z2,   g_z2);
    cudaGetSymbolAddress((void**)&p.xz,   g_xz);
    cudaGetSymbolAddress((void**)&p.t,    g_t);
    cudaGetSymbolAddress((void**)&p.u,    g_u);
    cudaGetSymbolAddress((void**)&p.a3v,  g_a3v);
    cudaGetSymbolAddress((void**)&p.W,    g_W);
    cudaGetSymbolAddress((void**)&p.attn, g_attn);
    cudaGetSymbolAddress((void**)&p.outl, g_outl);
    cudaGetSymbolAddress((void**)&p.rowsum, g_rowsum);
    cudaGetSymbolAddress((void**)&p.colsum, g_colsum);
    cudaGetSymbolAddress((void**)&p.scale,  g_scale);
}

static void nystrom_layer(Ptrs& p, float* h_io,
                          const float* ln_g, const float* ln_b,
                          const float* w_qkv, const float* w_out, const float* b_out,
                          const float* res_w)
{
    const long MMh = (long)MM * MM;          // per-head 256x256
    const long Sst = (long)NP * MM;          // per-head S stride

    // 1) LN + front pad
    ln_pad_k<<<NP, 256>>>(h_io, p.xp, ln_g, ln_b);

    // 2) qkv = xp @ w_qkv   [NP x 1536]
    launch_gemm(false, p.xp, w_qkv, p.qkv, NP, QKVW, C, C, QKVW, QKVW, 0, 0, 0, 1, 1.f);

    // 3) landmarks
    landmarks_k<<<HEADS * MM, DH>>>(p.qkv, p.ql, p.kl);

    // 4) a2 = softmax(q_l @ k_l^T)
    launch_gemm(true, p.ql, p.kl, p.a2, MM, MM, DH, DH, DH, MM,
                (long)MM * DH, (long)MM * DH, MMh, HEADS, 1.f);
    softmax256_k<<<(HEADS * MM + 7) / 8, dim3(32, 8)>>>(p.a2, HEADS * MM);

    // 5) pinv_iter(a2) -> z
    pinv_sums_k<<<HEADS, 256>>>(p.a2, p.rowsum, p.colsum);
    pinv_scale_k<<<1, 256>>>(p.rowsum, p.colsum, p.scale);
    pinv_init_k<<<(int)((HEADS * MMh + 255) / 256), 256>>>(p.a2, p.z, p.scale);
    float* zc = p.z; float* zn = p.z2;
    int nblk = (int)((HEADS * MMh + 255) / 256);
    for (int it = 0; it < 6; it++) {
        launch_gemm(false, p.a2, zc, p.xz, MM, MM, MM, MM, MM, MM, MMh, MMh, MMh, HEADS, 1.f);
        axpyI_k<<<nblk, 256>>>(p.xz, p.t, 7.f);
        launch_gemm(false, p.xz, p.t, p.u, MM, MM, MM, MM, MM, MM, MMh, MMh, MMh, HEADS, 1.f);
        axpyI_k<<<nblk, 256>>>(p.u, p.t, 15.f);
        launch_gemm(false, p.xz, p.t, p.u, MM, MM, MM, MM, MM, MM, MMh, MMh, MMh, HEADS, 1.f);
        axpyI_k<<<nblk, 256>>>(p.u, p.t, 13.f);
        launch_gemm(false, zc, p.t, zn, MM, MM, MM, MM, MM, MM, MMh, MMh, MMh, HEADS, 0.25f);
        float* tmp = zc; zc = zn; zn = tmp;
    }

    // 6) S3 = q_l @ k^T  [8, 256, NP], softmax, a3v = S3 @ v  [8,256,64]
    launch_gemm(true, p.ql, p.qkv + 512, p.S, MM, NP, DH, DH, QKVW, NP,
                (long)MM * DH, 64, Sst, HEADS, 1.f);
    softmax_long_k<<<HEADS * MM, 256>>>(p.S, NP);
    launch_gemm(false, p.S, p.qkv + 1024, p.a3v, MM, DH, NP, NP, QKVW, DH,
                Sst, 64, (long)MM * DH, HEADS, 1.f);

    // 7) W = pinv @ a3v
    launch_gemm(false, zc, p.a3v, p.W, MM, DH, MM, MM, DH, DH,
                MMh, (long)MM * DH, (long)MM * DH, HEADS, 1.f);

    // 8) S1 = (q * dh^-.5) @ k_l^T  [8, NP, 256], softmax, O1 = S1 @ W -> attn cols
    launch_gemm(true, p.qkv, p.kl, p.S, NP, MM, DH, QKVW, DH, MM,
                64, (long)MM * DH, Sst, HEADS, 0.125f);
    softmax256_k<<<(int)(((long)HEADS * NP + 7) / 8), dim3(32, 8)>>>(p.S, (long)HEADS * NP);
    launch_gemm(false, p.S, p.W, p.attn, NP, DH, MM, MM, DH, C,
                Sst, (long)MM * DH, 64, HEADS, 1.f);

    // 9) += depthwise conv of v over sequence
    conv_add_k<<<NP, C>>>(p.qkv, res_w, p.attn);

    // 10) out = attn[PADN:] @ w_out ; h += out + b
    launch_gemm(false, p.attn + (long)PADN * C, w_out, p.outl, NH, C, C, C, C, C,
                0, 0, 0, 1, 1.f);
    resid_add_k<<<(int)(((long)NH * C + 255) / 256), 256>>>(h_io, p.outl, b_out);
}

extern "C" void kernel_launch(void* const* d_in, const int* in_sizes, int n_in,
                              void* d_out, int out_size)
{
    const float* features = (const float*)d_in[0];
    const float* cls      = (const float*)d_in[1];
    const float* ln1_g    = (const float*)d_in[2];
    const float* ln1_b    = (const float*)d_in[3];
    const float* qkv1_w   = (const float*)d_in[4];
    const float* out1_w   = (const float*)d_in[5];
    const float* out1_b   = (const float*)d_in[6];
    const float* res1_w   = (const float*)d_in[7];
    const float* pe_w7    = (const float*)d_in[8];
    const float* pe_b7    = (const float*)d_in[9];
    const float* pe_w5    = (const float*)d_in[10];
    const float* pe_b5    = (const float*)d_in[11];
    const float* pe_w3    = (const float*)d_in[12];
    const float* pe_b3    = (const float*)d_in[13];
    const float* ln2_g    = (const float*)d_in[14];
    const float* ln2_b    = (const float*)d_in[15];
    const float* qkv2_w   = (const float*)d_in[16];
    const float* out2_w   = (const float*)d_in[17];
    const float* out2_b   = (const float*)d_in[18];
    const float* res2_w   = (const float*)d_in[19];

    Ptrs p; get_ptrs(p);

    // h = [cls ; features ; features[:100]]
    build_h_k<<<(int)(((long)NH * C + 255) / 256), 256>>>(features, cls, p.h);

    // layer 1
    nystrom_layer(p, p.h, ln1_g, ln1_b, qkv1_w, out1_w, out1_b, res1_w);

    // PPEG: h -> h2
    ppeg_k<<<dim3(HW, HW), C>>>(p.h, p.h2, pe_w7, pe_b7, pe_w5, pe_b5, pe_w3, pe_b3);

    // layer 2 (in place on h2)
    nystrom_layer(p, p.h2, ln2_g, ln2_b, qkv2_w, out2_w, out2_b, res2_w);

    // output = h2 flattened: [cls(512) , features(22500*512)]
    cudaMemcpyAsync(d_out, p.h2, (size_t)out_size * sizeof(float),
                    cudaMemcpyDeviceToDevice);
}

// round 4
// speedup vs baseline: 2.2941x; 2.2790x over previous
#include <cuda_runtime.h>
#include <cuda_bf16.h>
#include <math.h>
#include <stdint.h>

// ---------------- problem constants ----------------
#define NH    22501           // rows of h (cls + 22500)
#define NFEAT 22400           // original features
#define HW    150             // 150x150 grid
#define C     512
#define NP    22528           // padded seq len inside nystrom
#define PADN  27
#define HEADS 8
#define DH    64
#define MM    256             // landmarks
#define LL    88              // tokens per landmark
#define QKVW  1536

// ---------------- scratch (device globals; no allocation allowed) ----------------
__device__ float g_h    [(long)NH*C];
__device__ float g_h2   [(long)NH*C];
__device__ float g_xp   [(long)NP*C];
__device__ float g_qkv  [(long)NP*QKVW];
__device__ float g_ql   [HEADS*MM*DH];
__device__ float g_kl   [HEADS*MM*DH];
__device__ float g_S    [(long)HEADS*NP*MM];   // reused: S3 then S1
__device__ float g_a2   [HEADS*MM*MM];
__device__ float g_z    [HEADS*MM*MM];
__device__ float g_z2   [HEADS*MM*MM];
__device__ float g_xz   [HEADS*MM*MM];
__device__ float g_t    [HEADS*MM*MM];
__device__ float g_u    [HEADS*MM*MM];
__device__ float g_a3v  [HEADS*MM*DH];
__device__ float g_W    [HEADS*MM*DH];
__device__ float g_attn [(long)NP*C];
__device__ float g_outl [(long)NH*C];          // also: split-K partials for a3v
__device__ float g_rowsum[HEADS*MM];
__device__ float g_colsum[HEADS*MM];
__device__ float g_scale[1];

// =======================================================================
// bf16x3 emulated-fp32 batched GEMM via mma.sync.m16n8k16 (sm_100-safe)
// C = alpha * A @ op(B).  TB=false: B is [K,N]; TB=true: B is [N,K].
// Constraints (all call sites satisfy): N % 64 == 0, (K/ksplit) % 32 == 0,
// lda/ldb % 4 == 0, 16B-aligned bases. M may be ragged.
// Tile: 128x64x32, 256 threads, 8 warps (4m x 2n), warp tile 32x32.
// =======================================================================
#define RS      80                 // smem row stride in bytes (40 bf16)
#define AH_OFF  0                  // 128*80 = 10240
#define AL_OFF  10240
#define BH_OFF  20480              // 64*80 = 5120
#define BL_OFF  25600
#define STAGE   30720
#define GB_SMEM (2 * STAGE)

__device__ __forceinline__ uint32_t smem_to_u32(const void* p) {
    uint32_t a;
    asm("{ .reg .u64 t; cvta.to.shared.u64 t, %1; cvt.u32.u64 %0, t; }"
        : "=r"(a) : "l"(p));
    return a;
}
__device__ __forceinline__ void ldsm4(uint32_t addr, uint32_t& r0, uint32_t& r1,
                                      uint32_t& r2, uint32_t& r3)
{
    asm volatile("ldmatrix.sync.aligned.m8n8.x4.shared.b16 {%0,%1,%2,%3}, [%4];"
                 : "=r"(r0), "=r"(r1), "=r"(r2), "=r"(r3) : "r"(addr));
}
__device__ __forceinline__ void mma_bf16(float* c, const uint32_t* a,
                                         uint32_t b0, uint32_t b1)
{
    asm volatile("mma.sync.aligned.m16n8k16.row.col.f32.bf16.bf16.f32 "
                 "{%0,%1,%2,%3},{%4,%5,%6,%7},{%8,%9},{%0,%1,%2,%3};"
                 : "+f"(c[0]), "+f"(c[1]), "+f"(c[2]), "+f"(c[3])
                 : "r"(a[0]), "r"(a[1]), "r"(a[2]), "r"(a[3]), "r"(b0), "r"(b1));
}
__device__ __forceinline__ void split_bf(float x, float& hi, float& lo)
{
    hi = __bfloat162float(__float2bfloat16(x));
    lo = x - hi;
}
__device__ __forceinline__ uint32_t pack_bf2(float lo_elt, float hi_elt)
{
    // packs {upper=hi_elt, lower=lo_elt} — call as pack_bf2(x[k], x[k+1])
    uint32_t r;
    asm("cvt.rn.bf16x2.f32 %0, %1, %2;" : "=r"(r) : "f"(hi_elt), "f"(lo_elt));
    return r;
}

template<bool TB>
__global__ void __launch_bounds__(256)
gemm_bf(const float* __restrict__ A, const float* __restrict__ B, float* __restrict__ Cm,
        int M, int N, int K, int lda, int ldb, int ldc,
        long sA, long sB, long sC, float alpha, int ksplit)
{
    extern __shared__ __align__(16) char sm[];

    const int tid  = threadIdx.x;
    const int warp = tid >> 5, lane = tid & 31;
    const int wm   = warp & 3, wn = warp >> 2;

    const int z = blockIdx.z;
    const int batch = z / ksplit;
    const int split = z - batch * ksplit;
    A  += (long)batch * sA;
    B  += (long)batch * sB;
    Cm += (long)z * sC;

    const int row0 = blockIdx.y * 128;
    const int col0 = blockIdx.x * 64;
    const int kchunk = K / ksplit;
    const int kbase = split * kchunk;
    const int nch = kchunk >> 5;

    float acc[2][4][4];
    #pragma unroll
    for (int i = 0; i < 2; i++)
        #pragma unroll
        for (int j = 0; j < 4; j++)
            #pragma unroll
            for (int q = 0; q < 4; q++) acc[i][j][q] = 0.f;

    float4 pa[4], pb[2];
    const float4 zero4 = make_float4(0.f, 0.f, 0.f, 0.f);

    // ---- global loads into regs ----
    const int a_row = tid >> 1, a_half = tid & 1;
    auto ldgA = [&](int it) {
        int kc = kbase + it * 32 + a_half * 16;
        int gm = row0 + a_row;
        const float* src = A + (long)gm * lda + kc;
        #pragma unroll
        for (int i = 0; i < 4; i++)
            pa[i] = (gm < M) ? *reinterpret_cast<const float4*>(src + 4 * i) : zero4;
    };
    auto ldgB = [&](int it) {
        int kc = kbase + it * 32;
        if (TB) {
            int row = tid >> 2, q = tid & 3;
            const float* src = B + (long)(col0 + row) * ldb + kc + 4 * q;
            pb[0] = *reinterpret_cast<const float4*>(src);
            pb[1] = *reinterpret_cast<const float4*>(src + 16);
        } else {
            int k = tid >> 3, nq = tid & 7;
            const float* src = B + (long)(kc + k) * ldb + col0 + 4 * nq;
            pb[0] = *reinterpret_cast<const float4*>(src);
            pb[1] = *reinterpret_cast<const float4*>(src + 32);
        }
    };

    // ---- convert + store to smem stage ----
    auto stsA = [&](int stg) {
        char* base = sm + stg * STAGE;
        int koff = a_half * 16;
        #pragma unroll
        for (int i = 0; i < 4; i++) {
            float h0,l0,h1,l1,h2,l2,h3,l3;
            split_bf(pa[i].x, h0, l0); split_bf(pa[i].y, h1, l1);
            split_bf(pa[i].z, h2, l2); split_bf(pa[i].w, h3, l3);
            int k = koff + 4 * i;
            uint2 hh = make_uint2(pack_bf2(h0, h1), pack_bf2(h2, h3));
            uint2 ll = make_uint2(pack_bf2(l0, l1), pack_bf2(l2, l3));
            *reinterpret_cast<uint2*>(base + AH_OFF + a_row * RS + 2 * k) = hh;
            *reinterpret_cast<uint2*>(base + AL_OFF + a_row * RS + 2 * k) = ll;
        }
    };
    auto stsB = [&](int stg) {
        char* base = sm + stg * STAGE;
        if (TB) {
            int row = tid >> 2, q = tid & 3;
            #pragma unroll
            for (int part = 0; part < 2; part++) {
                float4 v = pb[part];
                float h0,l0,h1,l1,h2,l2,h3,l3;
                split_bf(v.x, h0, l0); split_bf(v.y, h1, l1);
                split_bf(v.z, h2, l2); split_bf(v.w, h3, l3);
                int k = part * 16 + 4 * q;
                *reinterpret_cast<uint2*>(base + BH_OFF + row * RS + 2 * k) =
                    make_uint2(pack_bf2(h0, h1), pack_bf2(h2, h3));
                *reinterpret_cast<uint2*>(base + BL_OFF + row * RS + 2 * k) =
                    make_uint2(pack_bf2(l0, l1), pack_bf2(l2, l3));
            }
        } else {
            int k = tid >> 3, nq = tid & 7;
            #pragma unroll
            for (int part = 0; part < 2; part++) {
                float4 v = pb[part];
                float vv[4] = {v.x, v.y, v.z, v.w};
                int n0 = part * 32 + 4 * nq;
                #pragma unroll
                for (int j = 0; j < 4; j++) {
                    float hi, lo; split_bf(vv[j], hi, lo);
                    *reinterpret_cast<__nv_bfloat16*>(base + BH_OFF + (n0 + j) * RS + 2 * k) =
                        __float2bfloat16(hi);
                    *reinterpret_cast<__nv_bfloat16*>(base + BL_OFF + (n0 + j) * RS + 2 * k) =
                        __float2bfloat16(lo);
                }
            }
        }
    };

    // ---- mma over one smem stage ----
    const int rsel = (lane & 7) + ((lane >> 3) & 1) * 8;   // row within 16
    const int ksel = ((lane >> 4) & 1) * 16;               // byte offset within k16
    auto do_mma = [&](int stg) {
        uint32_t sb = smem_to_u32(sm + stg * STAGE);
        #pragma unroll
        for (int kk = 0; kk < 2; kk++) {
            uint32_t ah[2][4], al[2][4], bh[4][2], bl[4][2];
            #pragma unroll
            for (int mt = 0; mt < 2; mt++) {
                uint32_t ad = sb + AH_OFF + (wm * 32 + mt * 16 + rsel) * RS + kk * 32 + ksel;
                ldsm4(ad, ah[mt][0], ah[mt][1], ah[mt][2], ah[mt][3]);
                ldsm4(ad + (AL_OFF - AH_OFF), al[mt][0], al[mt][1], al[mt][2], al[mt][3]);
            }
            #pragma unroll
            for (int np = 0; np < 2; np++) {
                uint32_t bd = sb + BH_OFF + (wn * 32 + np * 16 + rsel) * RS + kk * 32 + ksel;
                uint32_t q0, q1, q2, q3;
                ldsm4(bd, q0, q1, q2, q3);
                bh[2*np][0] = q0; bh[2*np][1] = q2;
                bh[2*np+1][0] = q1; bh[2*np+1][1] = q3;
                ldsm4(bd + (BL_OFF - BH_OFF), q0, q1, q2, q3);
                bl[2*np][0] = q0; bl[2*np][1] = q2;
                bl[2*np+1][0] = q1; bl[2*np+1][1] = q3;
            }
            #pragma unroll
            for (int mt = 0; mt < 2; mt++)
                #pragma unroll
                for (int nt = 0; nt < 4; nt++) {
                    mma_bf16(acc[mt][nt], ah[mt], bh[nt][0], bh[nt][1]);
                    mma_bf16(acc[mt][nt], ah[mt], bl[nt][0], bl[nt][1]);
                    mma_bf16(acc[mt][nt], al[mt], bh[nt][0], bh[nt][1]);
                }
        }
    };

    // ---- pipeline ----
    ldgA(0); ldgB(0);
    stsA(0); stsB(0);
    __syncthreads();
    for (int it = 0; it < nch; it++) {
        const int cur = it & 1;
        if (it + 1 < nch) { ldgA(it + 1); ldgB(it + 1); }
        do_mma(cur);
        if (it + 1 < nch) { stsA(cur ^ 1); stsB(cur ^ 1); }
        __syncthreads();
    }

    // ---- epilogue ----
    const int er = lane >> 2, eq = lane & 3;
    #pragma unroll
    for (int mt = 0; mt < 2; mt++) {
        #pragma unroll
        for (int nt = 0; nt < 4; nt++) {
            int gr = row0 + wm * 32 + mt * 16 + er;
            int gc = col0 + wn * 32 + nt * 8 + 2 * eq;
            if (gr < M)
                *reinterpret_cast<float2*>(Cm + (long)gr * ldc + gc) =
                    make_float2(alpha * acc[mt][nt][0], alpha * acc[mt][nt][1]);
            if (gr + 8 < M)
                *reinterpret_cast<float2*>(Cm + (long)(gr + 8) * ldc + gc) =
                    make_float2(alpha * acc[mt][nt][2], alpha * acc[mt][nt][3]);
        }
    }
}

static inline void launch_gemm(bool tb, const float* A, const float* B, float* Cm,
                               int M, int N, int K, int lda, int ldb, int ldc,
                               long sA, long sB, long sC, int batch, float alpha,
                               int ksplit = 1)
{
    dim3 g(N / 64, (M + 127) / 128, batch * ksplit), b(256);
    if (tb) gemm_bf<true ><<<g, b, GB_SMEM>>>(A, B, Cm, M, N, K, lda, ldb, ldc, sA, sB, sC, alpha, ksplit);
    else    gemm_bf<false><<<g, b, GB_SMEM>>>(A, B, Cm, M, N, K, lda, ldb, ldc, sA, sB, sC, alpha, ksplit);
}

// ---------------- split-K reduce for a3v: sum 8 partials ----------------
__global__ void reduce8_k(const float* __restrict__ part, float* __restrict__ out)
{
    int i = blockIdx.x * 256 + threadIdx.x;
    if (i >= HEADS * MM * DH) return;
    int head = i >> 14;             // MM*DH = 16384
    int r = i & 16383;
    const float* p = part + (long)head * 8 * 16384 + r;
    float s = 0.f;
    #pragma unroll
    for (int k = 0; k < 8; k++) s += p[(long)k * 16384];
    out[i] = s;
}

// ---------------- build h = [cls ; features ; features[:100]] ----------------
__global__ void build_h_k(const float* __restrict__ feat, const float* __restrict__ cls,
                          float* __restrict__ h)
{
    long i = (long)blockIdx.x * 256 + threadIdx.x;
    if (i >= (long)NH * C) return;
    long t = i >> 9;
    int  c = (int)(i & 511);
    float v;
    if (t == 0) v = cls[c];
    else {
        long r = t - 1;
        if (r >= NFEAT) r -= NFEAT;
        v = feat[r * C + c];
    }
    h[i] = v;
}

// ---------------- layernorm of h rows into front-padded xp ----------------
__global__ void ln_pad_k(const float* __restrict__ h, float* __restrict__ xp,
                         const float* __restrict__ g, const float* __restrict__ b)
{
    int t = blockIdx.x, c = threadIdx.x;     // 256 threads, 2 cols each
    float* out = xp + (long)t * C;
    if (t < PADN) { out[c] = 0.f; out[c + 256] = 0.f; return; }
    const float* row = h + (long)(t - PADN) * C;
    float a1 = row[c], a2 = row[c + 256];
    __shared__ float red[256];
    red[c] = a1 + a2; __syncthreads();
    for (int s = 128; s > 0; s >>= 1) { if (c < s) red[c] += red[c + s]; __syncthreads(); }
    float mu = red[0] * (1.f / 512.f);
    __syncthreads();
    float d1 = a1 - mu, d2 = a2 - mu;
    red[c] = d1 * d1 + d2 * d2; __syncthreads();
    for (int s = 128; s > 0; s >>= 1) { if (c < s) red[c] += red[c + s]; __syncthreads(); }
    float inv = rsqrtf(red[0] * (1.f / 512.f) + 1e-5f);
    out[c]       = d1 * inv * g[c]       + b[c];
    out[c + 256] = d2 * inv * g[c + 256] + b[c + 256];
}

// ---------------- landmarks: mean over 88-token groups (q pre-scaled) ----------------
__global__ void landmarks_k(const float* __restrict__ qkv,
                            float* __restrict__ ql, float* __restrict__ kl)
{
    int d = threadIdx.x;                       // 0..63
    int m = blockIdx.x & 255;
    int hh = blockIdx.x >> 8;
    const float* base = qkv + (long)(m * LL) * QKVW + hh * DH + d;
    float sq = 0.f, sk = 0.f;
    for (int j = 0; j < LL; j++) {
        sq += base[(long)j * QKVW];
        sk += base[(long)j * QKVW + 512];
    }
    ql[(hh * MM + m) * DH + d] = sq * (0.125f / (float)LL);   // * DH^-0.5 / l
    kl[(hh * MM + m) * DH + d] = sk * (1.f / (float)LL);
}

// ---------------- softmax, 256 cols, one warp per row ----------------
__global__ void softmax256_k(float* __restrict__ S, long nrows)
{
    long row = (long)blockIdx.x * 8 + threadIdx.y;
    if (row >= nrows) return;
    float* r = S + row * 256;
    int lane = threadIdx.x;
    float v[8], m = -1e30f;
    #pragma unroll
    for (int i = 0; i < 8; i++) { v[i] = r[lane + 32 * i]; m = fmaxf(m, v[i]); }
    #pragma unroll
    for (int o = 16; o; o >>= 1) m = fmaxf(m, __shfl_xor_sync(0xffffffffu, m, o));
    float s = 0.f;
    #pragma unroll
    for (int i = 0; i < 8; i++) { v[i] = __expf(v[i] - m); s += v[i]; }
    #pragma unroll
    for (int o = 16; o; o >>= 1) s += __shfl_xor_sync(0xffffffffu, s, o);
    float inv = 1.f / s;
    #pragma unroll
    for (int i = 0; i < 8; i++) r[lane + 32 * i] = v[i] * inv;
}

// ---------------- softmax, long rows (NP cols), one block per row ----------------
__global__ void softmax_long_k(float* __restrict__ S, int cols)
{
    float* row = S + (long)blockIdx.x * cols;
    __shared__ float red[256];
    int tid = threadIdx.x;
    float m = -1e30f;
    for (int i = tid; i < cols; i += 256) m = fmaxf(m, row[i]);
    red[tid] = m; __syncthreads();
    for (int s = 128; s > 0; s >>= 1) { if (tid < s) red[tid] = fmaxf(red[tid], red[tid + s]); __syncthreads(); }
    m = red[0]; __syncthreads();
    float sum = 0.f;
    for (int i = tid; i < cols; i += 256) { float e = __expf(row[i] - m); row[i] = e; sum += e; }
    red[tid] = sum; __syncthreads();
    for (int s = 128; s > 0; s >>= 1) { if (tid < s) red[tid] += red[tid + s]; __syncthreads(); }
    float inv = 1.f / red[0];
    for (int i = tid; i < cols; i += 256) row[i] *= inv;
}

// ---------------- pinv init helpers ----------------
__global__ void pinv_sums_k(const float* __restrict__ a2,
                            float* __restrict__ rs, float* __restrict__ cs)
{
    int hh = blockIdx.x, j = threadIdx.x;
    const float* X = a2 + (long)hh * MM * MM;
    float r = 0.f, c = 0.f;
    for (int k = 0; k < MM; k++) { r += fabsf(X[j * MM + k]); c += fabsf(X[k * MM + j]); }
    rs[hh * MM + j] = r; cs[hh * MM + j] = c;
}
__global__ void pinv_scale_k(const float* __restrict__ rs, const float* __restrict__ cs,
                             float* __restrict__ scale)
{
    __shared__ float m1[256], m2[256];
    float a = -1e30f, b = -1e30f;
    for (int i = threadIdx.x; i < HEADS * MM; i += 256) { a = fmaxf(a, rs[i]); b = fmaxf(b, cs[i]); }
    m1[threadIdx.x] = a; m2[threadIdx.x] = b; __syncthreads();
    for (int s = 128; s > 0; s >>= 1) {
        if (threadIdx.x < s) {
            m1[threadIdx.x] = fmaxf(m1[threadIdx.x], m1[threadIdx.x + s]);
            m2[threadIdx.x] = fmaxf(m2[threadIdx.x], m2[threadIdx.x + s]);
        }
        __syncthreads();
    }
    if (threadIdx.x == 0) scale[0] = 1.f / (m1[0] * m2[0]);
}
__global__ void pinv_init_k(const float* __restrict__ a2, float* __restrict__ z,
                            const float* __restrict__ scale)
{
    long i = (long)blockIdx.x * 256 + threadIdx.x;
    if (i >= (long)HEADS * MM * MM) return;
    long hh = i >> 16; int r = (int)((i >> 8) & 255), c = (int)(i & 255);
    z[i] = a2[(hh << 16) + ((long)c << 8) + r] * scale[0];
}
// out = alpha*I - in
__global__ void axpyI_k(const float* __restrict__ in, float* __restrict__ out, float alpha)
{
    long i = (long)blockIdx.x * 256 + threadIdx.x;
    if (i >= (long)HEADS * MM * MM) return;
    int r = (int)((i >> 8) & 255), c = (int)(i & 255);
    out[i] = (r == c ? alpha : 0.f) - in[i];
}

// ---------------- depthwise 33-tap conv over sequence of v, added into attn ----------------
__global__ void conv_add_k(const float* __restrict__ qkv, const float* __restrict__ rw,
                           float* __restrict__ attn)
{
    int t = blockIdx.x, c = threadIdx.x;   // 512 threads
    int hh = c >> 6;
    float acc = 0.f;
    #pragma unroll
    for (int k = 0; k < 33; k++) {
        int tt = t + k - 16;
        if ((unsigned)tt < (unsigned)NP)
            acc += qkv[(long)tt * QKVW + 1024 + c] * rw[hh * 33 + k];
    }
    attn[(long)t * C + c] += acc;
}

// ---------------- residual: h += lin + bias ----------------
__global__ void resid_add_k(float* __restrict__ h, const float* __restrict__ lin,
                            const float* __restrict__ bias)
{
    long i = (long)blockIdx.x * 256 + threadIdx.x;
    if (i >= (long)NH * C) return;
    h[i] += lin[i] + bias[i & 511];
}

// ---------------- PPEG: identity + dw7 + dw5 + dw3 + biases ----------------
__global__ void ppeg_k(const float* __restrict__ h, float* __restrict__ h2,
                       const float* __restrict__ w7, const float* __restrict__ b7,
                       const float* __restrict__ w5, const float* __restrict__ b5,
                       const float* __restrict__ w3, const float* __restrict__ b3)
{
    int x = blockIdx.x, y = blockIdx.y, c = threadIdx.x;  // 512 threads
    if (x == 0 && y == 0) h2[c] = h[c];                    // cls passthrough
    float acc = h[(long)(1 + y * HW + x) * C + c];         // identity
    #pragma unroll
    for (int ky = 0; ky < 7; ky++) {
        int yy = y + ky - 3; if (yy < 0 || yy >= HW) continue;
        #pragma unroll
        for (int kx = 0; kx < 7; kx++) {
            int xx = x + kx - 3; if (xx < 0 || xx >= HW) continue;
            acc += h[(long)(1 + yy * HW + xx) * C + c] * w7[c * 49 + ky * 7 + kx];
        }
    }
    #pragma unroll
    for (int ky = 0; ky < 5; ky++) {
        int yy = y + ky - 2; if (yy < 0 || yy >= HW) continue;
        #pragma unroll
        for (int kx = 0; kx < 5; kx++) {
            int xx = x + kx - 2; if (xx < 0 || xx >= HW) continue;
            acc += h[(long)(1 + yy * HW + xx) * C + c] * w5[c * 25 + ky * 5 + kx];
        }
    }
    #pragma unroll
    for (int ky = 0; ky < 3; ky++) {
        int yy = y + ky - 1; if (yy < 0 || yy >= HW) continue;
        #pragma unroll
        for (int kx = 0; kx < 3; kx++) {
            int xx = x + kx - 1; if (xx < 0 || xx >= HW) continue;
            acc += h[(long)(1 + yy * HW + xx) * C + c] * w3[c * 9 + ky * 3 + kx];
        }
    }
    acc += b7[c] + b5[c] + b3[c];
    h2[(long)(1 + y * HW + x) * C + c] = acc;
}

// ================= host orchestration =================
struct Ptrs {
    float *h, *h2, *xp, *qkv, *ql, *kl, *S, *a2, *z, *z2, *xz, *t, *u,
          *a3v, *W, *attn, *outl, *rowsum, *colsum, *scale;
};

static void get_ptrs(Ptrs& p)
{
    cudaGetSymbolAddress((void**)&p.h,    g_h);
    cudaGetSymbolAddress((void**)&p.h2,   g_h2);
    cudaGetSymbolAddress((void**)&p.xp,   g_xp);
    cudaGetSymbolAddress((void**)&p.qkv,  g_qkv);
    cudaGetSymbolAddress((void**)&p.ql,   g_ql);
    cudaGetSymbolAddress((void**)&p.kl,   g_kl);
    cudaGetSymbolAddress((void**)&p.S,    g_S);
    cudaGetSymbolAddress((void**)&p.a2,   g_a2);
    cudaGetSymbolAddress((void**)&p.z,    g_z);
    cudaGetSymbolAddress((void**)&p.z2,   g_z2);
    cudaGetSymbolAddress((void**)&p.xz,   g_xz);
    cudaGetSymbolAddress((void**)&p.t,    g_t);
    cudaGetSymbolAddress((void**)&p.u,    g_u);
    cudaGetSymbolAddress((void**)&p.a3v,  g_a3v);
    cudaGetSymbolAddress((void**)&p.W,    g_W);
    cudaGetSymbolAddress((void**)&p.attn, g_attn);
    cudaGetSymbolAddress((void**)&p.outl, g_outl);
    cudaGetSymbolAddress((void**)&p.rowsum, g_rowsum);
    cudaGetSymbolAddress((void**)&p.colsum, g_colsum);
    cudaGetSymbolAddress((void**)&p.scale,  g_scale);
}

static void nystrom_layer(Ptrs& p, float* h_io,
                          const float* ln_g, const float* ln_b,
                          const float* w_qkv, const float* w_out, const float* b_out,
                          const float* res_w)
{
    const long MMh = (long)MM * MM;          // per-head 256x256
    const long Sst = (long)NP * MM;          // per-head S stride

    // 1) LN + front pad
    ln_pad_k<<<NP, 256>>>(h_io, p.xp, ln_g, ln_b);

    // 2) qkv = xp @ w_qkv   [NP x 1536]
    launch_gemm(false, p.xp, w_qkv, p.qkv, NP, QKVW, C, C, QKVW, QKVW, 0, 0, 0, 1, 1.f);

    // 3) landmarks
    landmarks_k<<<HEADS * MM, DH>>>(p.qkv, p.ql, p.kl);

    // 4) a2 = softmax(q_l @ k_l^T)
    launch_gemm(true, p.ql, p.kl, p.a2, MM, MM, DH, DH, DH, MM,
                (long)MM * DH, (long)MM * DH, MMh, HEADS, 1.f);
    softmax256_k<<<(HEADS * MM + 7) / 8, dim3(32, 8)>>>(p.a2, HEADS * MM);

    // 5) pinv_iter(a2) -> z
    pinv_sums_k<<<HEADS, 256>>>(p.a2, p.rowsum, p.colsum);
    pinv_scale_k<<<1, 256>>>(p.rowsum, p.colsum, p.scale);
    pinv_init_k<<<(int)((HEADS * MMh + 255) / 256), 256>>>(p.a2, p.z, p.scale);
    float* zc = p.z; float* zn = p.z2;
    int nblk = (int)((HEADS * MMh + 255) / 256);
    for (int it = 0; it < 6; it++) {
        launch_gemm(false, p.a2, zc, p.xz, MM, MM, MM, MM, MM, MM, MMh, MMh, MMh, HEADS, 1.f);
        axpyI_k<<<nblk, 256>>>(p.xz, p.t, 7.f);
        launch_gemm(false, p.xz, p.t, p.u, MM, MM, MM, MM, MM, MM, MMh, MMh, MMh, HEADS, 1.f);
        axpyI_k<<<nblk, 256>>>(p.u, p.t, 15.f);
        launch_gemm(false, p.xz, p.t, p.u, MM, MM, MM, MM, MM, MM, MMh, MMh, MMh, HEADS, 1.f);
        axpyI_k<<<nblk, 256>>>(p.u, p.t, 13.f);
        launch_gemm(false, zc, p.t, zn, MM, MM, MM, MM, MM, MM, MMh, MMh, MMh, HEADS, 0.25f);
        float* tmp = zc; zc = zn; zn = tmp;
    }

    // 6) S3 = q_l @ k^T  [8, 256, NP], softmax, a3v = S3 @ v (split-K x8)
    launch_gemm(true, p.ql, p.qkv + 512, p.S, MM, NP, DH, DH, QKVW, NP,
                (long)MM * DH, 64, Sst, HEADS, 1.f);
    softmax_long_k<<<HEADS * MM, 256>>>(p.S, NP);
    launch_gemm(false, p.S, p.qkv + 1024, p.outl, MM, DH, NP, NP, QKVW, DH,
                Sst, 64, (long)MM * DH, HEADS, 1.f, /*ksplit=*/8);
    reduce8_k<<<(HEADS * MM * DH + 255) / 256, 256>>>(p.outl, p.a3v);

    // 7) W = pinv @ a3v
    launch_gemm(false, zc, p.a3v, p.W, MM, DH, MM, MM, DH, DH,
                MMh, (long)MM * DH, (long)MM * DH, HEADS, 1.f);

    // 8) S1 = (q * dh^-.5) @ k_l^T  [8, NP, 256], softmax, O1 = S1 @ W -> attn cols
    launch_gemm(true, p.qkv, p.kl, p.S, NP, MM, DH, QKVW, DH, MM,
                64, (long)MM * DH, Sst, HEADS, 0.125f);
    softmax256_k<<<(int)(((long)HEADS * NP + 7) / 8), dim3(32, 8)>>>(p.S, (long)HEADS * NP);
    launch_gemm(false, p.S, p.W, p.attn, NP, DH, MM, MM, DH, C,
                Sst, (long)MM * DH, 64, HEADS, 1.f);

    // 9) += depthwise conv of v over sequence
    conv_add_k<<<NP, C>>>(p.qkv, res_w, p.attn);

    // 10) out = attn[PADN:] @ w_out ; h += out + b
    launch_gemm(false, p.attn + (long)PADN * C, w_out, p.outl, NH, C, C, C, C, C,
                0, 0, 0, 1, 1.f);
    resid_add_k<<<(int)(((long)NH * C + 255) / 256), 256>>>(h_io, p.outl, b_out);
}

extern "C" void kernel_launch(void* const* d_in, const int* in_sizes, int n_in,
                              void* d_out, int out_size)
{
    const float* features = (const float*)d_in[0];
    const float* cls      = (const float*)d_in[1];
    const float* ln1_g    = (const float*)d_in[2];
    const float* ln1_b    = (const float*)d_in[3];
    const float* qkv1_w   = (const float*)d_in[4];
    const float* out1_w   = (const float*)d_in[5];
    const float* out1_b   = (const float*)d_in[6];
    const float* res1_w   = (const float*)d_in[7];
    const float* pe_w7    = (const float*)d_in[8];
    const float* pe_b7    = (const float*)d_in[9];
    const float* pe_w5    = (const float*)d_in[10];
    const float* pe_b5    = (const float*)d_in[11];
    const float* pe_w3    = (const float*)d_in[12];
    const float* pe_b3    = (const float*)d_in[13];
    const float* ln2_g    = (const float*)d_in[14];
    const float* ln2_b    = (const float*)d_in[15];
    const float* qkv2_w   = (const float*)d_in[16];
    const float* out2_w   = (const float*)d_in[17];
    const float* out2_b   = (const float*)d_in[18];
    const float* res2_w   = (const float*)d_in[19];

    // 60KB dynamic smem for the GEMM (host-side attr; capture-safe)
    cudaFuncSetAttribute(gemm_bf<false>, cudaFuncAttributeMaxDynamicSharedMemorySize, GB_SMEM);
    cudaFuncSetAttribute(gemm_bf<true>,  cudaFuncAttributeMaxDynamicSharedMemorySize, GB_SMEM);

    Ptrs p; get_ptrs(p);

    // h = [cls ; features ; features[:100]]
    build_h_k<<<(int)(((long)NH * C + 255) / 256), 256>>>(features, cls, p.h);

    // layer 1
    nystrom_layer(p, p.h, ln1_g, ln1_b, qkv1_w, out1_w, out1_b, res1_w);

    // PPEG: h -> h2
    ppeg_k<<<dim3(HW, HW), C>>>(p.h, p.h2, pe_w7, pe_b7, pe_w5, pe_b5, pe_w3, pe_b3);

    // layer 2 (in place on h2)
    nystrom_layer(p, p.h2, ln2_g, ln2_b, qkv2_w, out2_w, out2_b, res2_w);

    // output = h2 flattened: [cls(512) , features(22500*512)]
    cudaMemcpyAsync(d_out, p.h2, (size_t)out_size * sizeof(float),
                    cudaMemcpyDeviceToDevice);
}

// round 5
// speedup vs baseline: 2.4832x; 1.0824x over previous
#include <cuda_runtime.h>
#include <cuda_bf16.h>
#include <math.h>
#include <stdint.h>

typedef __nv_bfloat16 bf16;

// ---------------- problem constants ----------------
#define NH    22501
#define NFEAT 22400
#define HW    150
#define C     512
#define NP    22528
#define PADN  27
#define HEADS 8
#define DH    64
#define MM    256
#define LL    88
#define QKVW  1536

// ---------------- fp32 scratch ----------------
__device__ float g_h   [(long)NH*C];
__device__ float g_h2  [(long)NH*C];
__device__ float g_S   [(long)HEADS*NP*MM];
__device__ float g_a2  [HEADS*MM*MM];
__device__ float g_attn[(long)NP*C];
__device__ float g_outl[(long)NH*C];          // also split-K partials
__device__ float g_rowsum[HEADS*MM];
__device__ float g_colsum[HEADS*MM];
__device__ float g_scale[1];

// ---------------- bf16 hi/lo pair scratch ----------------
__device__ bf16 g_xph[(long)NP*C],     g_xpl[(long)NP*C];
__device__ bf16 g_qkvh[(long)NP*QKVW], g_qkvl[(long)NP*QKVW];
__device__ bf16 g_qlh[HEADS*MM*DH],    g_qll[HEADS*MM*DH];
__device__ bf16 g_klh[HEADS*MM*DH],    g_kll[HEADS*MM*DH];
__device__ bf16 g_Shh[(long)HEADS*NP*MM], g_Sll[(long)HEADS*NP*MM];
__device__ bf16 g_a2h[HEADS*MM*MM],    g_a2l[HEADS*MM*MM];
__device__ bf16 g_zh [HEADS*MM*MM], g_zl [HEADS*MM*MM];
__device__ bf16 g_zth[HEADS*MM*MM], g_ztl[HEADS*MM*MM];
__device__ bf16 g_z2h[HEADS*MM*MM], g_z2l[HEADS*MM*MM];
__device__ bf16 g_z2th[HEADS*MM*MM], g_z2tl[HEADS*MM*MM];
__device__ bf16 g_xzh[HEADS*MM*MM], g_xzl[HEADS*MM*MM];
__device__ bf16 g_tah[HEADS*MM*MM], g_tal[HEADS*MM*MM];
__device__ bf16 g_tbh[HEADS*MM*MM], g_tbl[HEADS*MM*MM];
__device__ bf16 g_vth[(long)HEADS*DH*NP], g_vtl[(long)HEADS*DH*NP];
__device__ bf16 g_a3h[HEADS*DH*MM],    g_a3l[HEADS*DH*MM];
__device__ bf16 g_Wth[HEADS*DH*MM],    g_Wtl[HEADS*DH*MM];
__device__ bf16 g_ath[(long)NP*C],     g_atl[(long)NP*C];
__device__ bf16 g_w1h[(long)QKVW*C],   g_w1l[(long)QKVW*C];   // wqkv^T pair
__device__ bf16 g_w2h[(long)C*C],      g_w2l[(long)C*C];      // wout^T pair

// ---------------- small device helpers ----------------
__device__ __forceinline__ uint32_t smem_to_u32(const void* p) {
    uint32_t a;
    asm("{ .reg .u64 t; cvta.to.shared.u64 t, %1; cvt.u32.u64 %0, t; }"
        : "=r"(a) : "l"(p));
    return a;
}
__device__ __forceinline__ void ldsm4(uint32_t addr, uint32_t& r0, uint32_t& r1,
                                      uint32_t& r2, uint32_t& r3)
{
    asm volatile("ldmatrix.sync.aligned.m8n8.x4.shared.b16 {%0,%1,%2,%3}, [%4];"
                 : "=r"(r0), "=r"(r1), "=r"(r2), "=r"(r3) : "r"(addr));
}
__device__ __forceinline__ void mma_bf16(float* c, const uint32_t* a,
                                         uint32_t b0, uint32_t b1)
{
    asm volatile("mma.sync.aligned.m16n8k16.row.col.f32.bf16.bf16.f32 "
                 "{%0,%1,%2,%3},{%4,%5,%6,%7},{%8,%9},{%0,%1,%2,%3};"
                 : "+f"(c[0]), "+f"(c[1]), "+f"(c[2]), "+f"(c[3])
                 : "r"(a[0]), "r"(a[1]), "r"(a[2]), "r"(a[3]), "r"(b0), "r"(b1));
}
__device__ __forceinline__ void cpa16(uint32_t dst, const void* src, int sz)
{
    asm volatile("cp.async.cg.shared.global [%0], [%1], 16, %2;"
                 :: "r"(dst), "l"(src), "r"(sz));
}
__device__ __forceinline__ uint32_t pack2(float a, float b)   // a->low, b->high
{
    uint32_t r;
    asm("cvt.rn.bf16x2.f32 %0, %1, %2;" : "=r"(r) : "f"(b), "f"(a));
    return r;
}
__device__ __forceinline__ void split_bf(float x, float& hi, float& lo)
{
    hi = __bfloat162float(__float2bfloat16(x));
    lo = x - hi;
}
__device__ __forceinline__ float pairval(const bf16* h, const bf16* l, long i)
{
    return __bfloat162float(h[i]) + __bfloat162float(l[i]);
}

// =======================================================================
// bf16x3 GEMM, operands pre-split; B always [N,K]. cp.async 3-stage.
// Tile 128x64x32, 256 threads, 8 warps (4m x 2n).
// =======================================================================
#define RS      80
#define AH_OFF  0
#define AL_OFF  10240
#define BH_OFF  20480
#define BL_OFF  25600
#define STAGE   30720
#define GP_SMEM (3 * STAGE)

struct EpiOut {
    float* f; float falpha; int ldf; long sF;              // fp32 out
    bf16 *ph, *pl; float palpha; int ldp; long sP;         // plain pair out
    bf16 *th, *tl; float talpha, tdiag; int ldt; long sT;  // transposed pair out (+diag)
};

__global__ void __launch_bounds__(256)
gemm_p(const bf16* __restrict__ Ah, const bf16* __restrict__ Al,
       const bf16* __restrict__ Bh, const bf16* __restrict__ Bl,
       int M, int K, int lda, int ldb, long sA, long sB,
       EpiOut ep, int ksplit)
{
    extern __shared__ __align__(16) char sm[];
    const uint32_t sb0 = smem_to_u32(sm);
    const int tid = threadIdx.x, warp = tid >> 5, lane = tid & 31;
    const int wm = warp & 3, wn = warp >> 2;

    const int z = blockIdx.z;
    const int batch = z / ksplit;
    const int split = z - batch * ksplit;
    Ah += (long)batch * sA;  Al += (long)batch * sA;
    Bh += (long)batch * sB;  Bl += (long)batch * sB;

    const int row0 = blockIdx.y * 128, col0 = blockIdx.x * 64;
    const int kchunk = K / ksplit, kbase = split * kchunk, nch = kchunk >> 5;

    float acc[2][4][4];
    #pragma unroll
    for (int i = 0; i < 2; i++)
        #pragma unroll
        for (int j = 0; j < 4; j++)
            #pragma unroll
            for (int q = 0; q < 4; q++) acc[i][j][q] = 0.f;

    auto issue = [&](int it) {
        const int stg = it % 3;
        const uint32_t sb = sb0 + stg * STAGE;
        const int kc = kbase + it * 32;
        #pragma unroll
        for (int rep = 0; rep < 2; rep++) {
            int c = tid + rep * 256;
            int row = c >> 2, seg = c & 3;
            int gm = row0 + row;
            long go = (long)gm * lda + kc + seg * 8;
            int sz = (gm < M) ? 16 : 0;
            cpa16(sb + AH_OFF + row * RS + seg * 16, Ah + go, sz);
            cpa16(sb + AL_OFF + row * RS + seg * 16, Al + go, sz);
        }
        {
            int n = tid >> 2, seg = tid & 3;
            long go = (long)(col0 + n) * ldb + kc + seg * 8;
            cpa16(sb + BH_OFF + n * RS + seg * 16, Bh + go, 16);
            cpa16(sb + BL_OFF + n * RS + seg * 16, Bl + go, 16);
        }
        asm volatile("cp.async.commit_group;");
    };

    const int rsel = (lane & 7) + ((lane >> 3) & 1) * 8;
    const int ksel = ((lane >> 4) & 1) * 16;
    auto do_mma = [&](int stg) {
        uint32_t sb = sb0 + stg * STAGE;
        #pragma unroll
        for (int kk = 0; kk < 2; kk++) {
            uint32_t ah[2][4], al[2][4], bh[4][2], bl[4][2];
            #pragma unroll
            for (int mt = 0; mt < 2; mt++) {
                uint32_t ad = sb + AH_OFF + (wm * 32 + mt * 16 + rsel) * RS + kk * 32 + ksel;
                ldsm4(ad, ah[mt][0], ah[mt][1], ah[mt][2], ah[mt][3]);
                ldsm4(ad + (AL_OFF - AH_OFF), al[mt][0], al[mt][1], al[mt][2], al[mt][3]);
            }
            #pragma unroll
            for (int np = 0; np < 2; np++) {
                uint32_t bd = sb + BH_OFF + (wn * 32 + np * 16 + rsel) * RS + kk * 32 + ksel;
                uint32_t q0, q1, q2, q3;
                ldsm4(bd, q0, q1, q2, q3);
                bh[2*np][0] = q0; bh[2*np][1] = q2;
                bh[2*np+1][0] = q1; bh[2*np+1][1] = q3;
                ldsm4(bd + (BL_OFF - BH_OFF), q0, q1, q2, q3);
                bl[2*np][0] = q0; bl[2*np][1] = q2;
                bl[2*np+1][0] = q1; bl[2*np+1][1] = q3;
            }
            #pragma unroll
            for (int mt = 0; mt < 2; mt++)
                #pragma unroll
                for (int nt = 0; nt < 4; nt++) {
                    mma_bf16(acc[mt][nt], ah[mt], bh[nt][0], bh[nt][1]);
                    mma_bf16(acc[mt][nt], ah[mt], bl[nt][0], bl[nt][1]);
                    mma_bf16(acc[mt][nt], al[mt], bh[nt][0], bh[nt][1]);
                }
        }
    };

    issue(0);
    if (nch > 1) issue(1);
    for (int it = 0; it < nch; it++) {
        if (it + 1 < nch) asm volatile("cp.async.wait_group 1;");
        else              asm volatile("cp.async.wait_group 0;");
        __syncthreads();
        if (it + 2 < nch) issue(it + 2);
        do_mma(it % 3);
    }

    // ---- epilogue ----
    const int er = lane >> 2, eq = lane & 3;
    float* F  = ep.f  ? ep.f  + (long)z     * ep.sF : (float*)0;
    bf16* Ph  = ep.ph ? ep.ph + (long)batch * ep.sP : (bf16*)0;
    bf16* Pl  = ep.pl ? ep.pl + (long)batch * ep.sP : (bf16*)0;
    bf16* Th  = ep.th ? ep.th + (long)batch * ep.sT : (bf16*)0;
    bf16* Tl  = ep.tl ? ep.tl + (long)batch * ep.sT : (bf16*)0;

    #pragma unroll
    for (int mt = 0; mt < 2; mt++)
        #pragma unroll
        for (int nt = 0; nt < 4; nt++) {
            int gr0 = row0 + wm * 32 + mt * 16 + er;
            int gc  = col0 + wn * 32 + nt * 8 + 2 * eq;
            #pragma unroll
            for (int half = 0; half < 2; half++) {
                int gr = gr0 + 8 * half;
                if (gr >= M) continue;
                float va = acc[mt][nt][2 * half], vb = acc[mt][nt][2 * half + 1];
                if (F)
                    *reinterpret_cast<float2*>(F + (long)gr * ep.ldf + gc) =
                        make_float2(ep.falpha * va, ep.falpha * vb);
                if (Ph) {
                    float s0 = ep.palpha * va, s1 = ep.palpha * vb;
                    float h0, l0, h1, l1;
                    split_bf(s0, h0, l0); split_bf(s1, h1, l1);
                    *reinterpret_cast<uint32_t*>(Ph + (long)gr * ep.ldp + gc) = pack2(h0, h1);
                    *reinterpret_cast<uint32_t*>(Pl + (long)gr * ep.ldp + gc) = pack2(l0, l1);
                }
                if (Th) {
                    #pragma unroll
                    for (int j = 0; j < 2; j++) {
                        int cc = gc + j;
                        float v = (j == 0) ? va : vb;
                        float s = ep.talpha * v + ((gr == cc) ? ep.tdiag : 0.f);
                        float hi, lo; split_bf(s, hi, lo);
                        Th[(long)cc * ep.ldt + gr] = __float2bfloat16(hi);
                        Tl[(long)cc * ep.ldt + gr] = __float2bfloat16(lo);
                    }
                }
            }
        }
}

// host-side launch helper
static EpiOut epi0() { EpiOut e{}; return e; }
static void gemmP(const bf16* Ah, const bf16* Al, const bf16* Bh, const bf16* Bl,
                  int M, int N, int K, int lda, int ldb, long sA, long sB,
                  int batch, int ksplit, EpiOut ep)
{
    dim3 g(N / 64, (M + 127) / 128, batch * ksplit), b(256);
    gemm_p<<<g, b, GP_SMEM>>>(Ah, Al, Bh, Bl, M, K, lda, ldb, sA, sB, ep, ksplit);
}

// =======================================================================
// auxiliary kernels
// =======================================================================

// weights [K,N] fp32 -> [N][K] bf16 pair
__global__ void wconvT_k(const float* __restrict__ w, bf16* __restrict__ th,
                         bf16* __restrict__ tl, int K, int N)
{
    int i = blockIdx.x * 256 + threadIdx.x;
    if (i >= N * K) return;
    int n = i / K, k = i - n * K;
    float v = w[(long)k * N + n];
    float hi, lo; split_bf(v, hi, lo);
    th[i] = __float2bfloat16(hi);
    tl[i] = __float2bfloat16(lo);
}

// h = [cls ; features ; features[:100]]
__global__ void build_h_k(const float* __restrict__ feat, const float* __restrict__ cls,
                          float* __restrict__ h)
{
    long i = (long)blockIdx.x * 256 + threadIdx.x;
    if (i >= (long)NH * C) return;
    long t = i >> 9;
    int  c = (int)(i & 511);
    float v;
    if (t == 0) v = cls[c];
    else {
        long r = t - 1;
        if (r >= NFEAT) r -= NFEAT;
        v = feat[r * C + c];
    }
    h[i] = v;
}

// layernorm rows of h into front-padded xp PAIR
__global__ void ln_pad_k(const float* __restrict__ h, bf16* __restrict__ xh,
                         bf16* __restrict__ xl,
                         const float* __restrict__ g, const float* __restrict__ b)
{
    int t = blockIdx.x, c = threadIdx.x;
    long o = (long)t * C;
    if (t < PADN) {
        bf16 z = __float2bfloat16(0.f);
        xh[o + c] = z; xh[o + c + 256] = z;
        xl[o + c] = z; xl[o + c + 256] = z;
        return;
    }
    const float* row = h + (long)(t - PADN) * C;
    float a1 = row[c], a2 = row[c + 256];
    __shared__ float red[256];
    red[c] = a1 + a2; __syncthreads();
    for (int s = 128; s > 0; s >>= 1) { if (c < s) red[c] += red[c + s]; __syncthreads(); }
    float mu = red[0] * (1.f / 512.f);
    __syncthreads();
    float d1 = a1 - mu, d2 = a2 - mu;
    red[c] = d1 * d1 + d2 * d2; __syncthreads();
    for (int s = 128; s > 0; s >>= 1) { if (c < s) red[c] += red[c + s]; __syncthreads(); }
    float inv = rsqrtf(red[0] * (1.f / 512.f) + 1e-5f);
    float v1 = d1 * inv * g[c] + b[c];
    float v2 = d2 * inv * g[c + 256] + b[c + 256];
    float h1, l1, h2, l2;
    split_bf(v1, h1, l1); split_bf(v2, h2, l2);
    xh[o + c] = __float2bfloat16(h1);       xl[o + c] = __float2bfloat16(l1);
    xh[o + c + 256] = __float2bfloat16(h2); xl[o + c + 256] = __float2bfloat16(l2);
}

// landmarks from qkv pair -> ql/kl pairs (q pre-scaled)
__global__ void landmarks_k(const bf16* __restrict__ qh, const bf16* __restrict__ ql_,
                            bf16* __restrict__ qlh, bf16* __restrict__ qll,
                            bf16* __restrict__ klh, bf16* __restrict__ kll)
{
    int d = threadIdx.x;
    int m = blockIdx.x & 255;
    int hh = blockIdx.x >> 8;
    long base = (long)(m * LL) * QKVW + hh * DH + d;
    float sq = 0.f, sk = 0.f;
    for (int j = 0; j < LL; j++) {
        long o = base + (long)j * QKVW;
        sq += pairval(qh, ql_, o);
        sk += pairval(qh, ql_, o + 512);
    }
    float vq = sq * (0.125f / (float)LL);
    float vk = sk * (1.f / (float)LL);
    int oi = (hh * MM + m) * DH + d;
    float hi, lo;
    split_bf(vq, hi, lo); qlh[oi] = __float2bfloat16(hi); qll[oi] = __float2bfloat16(lo);
    split_bf(vk, hi, lo); klh[oi] = __float2bfloat16(hi); kll[oi] = __float2bfloat16(lo);
}

// softmax over 256-col rows; optional fp32 writeback + pair out
__global__ void softmax256_k(const float* __restrict__ in, float* __restrict__ fout,
                             bf16* __restrict__ ph, bf16* __restrict__ pl, long nrows)
{
    long row = (long)blockIdx.x * 8 + threadIdx.y;
    if (row >= nrows) return;
    const float* r = in + row * 256;
    int lane = threadIdx.x;
    float v[8], m = -1e30f;
    #pragma unroll
    for (int i = 0; i < 8; i++) { v[i] = r[lane + 32 * i]; m = fmaxf(m, v[i]); }
    #pragma unroll
    for (int o = 16; o; o >>= 1) m = fmaxf(m, __shfl_xor_sync(0xffffffffu, m, o));
    float s = 0.f;
    #pragma unroll
    for (int i = 0; i < 8; i++) { v[i] = __expf(v[i] - m); s += v[i]; }
    #pragma unroll
    for (int o = 16; o; o >>= 1) s += __shfl_xor_sync(0xffffffffu, s, o);
    float inv = 1.f / s;
    #pragma unroll
    for (int i = 0; i < 8; i++) {
        float val = v[i] * inv;
        long o = row * 256 + lane + 32 * i;
        if (fout) fout[o] = val;
        float hi, lo; split_bf(val, hi, lo);
        ph[o] = __float2bfloat16(hi);
        pl[o] = __float2bfloat16(lo);
    }
}

// softmax over long rows (NP cols) -> pair out
__global__ void softmax_long_k(const float* __restrict__ S, bf16* __restrict__ ph,
                               bf16* __restrict__ pl, int cols)
{
    const float* row = S + (long)blockIdx.x * cols;
    long ob = (long)blockIdx.x * cols;
    __shared__ float red[256];
    int tid = threadIdx.x;
    float m = -1e30f;
    for (int i = tid; i < cols; i += 256) m = fmaxf(m, row[i]);
    red[tid] = m; __syncthreads();
    for (int s = 128; s > 0; s >>= 1) { if (tid < s) red[tid] = fmaxf(red[tid], red[tid + s]); __syncthreads(); }
    m = red[0]; __syncthreads();
    float sum = 0.f;
    for (int i = tid; i < cols; i += 256) sum += __expf(row[i] - m);
    red[tid] = sum; __syncthreads();
    for (int s = 128; s > 0; s >>= 1) { if (tid < s) red[tid] += red[tid + s]; __syncthreads(); }
    float inv = 1.f / red[0];
    for (int i = tid; i < cols; i += 256) {
        float val = __expf(row[i] - m) * inv;
        float hi, lo; split_bf(val, hi, lo);
        ph[ob + i] = __float2bfloat16(hi);
        pl[ob + i] = __float2bfloat16(lo);
    }
}

// pinv scale helpers (fp32 a2)
__global__ void pinv_sums_k(const float* __restrict__ a2,
                            float* __restrict__ rs, float* __restrict__ cs)
{
    int hh = blockIdx.x, j = threadIdx.x;
    const float* X = a2 + (long)hh * MM * MM;
    float r = 0.f, c = 0.f;
    for (int k = 0; k < MM; k++) { r += fabsf(X[j * MM + k]); c += fabsf(X[k * MM + j]); }
    rs[hh * MM + j] = r; cs[hh * MM + j] = c;
}
__global__ void pinv_scale_k(const float* __restrict__ rs, const float* __restrict__ cs,
                             float* __restrict__ scale)
{
    __shared__ float m1[256], m2[256];
    float a = -1e30f, b = -1e30f;
    for (int i = threadIdx.x; i < HEADS * MM; i += 256) { a = fmaxf(a, rs[i]); b = fmaxf(b, cs[i]); }
    m1[threadIdx.x] = a; m2[threadIdx.x] = b; __syncthreads();
    for (int s = 128; s > 0; s >>= 1) {
        if (threadIdx.x < s) {
            m1[threadIdx.x] = fmaxf(m1[threadIdx.x], m1[threadIdx.x + s]);
            m2[threadIdx.x] = fmaxf(m2[threadIdx.x], m2[threadIdx.x + s]);
        }
        __syncthreads();
    }
    if (threadIdx.x == 0) scale[0] = 1.f / (m1[0] * m2[0]);
}
// z = a2^T * s (plain pair) ; zT = a2 * s (trans pair)
__global__ void pinv_init_k(const float* __restrict__ a2, const float* __restrict__ scale,
                            bf16* __restrict__ zph, bf16* __restrict__ zpl,
                            bf16* __restrict__ zth, bf16* __restrict__ ztl)
{
    long i = (long)blockIdx.x * 256 + threadIdx.x;
    if (i >= (long)HEADS * MM * MM) return;
    float s = scale[0];
    long hb = i & ~65535L;
    int r = (int)((i >> 8) & 255), c = (int)(i & 255);
    float vt = a2[i] * s;
    float vp = a2[hb + ((long)c << 8) + r] * s;
    float hi, lo;
    split_bf(vt, hi, lo); zth[i] = __float2bfloat16(hi); ztl[i] = __float2bfloat16(lo);
    split_bf(vp, hi, lo); zph[i] = __float2bfloat16(hi); zpl[i] = __float2bfloat16(lo);
}

// transpose-convert v from qkv pair -> vT pair [head][d][token]
__global__ void vT_k(const bf16* __restrict__ qh, const bf16* __restrict__ ql_,
                     bf16* __restrict__ vth, bf16* __restrict__ vtl)
{
    __shared__ bf16 tile[32][33];
    int t0 = blockIdx.x * 32;
    int head = blockIdx.y >> 1;
    int lopart = blockIdx.y & 1;
    int d0 = blockIdx.z * 32;
    const bf16* src = (lopart ? ql_ : qh) + 1024 + head * 64 + d0;
    bf16* dst = (lopart ? vtl : vth) + (long)head * 64 * NP + (long)d0 * NP;
    int tx = threadIdx.x, ty = threadIdx.y;
    #pragma unroll
    for (int i = 0; i < 4; i++)
        tile[ty + 8 * i][tx] = src[(long)(t0 + ty + 8 * i) * QKVW + tx];
    __syncthreads();
    #pragma unroll
    for (int i = 0; i < 4; i++)
        dst[(long)(ty + 8 * i) * NP + t0 + tx] = tile[tx][ty + 8 * i];
}

// split-K reduce -> a3v^T pair [head][d][m]
__global__ void reduce8_k(const float* __restrict__ part,
                          bf16* __restrict__ oh, bf16* __restrict__ ol)
{
    int i = blockIdx.x * 256 + threadIdx.x;
    if (i >= HEADS * MM * DH) return;
    int head = i >> 14;
    int r = i & 16383;
    int m = r >> 6, d = r & 63;
    float s = 0.f;
    #pragma unroll
    for (int k = 0; k < 8; k++) s += part[(long)((head << 3) + k) * 16384 + r];
    float hi, lo; split_bf(s, hi, lo);
    long o = (long)(head << 14) + d * 256 + m;
    oh[o] = __float2bfloat16(hi);
    ol[o] = __float2bfloat16(lo);
}

// attn(fp32 O1) + depthwise33(v) -> attn pair
__global__ void conv_add_k(const bf16* __restrict__ qh, const bf16* __restrict__ ql_,
                           const float* __restrict__ rw, const float* __restrict__ attnf,
                           bf16* __restrict__ ah, bf16* __restrict__ al)
{
    int t = blockIdx.x, c = threadIdx.x;
    int hh = c >> 6;
    float acc = attnf[(long)t * C + c];
    #pragma unroll
    for (int k = 0; k < 33; k++) {
        int tt = t + k - 16;
        if ((unsigned)tt < (unsigned)NP)
            acc += pairval(qh, ql_, (long)tt * QKVW + 1024 + c) * rw[hh * 33 + k];
    }
    float hi, lo; split_bf(acc, hi, lo);
    long o = (long)t * C + c;
    ah[o] = __float2bfloat16(hi);
    al[o] = __float2bfloat16(lo);
}

__global__ void resid_add_k(float* __restrict__ h, const float* __restrict__ lin,
                            const float* __restrict__ bias)
{
    long i = (long)blockIdx.x * 256 + threadIdx.x;
    if (i >= (long)NH * C) return;
    h[i] += lin[i] + bias[i & 511];
}

// PPEG fused convs
__global__ void ppeg_k(const float* __restrict__ h, float* __restrict__ h2,
                       const float* __restrict__ w7, const float* __restrict__ b7,
                       const float* __restrict__ w5, const float* __restrict__ b5,
                       const float* __restrict__ w3, const float* __restrict__ b3)
{
    int x = blockIdx.x, y = blockIdx.y, c = threadIdx.x;
    if (x == 0 && y == 0) h2[c] = h[c];
    float acc = h[(long)(1 + y * HW + x) * C + c];
    #pragma unroll
    for (int ky = 0; ky < 7; ky++) {
        int yy = y + ky - 3; if (yy < 0 || yy >= HW) continue;
        #pragma unroll
        for (int kx = 0; kx < 7; kx++) {
            int xx = x + kx - 3; if (xx < 0 || xx >= HW) continue;
            acc += h[(long)(1 + yy * HW + xx) * C + c] * w7[c * 49 + ky * 7 + kx];
        }
    }
    #pragma unroll
    for (int ky = 0; ky < 5; ky++) {
        int yy = y + ky - 2; if (yy < 0 || yy >= HW) continue;
        #pragma unroll
        for (int kx = 0; kx < 5; kx++) {
            int xx = x + kx - 2; if (xx < 0 || xx >= HW) continue;
            acc += h[(long)(1 + yy * HW + xx) * C + c] * w5[c * 25 + ky * 5 + kx];
        }
    }
    #pragma unroll
    for (int ky = 0; ky < 3; ky++) {
        int yy = y + ky - 1; if (yy < 0 || yy >= HW) continue;
        #pragma unroll
        for (int kx = 0; kx < 3; kx++) {
            int xx = x + kx - 1; if (xx < 0 || xx >= HW) continue;
            acc += h[(long)(1 + yy * HW + xx) * C + c] * w3[c * 9 + ky * 3 + kx];
        }
    }
    acc += b7[c] + b5[c] + b3[c];
    h2[(long)(1 + y * HW + x) * C + c] = acc;
}

// ================= host orchestration =================
struct Ptrs {
    float *h, *h2, *S, *a2, *attn, *outl, *rowsum, *colsum, *scale;
    bf16 *xph, *xpl, *qkvh, *qkvl, *qlh, *qll, *klh, *kll, *Sh, *Sl,
         *a2h, *a2l, *zh, *zl, *zth, *ztl, *z2h, *z2l, *z2th, *z2tl,
         *xzh, *xzl, *tah, *tal, *tbh, *tbl, *vth, *vtl,
         *a3h, *a3l, *Wth, *Wtl, *ath, *atl, *w1h, *w1l, *w2h, *w2l;
};
#define GSYM(f, s) cudaGetSymbolAddress((void**)&p.f, s)
static void get_ptrs(Ptrs& p)
{
    GSYM(h, g_h); GSYM(h2, g_h2); GSYM(S, g_S); GSYM(a2, g_a2);
    GSYM(attn, g_attn); GSYM(outl, g_outl);
    GSYM(rowsum, g_rowsum); GSYM(colsum, g_colsum); GSYM(scale, g_scale);
    GSYM(xph, g_xph); GSYM(xpl, g_xpl); GSYM(qkvh, g_qkvh); GSYM(qkvl, g_qkvl);
    GSYM(qlh, g_qlh); GSYM(qll, g_qll); GSYM(klh, g_klh); GSYM(kll, g_kll);
    GSYM(Sh, g_Shh); GSYM(Sl, g_Sll); GSYM(a2h, g_a2h); GSYM(a2l, g_a2l);
    GSYM(zh, g_zh); GSYM(zl, g_zl); GSYM(zth, g_zth); GSYM(ztl, g_ztl);
    GSYM(z2h, g_z2h); GSYM(z2l, g_z2l); GSYM(z2th, g_z2th); GSYM(z2tl, g_z2tl);
    GSYM(xzh, g_xzh); GSYM(xzl, g_xzl);
    GSYM(tah, g_tah); GSYM(tal, g_tal); GSYM(tbh, g_tbh); GSYM(tbl, g_tbl);
    GSYM(vth, g_vth); GSYM(vtl, g_vtl); GSYM(a3h, g_a3h); GSYM(a3l, g_a3l);
    GSYM(Wth, g_Wth); GSYM(Wtl, g_Wtl); GSYM(ath, g_ath); GSYM(atl, g_atl);
    GSYM(w1h, g_w1h); GSYM(w1l, g_w1l); GSYM(w2h, g_w2h); GSYM(w2l, g_w2l);
}

static void nystrom_layer(Ptrs& p, float* h_io,
                          const float* ln_g, const float* ln_b,
                          const float* w_qkv, const float* w_out, const float* b_out,
                          const float* res_w)
{
    const long MMh = (long)MM * MM;
    const long Sst = (long)NP * MM;

    // weight transpose-converts
    wconvT_k<<<(QKVW * C + 255) / 256, 256>>>(w_qkv, p.w1h, p.w1l, C, QKVW);
    wconvT_k<<<(C * C + 255) / 256, 256>>>(w_out, p.w2h, p.w2l, C, C);

    // 1) LN + pad -> xp pair
    ln_pad_k<<<NP, 256>>>(h_io, p.xph, p.xpl, ln_g, ln_b);

    // 2) qkv pair = xp @ wqkv
    { EpiOut e = epi0(); e.ph = p.qkvh; e.pl = p.qkvl; e.palpha = 1.f; e.ldp = QKVW;
      gemmP(p.xph, p.xpl, p.w1h, p.w1l, NP, QKVW, C, C, C, 0, 0, 1, 1, e); }

    // 3) landmarks
    landmarks_k<<<HEADS * MM, DH>>>(p.qkvh, p.qkvl, p.qlh, p.qll, p.klh, p.kll);

    // 4) a2 = softmax(ql @ kl^T) -> fp32 + pair
    { EpiOut e = epi0(); e.f = p.a2; e.falpha = 1.f; e.ldf = MM; e.sF = MMh;
      gemmP(p.qlh, p.qll, p.klh, p.kll, MM, MM, DH, DH, DH,
            (long)MM * DH, (long)MM * DH, HEADS, 1, e); }
    softmax256_k<<<(HEADS * MM + 7) / 8, dim3(32, 8)>>>(p.a2, p.a2, p.a2h, p.a2l, HEADS * MM);

    // 5) pinv
    pinv_sums_k<<<HEADS, 256>>>(p.a2, p.rowsum, p.colsum);
    pinv_scale_k<<<1, 256>>>(p.rowsum, p.colsum, p.scale);
    pinv_init_k<<<(int)((HEADS * MMh + 255) / 256), 256>>>(p.a2, p.scale,
                                                           p.zh, p.zl, p.zth, p.ztl);
    bf16 *zch = p.zh, *zcl = p.zl, *zcth = p.zth, *zctl = p.ztl;
    bf16 *znh = p.z2h, *znl = p.z2l, *znth = p.z2th, *zntl = p.z2tl;
    for (int it = 0; it < 6; it++) {
        { EpiOut e = epi0();
          e.ph = p.xzh; e.pl = p.xzl; e.palpha = 1.f; e.ldp = MM; e.sP = MMh;
          e.th = p.tah; e.tl = p.tal; e.talpha = -1.f; e.tdiag = 7.f; e.ldt = MM; e.sT = MMh;
          gemmP(p.a2h, p.a2l, zcth, zctl, MM, MM, MM, MM, MM, MMh, MMh, HEADS, 1, e); }
        { EpiOut e = epi0();
          e.th = p.tbh; e.tl = p.tbl; e.talpha = -1.f; e.tdiag = 15.f; e.ldt = MM; e.sT = MMh;
          gemmP(p.xzh, p.xzl, p.tah, p.tal, MM, MM, MM, MM, MM, MMh, MMh, HEADS, 1, e); }
        { EpiOut e = epi0();
          e.th = p.tah; e.tl = p.tal; e.talpha = -1.f; e.tdiag = 13.f; e.ldt = MM; e.sT = MMh;
          gemmP(p.xzh, p.xzl, p.tbh, p.tbl, MM, MM, MM, MM, MM, MMh, MMh, HEADS, 1, e); }
        { EpiOut e = epi0();
          e.ph = znh; e.pl = znl; e.palpha = 0.25f; e.ldp = MM; e.sP = MMh;
          e.th = znth; e.tl = zntl; e.talpha = 0.25f; e.tdiag = 0.f; e.ldt = MM; e.sT = MMh;
          gemmP(zch, zcl, p.tah, p.tal, MM, MM, MM, MM, MM, MMh, MMh, HEADS, 1, e); }
        bf16* t;
        t = zch; zch = znh; znh = t;   t = zcl; zcl = znl; znl = t;
        t = zcth; zcth = znth; znth = t; t = zctl; zctl = zntl; zntl = t;
    }

    // 6) S3 = ql @ k^T -> fp32 S ; softmax -> S pair ; a3v split-K
    { EpiOut e = epi0(); e.f = p.S; e.falpha = 1.f; e.ldf = NP; e.sF = Sst;
      gemmP(p.qlh, p.qll, p.qkvh + 512, p.qkvl + 512, MM, NP, DH,
            DH, QKVW, (long)MM * DH, 64, HEADS, 1, e); }
    softmax_long_k<<<HEADS * MM, 256>>>(p.S, p.Sh, p.Sl, NP);
    vT_k<<<dim3(NP / 32, HEADS * 2, 2), dim3(32, 8)>>>(p.qkvh, p.qkvl, p.vth, p.vtl);
    { EpiOut e = epi0(); e.f = p.outl; e.falpha = 1.f; e.ldf = DH; e.sF = (long)MM * DH;
      gemmP(p.Sh, p.Sl, p.vth, p.vtl, MM, DH, NP, NP, NP,
            Sst, (long)DH * NP, HEADS, 8, e); }
    reduce8_k<<<(HEADS * MM * DH + 255) / 256, 256>>>(p.outl, p.a3h, p.a3l);

    // 7) W^T pair = (z @ a3v)^T
    { EpiOut e = epi0(); e.th = p.Wth; e.tl = p.Wtl; e.talpha = 1.f; e.tdiag = 0.f;
      e.ldt = MM; e.sT = (long)DH * MM;
      gemmP(zch, zcl, p.a3h, p.a3l, MM, DH, MM, MM, MM, MMh, (long)DH * MM, HEADS, 1, e); }

    // 8) S1 = 0.125 * q @ kl^T -> fp32 S ; softmax -> pair ; O1 -> attn fp32
    { EpiOut e = epi0(); e.f = p.S; e.falpha = 0.125f; e.ldf = MM; e.sF = Sst;
      gemmP(p.qkvh, p.qkvl, p.klh, p.kll, NP, MM, DH,
            QKVW, DH, 64, (long)MM * DH, HEADS, 1, e); }
    softmax256_k<<<(int)(((long)HEADS * NP + 7) / 8), dim3(32, 8)>>>(p.S, (float*)0,
                                                                     p.Sh, p.Sl, (long)HEADS * NP);
    { EpiOut e = epi0(); e.f = p.attn; e.falpha = 1.f; e.ldf = C; e.sF = 64;
      gemmP(p.Sh, p.Sl, p.Wth, p.Wtl, NP, DH, MM,
            MM, MM, Sst, (long)DH * MM, HEADS, 1, e); }

    // 9) attn pair = attn + conv(v)
    conv_add_k<<<NP, C>>>(p.qkvh, p.qkvl, res_w, p.attn, p.ath, p.atl);

    // 10) out = attn[PADN:] @ wout ; h += out + bias
    { EpiOut e = epi0(); e.f = p.outl; e.falpha = 1.f; e.ldf = C;
      gemmP(p.ath + (long)PADN * C, p.atl + (long)PADN * C, p.w2h, p.w2l,
            NH, C, C, C, C, 0, 0, 1, 1, e); }
    resid_add_k<<<(int)(((long)NH * C + 255) / 256), 256>>>(h_io, p.outl, b_out);
}

extern "C" void kernel_launch(void* const* d_in, const int* in_sizes, int n_in,
                              void* d_out, int out_size)
{
    const float* features = (const float*)d_in[0];
    const float* cls      = (const float*)d_in[1];
    const float* ln1_g    = (const float*)d_in[2];
    const float* ln1_b    = (const float*)d_in[3];
    const float* qkv1_w   = (const float*)d_in[4];
    const float* out1_w   = (const float*)d_in[5];
    const float* out1_b   = (const float*)d_in[6];
    const float* res1_w   = (const float*)d_in[7];
    const float* pe_w7    = (const float*)d_in[8];
    const float* pe_b7    = (const float*)d_in[9];
    const float* pe_w5    = (const float*)d_in[10];
    const float* pe_b5    = (const float*)d_in[11];
    const float* pe_w3    = (const float*)d_in[12];
    const float* pe_b3    = (const float*)d_in[13];
    const float* ln2_g    = (const float*)d_in[14];
    const float* ln2_b    = (const float*)d_in[15];
    const float* qkv2_w   = (const float*)d_in[16];
    const float* out2_w   = (const float*)d_in[17];
    const float* out2_b   = (const float*)d_in[18];
    const float* res2_w   = (const float*)d_in[19];

    cudaFuncSetAttribute(gemm_p, cudaFuncAttributeMaxDynamicSharedMemorySize, GP_SMEM);

    Ptrs p; get_ptrs(p);

    build_h_k<<<(int)(((long)NH * C + 255) / 256), 256>>>(features, cls, p.h);

    nystrom_layer(p, p.h, ln1_g, ln1_b, qkv1_w, out1_w, out1_b, res1_w);

    ppeg_k<<<dim3(HW, HW), C>>>(p.h, p.h2, pe_w7, pe_b7, pe_w5, pe_b5, pe_w3, pe_b3);

    nystrom_layer(p, p.h2, ln2_g, ln2_b, qkv2_w, out2_w, out2_b, res2_w);

    cudaMemcpyAsync(d_out, p.h2, (size_t)out_size * sizeof(float),
                    cudaMemcpyDeviceToDevice);
}

// round 6
// speedup vs baseline: 2.5985x; 1.0464x over previous
#include <cuda_runtime.h>
#include <cuda_bf16.h>
#include <math.h>
#include <stdint.h>

typedef __nv_bfloat16 bf16;

// ---------------- problem constants ----------------
#define NH    22501
#define NFEAT 22400
#define HW    150
#define C     512
#define NP    22528
#define PADN  27
#define HEADS 8
#define DH    64
#define MM    256
#define LL    88
#define QKVW  1536

// ---------------- fp32 scratch ----------------
__device__ float g_h   [(long)NH*C];
__device__ float g_h2  [(long)NH*C];
__device__ float g_S   [(long)HEADS*NP*MM];
__device__ float g_a2  [HEADS*MM*MM];
__device__ float g_attn[(long)NP*C];
__device__ float g_outl[(long)NH*C];          // split-K partials
__device__ float g_rowsum[HEADS*MM];
__device__ float g_colsum[HEADS*MM];
__device__ float g_srow[HEADS*MM];
__device__ float g_scale[1];

// ---------------- bf16 hi/lo pair scratch ----------------
__device__ bf16 g_xph[(long)NP*C],     g_xpl[(long)NP*C];
__device__ bf16 g_qkvh[(long)NP*QKVW], g_qkvl[(long)NP*QKVW];
__device__ bf16 g_qlh[HEADS*MM*DH],    g_qll[HEADS*MM*DH];
__device__ bf16 g_klh[HEADS*MM*DH],    g_kll[HEADS*MM*DH];
__device__ bf16 g_Shh[(long)HEADS*NP*MM], g_Sll[(long)HEADS*NP*MM];
__device__ bf16 g_a2h[HEADS*MM*MM],    g_a2l[HEADS*MM*MM];
__device__ bf16 g_zh [HEADS*MM*MM], g_zl [HEADS*MM*MM];
__device__ bf16 g_zth[HEADS*MM*MM], g_ztl[HEADS*MM*MM];
__device__ bf16 g_z2h[HEADS*MM*MM], g_z2l[HEADS*MM*MM];
__device__ bf16 g_z2th[HEADS*MM*MM], g_z2tl[HEADS*MM*MM];
__device__ bf16 g_xzh[HEADS*MM*MM], g_xzl[HEADS*MM*MM];
__device__ bf16 g_tah[HEADS*MM*MM], g_tal[HEADS*MM*MM];
__device__ bf16 g_tbh[HEADS*MM*MM], g_tbl[HEADS*MM*MM];
__device__ bf16 g_vth[(long)HEADS*DH*NP], g_vtl[(long)HEADS*DH*NP];
__device__ bf16 g_a3h[HEADS*DH*MM],    g_a3l[HEADS*DH*MM];
__device__ bf16 g_Wth[HEADS*DH*MM],    g_Wtl[HEADS*DH*MM];
__device__ bf16 g_ath[(long)NP*C],     g_atl[(long)NP*C];
__device__ bf16 g_w1ah[(long)QKVW*C],  g_w1al[(long)QKVW*C];  // L1 wqkv^T
__device__ bf16 g_w2ah[(long)C*C],     g_w2al[(long)C*C];     // L1 wout^T
__device__ bf16 g_w1bh[(long)QKVW*C],  g_w1bl[(long)QKVW*C];  // L2 wqkv^T
__device__ bf16 g_w2bh[(long)C*C],     g_w2bl[(long)C*C];     // L2 wout^T

// ---------------- small device helpers ----------------
__device__ __forceinline__ uint32_t smem_to_u32(const void* p) {
    uint32_t a;
    asm("{ .reg .u64 t; cvta.to.shared.u64 t, %1; cvt.u32.u64 %0, t; }"
        : "=r"(a) : "l"(p));
    return a;
}
__device__ __forceinline__ void ldsm4(uint32_t addr, uint32_t& r0, uint32_t& r1,
                                      uint32_t& r2, uint32_t& r3)
{
    asm volatile("ldmatrix.sync.aligned.m8n8.x4.shared.b16 {%0,%1,%2,%3}, [%4];"
                 : "=r"(r0), "=r"(r1), "=r"(r2), "=r"(r3) : "r"(addr));
}
__device__ __forceinline__ void mma_bf16(float* c, const uint32_t* a,
                                         uint32_t b0, uint32_t b1)
{
    asm volatile("mma.sync.aligned.m16n8k16.row.col.f32.bf16.bf16.f32 "
                 "{%0,%1,%2,%3},{%4,%5,%6,%7},{%8,%9},{%0,%1,%2,%3};"
                 : "+f"(c[0]), "+f"(c[1]), "+f"(c[2]), "+f"(c[3])
                 : "r"(a[0]), "r"(a[1]), "r"(a[2]), "r"(a[3]), "r"(b0), "r"(b1));
}
__device__ __forceinline__ void cpa16(uint32_t dst, const void* src, int sz)
{
    asm volatile("cp.async.cg.shared.global [%0], [%1], 16, %2;"
                 :: "r"(dst), "l"(src), "r"(sz));
}
__device__ __forceinline__ uint32_t pack2(float a, float b)   // a->low, b->high
{
    uint32_t r;
    asm("cvt.rn.bf16x2.f32 %0, %1, %2;" : "=r"(r) : "f"(b), "f"(a));
    return r;
}
__device__ __forceinline__ void split_bf(float x, float& hi, float& lo)
{
    hi = __bfloat162float(__float2bfloat16(x));
    lo = x - hi;
}
__device__ __forceinline__ float pairval(const bf16* h, const bf16* l, long i)
{
    return __bfloat162float(h[i]) + __bfloat162float(l[i]);
}

// =======================================================================
// bf16x3 GEMM, operands pre-split; B always [N,K]. cp.async 3-stage.
// Tile 128x64x32, 256 threads, 8 warps (4m x 2n).
// =======================================================================
#define RS      80
#define AH_OFF  0
#define AL_OFF  10240
#define BH_OFF  20480
#define BL_OFF  25600
#define STAGE   30720
#define GP_SMEM (3 * STAGE)

struct EpiOut {
    float* f; float falpha; int ldf; long sF;              // fp32 out
    bf16 *ph, *pl; float palpha; int ldp; long sP;         // plain pair out
    bf16 *th, *tl; float talpha, tdiag; int ldt; long sT;  // transposed pair out (+diag)
    const float* resid;                                    // fp32 residual add
    const float* bias;                                     // per-col bias add
};

__global__ void __launch_bounds__(256)
gemm_p(const bf16* __restrict__ Ah, const bf16* __restrict__ Al,
       const bf16* __restrict__ Bh, const bf16* __restrict__ Bl,
       int M, int K, int lda, int ldb, long sA, long sB,
       EpiOut ep, int ksplit)
{
    extern __shared__ __align__(16) char sm[];
    const uint32_t sb0 = smem_to_u32(sm);
    const int tid = threadIdx.x, warp = tid >> 5, lane = tid & 31;
    const int wm = warp & 3, wn = warp >> 2;

    const int z = blockIdx.z;
    const int batch = z / ksplit;
    const int split = z - batch * ksplit;
    Ah += (long)batch * sA;  Al += (long)batch * sA;
    Bh += (long)batch * sB;  Bl += (long)batch * sB;

    const int row0 = blockIdx.y * 128, col0 = blockIdx.x * 64;
    const int kchunk = K / ksplit, kbase = split * kchunk, nch = kchunk >> 5;

    float acc[2][4][4];
    #pragma unroll
    for (int i = 0; i < 2; i++)
        #pragma unroll
        for (int j = 0; j < 4; j++)
            #pragma unroll
            for (int q = 0; q < 4; q++) acc[i][j][q] = 0.f;

    auto issue = [&](int it) {
        const int stg = it % 3;
        const uint32_t sb = sb0 + stg * STAGE;
        const int kc = kbase + it * 32;
        #pragma unroll
        for (int rep = 0; rep < 2; rep++) {
            int c = tid + rep * 256;
            int row = c >> 2, seg = c & 3;
            int gm = row0 + row;
            long go = (long)gm * lda + kc + seg * 8;
            int sz = (gm < M) ? 16 : 0;
            cpa16(sb + AH_OFF + row * RS + seg * 16, Ah + go, sz);
            cpa16(sb + AL_OFF + row * RS + seg * 16, Al + go, sz);
        }
        {
            int n = tid >> 2, seg = tid & 3;
            long go = (long)(col0 + n) * ldb + kc + seg * 8;
            cpa16(sb + BH_OFF + n * RS + seg * 16, Bh + go, 16);
            cpa16(sb + BL_OFF + n * RS + seg * 16, Bl + go, 16);
        }
        asm volatile("cp.async.commit_group;");
    };

    const int rsel = (lane & 7) + ((lane >> 3) & 1) * 8;
    const int ksel = ((lane >> 4) & 1) * 16;
    auto do_mma = [&](int stg) {
        uint32_t sb = sb0 + stg * STAGE;
        #pragma unroll
        for (int kk = 0; kk < 2; kk++) {
            uint32_t ah[2][4], al[2][4], bh[4][2], bl[4][2];
            #pragma unroll
            for (int mt = 0; mt < 2; mt++) {
                uint32_t ad = sb + AH_OFF + (wm * 32 + mt * 16 + rsel) * RS + kk * 32 + ksel;
                ldsm4(ad, ah[mt][0], ah[mt][1], ah[mt][2], ah[mt][3]);
                ldsm4(ad + (AL_OFF - AH_OFF), al[mt][0], al[mt][1], al[mt][2], al[mt][3]);
            }
            #pragma unroll
            for (int np = 0; np < 2; np++) {
                uint32_t bd = sb + BH_OFF + (wn * 32 + np * 16 + rsel) * RS + kk * 32 + ksel;
                uint32_t q0, q1, q2, q3;
                ldsm4(bd, q0, q1, q2, q3);
                bh[2*np][0] = q0; bh[2*np][1] = q2;
                bh[2*np+1][0] = q1; bh[2*np+1][1] = q3;
                ldsm4(bd + (BL_OFF - BH_OFF), q0, q1, q2, q3);
                bl[2*np][0] = q0; bl[2*np][1] = q2;
                bl[2*np+1][0] = q1; bl[2*np+1][1] = q3;
            }
            #pragma unroll
            for (int mt = 0; mt < 2; mt++)
                #pragma unroll
                for (int nt = 0; nt < 4; nt++) {
                    mma_bf16(acc[mt][nt], ah[mt], bh[nt][0], bh[nt][1]);
                    mma_bf16(acc[mt][nt], ah[mt], bl[nt][0], bl[nt][1]);
                    mma_bf16(acc[mt][nt], al[mt], bh[nt][0], bh[nt][1]);
                }
        }
    };

    issue(0);
    if (nch > 1) issue(1);
    for (int it = 0; it < nch; it++) {
        if (it + 1 < nch) asm volatile("cp.async.wait_group 1;");
        else              asm volatile("cp.async.wait_group 0;");
        __syncthreads();
        if (it + 2 < nch) issue(it + 2);
        do_mma(it % 3);
    }

    // ---- epilogue ----
    const int er = lane >> 2, eq = lane & 3;
    float* F  = ep.f  ? ep.f  + (long)z     * ep.sF : (float*)0;
    bf16* Ph  = ep.ph ? ep.ph + (long)batch * ep.sP : (bf16*)0;
    bf16* Pl  = ep.pl ? ep.pl + (long)batch * ep.sP : (bf16*)0;
    bf16* Th  = ep.th ? ep.th + (long)batch * ep.sT : (bf16*)0;
    bf16* Tl  = ep.tl ? ep.tl + (long)batch * ep.sT : (bf16*)0;

    #pragma unroll
    for (int mt = 0; mt < 2; mt++)
        #pragma unroll
        for (int nt = 0; nt < 4; nt++) {
            int gr0 = row0 + wm * 32 + mt * 16 + er;
            int gc  = col0 + wn * 32 + nt * 8 + 2 * eq;
            #pragma unroll
            for (int half = 0; half < 2; half++) {
                int gr = gr0 + 8 * half;
                if (gr >= M) continue;
                float va = acc[mt][nt][2 * half], vb = acc[mt][nt][2 * half + 1];
                if (F) {
                    float o0 = ep.falpha * va, o1 = ep.falpha * vb;
                    if (ep.bias)  { o0 += ep.bias[gc]; o1 += ep.bias[gc + 1]; }
                    if (ep.resid) {
                        o0 += ep.resid[(long)gr * ep.ldf + gc];
                        o1 += ep.resid[(long)gr * ep.ldf + gc + 1];
                    }
                    *reinterpret_cast<float2*>(F + (long)gr * ep.ldf + gc) =
                        make_float2(o0, o1);
                }
                if (Ph) {
                    float s0 = ep.palpha * va, s1 = ep.palpha * vb;
                    float h0, l0, h1, l1;
                    split_bf(s0, h0, l0); split_bf(s1, h1, l1);
                    *reinterpret_cast<uint32_t*>(Ph + (long)gr * ep.ldp + gc) = pack2(h0, h1);
                    *reinterpret_cast<uint32_t*>(Pl + (long)gr * ep.ldp + gc) = pack2(l0, l1);
                }
                if (Th) {
                    #pragma unroll
                    for (int j = 0; j < 2; j++) {
                        int cc = gc + j;
                        float v = (j == 0) ? va : vb;
                        float s = ep.talpha * v + ((gr == cc) ? ep.tdiag : 0.f);
                        float hi, lo; split_bf(s, hi, lo);
                        Th[(long)cc * ep.ldt + gr] = __float2bfloat16(hi);
                        Tl[(long)cc * ep.ldt + gr] = __float2bfloat16(lo);
                    }
                }
            }
        }
}

static EpiOut epi0() { EpiOut e{}; return e; }
static void gemmP(const bf16* Ah, const bf16* Al, const bf16* Bh, const bf16* Bl,
                  int M, int N, int K, int lda, int ldb, long sA, long sB,
                  int batch, int ksplit, EpiOut ep)
{
    dim3 g(N / 64, (M + 127) / 128, batch * ksplit), b(256);
    gemm_p<<<g, b, GP_SMEM>>>(Ah, Al, Bh, Bl, M, K, lda, ldb, sA, sB, ep, ksplit);
}

// =======================================================================
// fused S1 -> softmax -> O1 : per CTA 64 q-rows x 256 landmarks, one head
// phase1: S = 0.125 * q @ kl^T (K=64), softmax in regs (sum deferred)
// phase2: O = P @ W (K=256), W cp.async 3-stage; out /= rowsum -> attn fp32
// =======================================================================
#define FA_RS1  144
#define FA_AH   0
#define FA_AL   9216
#define FA_BH   18432
#define FA_BL   55296                 // phase1 ends 92160
#define FA_PH   0
#define FA_PL   33792                 // P ends 67584 (row stride 528)
#define FA_WS   67584                 // 3 stages x 10240 -> 98304
#define FA_WST  10240
#define FA_SMEM 98304

__global__ void __launch_bounds__(128)
fused_attn1_k(const bf16* __restrict__ qh, const bf16* __restrict__ ql_,
              const bf16* __restrict__ klh, const bf16* __restrict__ kll,
              const bf16* __restrict__ Wth, const bf16* __restrict__ Wtl,
              float* __restrict__ attn)
{
    extern __shared__ __align__(16) char sm[];
    const uint32_t sb = smem_to_u32(sm);
    const int tid = threadIdx.x, warp = tid >> 5, lane = tid & 31;
    const int row0 = blockIdx.x * 64;
    const int head = blockIdx.y;

    // ---- phase0: load q tile + kl ----
    const bf16* qsh = qh  + (long)row0 * QKVW + head * DH;
    const bf16* qsl = ql_ + (long)row0 * QKVW + head * DH;
    #pragma unroll
    for (int i = 0; i < 4; i++) {
        int s = tid + 128 * i;            // 0..511
        int r = s >> 3, seg = s & 7;
        long go = (long)r * QKVW + seg * 8;
        cpa16(sb + FA_AH + r * FA_RS1 + seg * 16, qsh + go, 16);
        cpa16(sb + FA_AL + r * FA_RS1 + seg * 16, qsl + go, 16);
    }
    const bf16* ksh = klh + (long)head * MM * DH;
    const bf16* ksl = kll + (long)head * MM * DH;
    #pragma unroll
    for (int i = 0; i < 16; i++) {
        int s = tid + 128 * i;            // 0..2047
        int r = s >> 3, seg = s & 7;
        long go = (long)r * DH + seg * 8;
        cpa16(sb + FA_BH + r * FA_RS1 + seg * 16, ksh + go, 16);
        cpa16(sb + FA_BL + r * FA_RS1 + seg * 16, ksl + go, 16);
    }
    asm volatile("cp.async.commit_group;");
    asm volatile("cp.async.wait_group 0;");
    __syncthreads();

    // ---- phase1 mma: sacc[32 n8-tiles][4] ----
    const int rsel = (lane & 7) + ((lane >> 3) & 1) * 8;
    const int ksel = ((lane >> 4) & 1) * 16;
    float sacc[32][4];
    #pragma unroll
    for (int i = 0; i < 32; i++)
        #pragma unroll
        for (int j = 0; j < 4; j++) sacc[i][j] = 0.f;

    #pragma unroll
    for (int k16 = 0; k16 < 4; k16++) {
        uint32_t ah[4], al[4];
        uint32_t ad = sb + FA_AH + (warp * 16 + rsel) * FA_RS1 + k16 * 32 + ksel;
        ldsm4(ad, ah[0], ah[1], ah[2], ah[3]);
        ldsm4(ad + (FA_AL - FA_AH), al[0], al[1], al[2], al[3]);
        #pragma unroll
        for (int n16 = 0; n16 < 16; n16++) {
            uint32_t bd = sb + FA_BH + (n16 * 16 + rsel) * FA_RS1 + k16 * 32 + ksel;
            uint32_t q0, q1, q2, q3, p0, p1, p2, p3;
            ldsm4(bd, q0, q1, q2, q3);
            ldsm4(bd + (FA_BL - FA_BH), p0, p1, p2, p3);
            mma_bf16(sacc[2*n16],   ah, q0, q2);
            mma_bf16(sacc[2*n16],   ah, p0, p2);
            mma_bf16(sacc[2*n16],   al, q0, q2);
            mma_bf16(sacc[2*n16+1], ah, q1, q3);
            mma_bf16(sacc[2*n16+1], ah, p1, p3);
            mma_bf16(sacc[2*n16+1], al, q1, q3);
        }
    }

    // ---- softmax (rows er, er+8 of this warp's 16) ----
    float mx0 = -1e30f, mx1 = -1e30f;
    #pragma unroll
    for (int nt = 0; nt < 32; nt++) {
        #pragma unroll
        for (int j = 0; j < 4; j++) sacc[nt][j] *= 0.125f;
        mx0 = fmaxf(mx0, fmaxf(sacc[nt][0], sacc[nt][1]));
        mx1 = fmaxf(mx1, fmaxf(sacc[nt][2], sacc[nt][3]));
    }
    #pragma unroll
    for (int o = 1; o <= 2; o <<= 1) {
        mx0 = fmaxf(mx0, __shfl_xor_sync(0xffffffffu, mx0, o));
        mx1 = fmaxf(mx1, __shfl_xor_sync(0xffffffffu, mx1, o));
    }
    float sm0 = 0.f, sm1 = 0.f;
    #pragma unroll
    for (int nt = 0; nt < 32; nt++) {
        sacc[nt][0] = __expf(sacc[nt][0] - mx0);
        sacc[nt][1] = __expf(sacc[nt][1] - mx0);
        sacc[nt][2] = __expf(sacc[nt][2] - mx1);
        sacc[nt][3] = __expf(sacc[nt][3] - mx1);
        sm0 += sacc[nt][0] + sacc[nt][1];
        sm1 += sacc[nt][2] + sacc[nt][3];
    }
    #pragma unroll
    for (int o = 1; o <= 2; o <<= 1) {
        sm0 += __shfl_xor_sync(0xffffffffu, sm0, o);
        sm1 += __shfl_xor_sync(0xffffffffu, sm1, o);
    }
    __syncthreads();          // all phase1 smem reads complete

    // ---- prefetch W chunks 0,1 (region beyond phase1 data) ----
    const bf16* Wsh = Wth + (long)head * DH * MM;
    const bf16* Wsl = Wtl + (long)head * DH * MM;
    auto wissue = [&](int it) {
        int stg = it % 3;
        uint32_t base = sb + FA_WS + stg * FA_WST;
        #pragma unroll
        for (int i = 0; i < 2; i++) {
            int s = tid + 128 * i;        // 0..255
            int r = s >> 2, seg = s & 3;
            long go = (long)r * MM + it * 32 + seg * 8;
            cpa16(base + r * 80 + seg * 16, Wsh + go, 16);
            cpa16(base + 5120 + r * 80 + seg * 16, Wsl + go, 16);
        }
        asm volatile("cp.async.commit_group;");
    };
    wissue(0); wissue(1);

    // ---- write P pair to smem ----
    {
        int pr = warp * 16 + (lane >> 2);
        int pc = (lane & 3) * 2;
        #pragma unroll
        for (int nt = 0; nt < 32; nt++) {
            int col = nt * 8 + pc;
            float h0, l0, h1, l1;
            split_bf(sacc[nt][0], h0, l0); split_bf(sacc[nt][1], h1, l1);
            *reinterpret_cast<uint32_t*>(sm + FA_PH + pr * 528 + col * 2) = pack2(h0, h1);
            *reinterpret_cast<uint32_t*>(sm + FA_PL + pr * 528 + col * 2) = pack2(l0, l1);
            split_bf(sacc[nt][2], h0, l0); split_bf(sacc[nt][3], h1, l1);
            *reinterpret_cast<uint32_t*>(sm + FA_PH + (pr + 8) * 528 + col * 2) = pack2(h0, h1);
            *reinterpret_cast<uint32_t*>(sm + FA_PL + (pr + 8) * 528 + col * 2) = pack2(l0, l1);
        }
    }
    __syncthreads();

    // ---- phase2: O = P @ W ----
    float oacc[8][4];
    #pragma unroll
    for (int i = 0; i < 8; i++)
        #pragma unroll
        for (int j = 0; j < 4; j++) oacc[i][j] = 0.f;

    for (int it = 0; it < 8; it++) {
        if (it < 7) asm volatile("cp.async.wait_group 1;");
        else        asm volatile("cp.async.wait_group 0;");
        __syncthreads();
        if (it + 2 < 8) wissue(it + 2);
        uint32_t wb = sb + FA_WS + (it % 3) * FA_WST;
        #pragma unroll
        for (int k16 = 0; k16 < 2; k16++) {
            int gk = it * 2 + k16;
            uint32_t ph[4], pl[4];
            uint32_t ad = sb + FA_PH + (warp * 16 + rsel) * 528 + gk * 32 + ksel;
            ldsm4(ad, ph[0], ph[1], ph[2], ph[3]);
            ldsm4(ad + (FA_PL - FA_PH), pl[0], pl[1], pl[2], pl[3]);
            #pragma unroll
            for (int n16 = 0; n16 < 4; n16++) {
                uint32_t bd = wb + (n16 * 16 + rsel) * 80 + k16 * 32 + ksel;
                uint32_t q0, q1, q2, q3, r0, r1, r2, r3;
                ldsm4(bd, q0, q1, q2, q3);
                ldsm4(bd + 5120, r0, r1, r2, r3);
                mma_bf16(oacc[2*n16],   ph, q0, q2);
                mma_bf16(oacc[2*n16],   ph, r0, r2);
                mma_bf16(oacc[2*n16],   pl, q0, q2);
                mma_bf16(oacc[2*n16+1], ph, q1, q3);
                mma_bf16(oacc[2*n16+1], ph, r1, r3);
                mma_bf16(oacc[2*n16+1], pl, q1, q3);
            }
        }
    }

    // ---- epilogue: /= rowsum, write fp32 attn ----
    float inv0 = 1.f / sm0, inv1 = 1.f / sm1;
    int orow = row0 + warp * 16 + (lane >> 2);
    int ocol = head * DH + (lane & 3) * 2;
    #pragma unroll
    for (int nt = 0; nt < 8; nt++) {
        int col = ocol + nt * 8;
        *reinterpret_cast<float2*>(attn + (long)orow * C + col) =
            make_float2(oacc[nt][0] * inv0, oacc[nt][1] * inv0);
        *reinterpret_cast<float2*>(attn + (long)(orow + 8) * C + col) =
            make_float2(oacc[nt][2] * inv1, oacc[nt][3] * inv1);
    }
}

// =======================================================================
// auxiliary kernels
// =======================================================================

__global__ void wconvT_k(const float* __restrict__ w, bf16* __restrict__ th,
                         bf16* __restrict__ tl, int K, int N)
{
    int i = blockIdx.x * 256 + threadIdx.x;
    if (i >= N * K) return;
    int n = i / K, k = i - n * K;
    float v = w[(long)k * N + n];
    float hi, lo; split_bf(v, hi, lo);
    th[i] = __float2bfloat16(hi);
    tl[i] = __float2bfloat16(lo);
}

__global__ void build_h_k(const float* __restrict__ feat, const float* __restrict__ cls,
                          float* __restrict__ h)
{
    long i = (long)blockIdx.x * 256 + threadIdx.x;
    if (i >= (long)NH * C) return;
    long t = i >> 9;
    int  c = (int)(i & 511);
    float v;
    if (t == 0) v = cls[c];
    else {
        long r = t - 1;
        if (r >= NFEAT) r -= NFEAT;
        v = feat[r * C + c];
    }
    h[i] = v;
}

// layernorm -> front-padded xp pair (packed stores; thread owns cols 2c,2c+1)
__global__ void ln_pad_k(const float* __restrict__ h, bf16* __restrict__ xh,
                         bf16* __restrict__ xl,
                         const float* __restrict__ g, const float* __restrict__ b)
{
    int t = blockIdx.x, c = threadIdx.x;
    long o = (long)t * C;
    if (t < PADN) {
        *reinterpret_cast<uint32_t*>(xh + o + 2 * c) = 0u;
        *reinterpret_cast<uint32_t*>(xl + o + 2 * c) = 0u;
        return;
    }
    const float* row = h + (long)(t - PADN) * C;
    float a1 = row[2 * c], a2 = row[2 * c + 1];
    __shared__ float red[256];
    red[c] = a1 + a2; __syncthreads();
    for (int s = 128; s > 0; s >>= 1) { if (c < s) red[c] += red[c + s]; __syncthreads(); }
    float mu = red[0] * (1.f / 512.f);
    __syncthreads();
    float d1 = a1 - mu, d2 = a2 - mu;
    red[c] = d1 * d1 + d2 * d2; __syncthreads();
    for (int s = 128; s > 0; s >>= 1) { if (c < s) red[c] += red[c + s]; __syncthreads(); }
    float inv = rsqrtf(red[0] * (1.f / 512.f) + 1e-5f);
    float v1 = d1 * inv * g[2 * c] + b[2 * c];
    float v2 = d2 * inv * g[2 * c + 1] + b[2 * c + 1];
    float h1, l1, h2, l2;
    split_bf(v1, h1, l1); split_bf(v2, h2, l2);
    *reinterpret_cast<uint32_t*>(xh + o + 2 * c) = pack2(h1, h2);
    *reinterpret_cast<uint32_t*>(xl + o + 2 * c) = pack2(l1, l2);
}

__global__ void landmarks_k(const bf16* __restrict__ qh, const bf16* __restrict__ ql_,
                            bf16* __restrict__ qlh, bf16* __restrict__ qll,
                            bf16* __restrict__ klh, bf16* __restrict__ kll)
{
    int d = threadIdx.x;
    int m = blockIdx.x & 255;
    int hh = blockIdx.x >> 8;
    long base = (long)(m * LL) * QKVW + hh * DH + d;
    float sq = 0.f, sk = 0.f;
    for (int j = 0; j < LL; j++) {
        long o = base + (long)j * QKVW;
        sq += pairval(qh, ql_, o);
        sk += pairval(qh, ql_, o + 512);
    }
    float vq = sq * (0.125f / (float)LL);
    float vk = sk * (1.f / (float)LL);
    int oi = (hh * MM + m) * DH + d;
    float hi, lo;
    split_bf(vq, hi, lo); qlh[oi] = __float2bfloat16(hi); qll[oi] = __float2bfloat16(lo);
    split_bf(vk, hi, lo); klh[oi] = __float2bfloat16(hi); kll[oi] = __float2bfloat16(lo);
}

// softmax over 256-col rows (a2 only); fp32 + pair out
__global__ void softmax256_k(const float* __restrict__ in, float* __restrict__ fout,
                             bf16* __restrict__ ph, bf16* __restrict__ pl, long nrows)
{
    long row = (long)blockIdx.x * 8 + threadIdx.y;
    if (row >= nrows) return;
    const float* r = in + row * 256;
    int lane = threadIdx.x;
    float v[8], m = -1e30f;
    #pragma unroll
    for (int i = 0; i < 8; i++) { v[i] = r[lane + 32 * i]; m = fmaxf(m, v[i]); }
    #pragma unroll
    for (int o = 16; o; o >>= 1) m = fmaxf(m, __shfl_xor_sync(0xffffffffu, m, o));
    float s = 0.f;
    #pragma unroll
    for (int i = 0; i < 8; i++) { v[i] = __expf(v[i] - m); s += v[i]; }
    #pragma unroll
    for (int o = 16; o; o >>= 1) s += __shfl_xor_sync(0xffffffffu, s, o);
    float inv = 1.f / s;
    #pragma unroll
    for (int i = 0; i < 8; i++) {
        float val = v[i] * inv;
        long o = row * 256 + lane + 32 * i;
        if (fout) fout[o] = val;
        float hi, lo; split_bf(val, hi, lo);
        ph[o] = __float2bfloat16(hi);
        pl[o] = __float2bfloat16(lo);
    }
}

// softmax long rows: unnormalized exp pairs + rowsum (scaling folded downstream)
__global__ void softmax_long_k(const float* __restrict__ S, bf16* __restrict__ ph,
                               bf16* __restrict__ pl, float* __restrict__ srow, int cols)
{
    const float* row = S + (long)blockIdx.x * cols;
    long ob = (long)blockIdx.x * cols;
    __shared__ float red[256];
    int tid = threadIdx.x;
    float m = -1e30f;
    for (int i = tid; i < cols; i += 256) m = fmaxf(m, row[i]);
    red[tid] = m; __syncthreads();
    for (int s = 128; s > 0; s >>= 1) { if (tid < s) red[tid] = fmaxf(red[tid], red[tid + s]); __syncthreads(); }
    m = red[0]; __syncthreads();
    float sum = 0.f;
    for (int i = 2 * tid; i < cols; i += 512) {
        float e0 = __expf(row[i] - m), e1 = __expf(row[i + 1] - m);
        sum += e0 + e1;
        float h0, l0, h1, l1;
        split_bf(e0, h0, l0); split_bf(e1, h1, l1);
        *reinterpret_cast<uint32_t*>(ph + ob + i) = pack2(h0, h1);
        *reinterpret_cast<uint32_t*>(pl + ob + i) = pack2(l0, l1);
    }
    red[tid] = sum; __syncthreads();
    for (int s = 128; s > 0; s >>= 1) { if (tid < s) red[tid] += red[tid + s]; __syncthreads(); }
    if (tid == 0) srow[blockIdx.x] = red[0];
}

__global__ void pinv_sums_k(const float* __restrict__ a2,
                            float* __restrict__ rs, float* __restrict__ cs)
{
    int hh = blockIdx.x, j = threadIdx.x;
    const float* X = a2 + (long)hh * MM * MM;
    float r = 0.f, c = 0.f;
    for (int k = 0; k < MM; k++) { r += fabsf(X[j * MM + k]); c += fabsf(X[k * MM + j]); }
    rs[hh * MM + j] = r; cs[hh * MM + j] = c;
}
__global__ void pinv_scale_k(const float* __restrict__ rs, const float* __restrict__ cs,
                             float* __restrict__ scale)
{
    __shared__ float m1[256], m2[256];
    float a = -1e30f, b = -1e30f;
    for (int i = threadIdx.x; i < HEADS * MM; i += 256) { a = fmaxf(a, rs[i]); b = fmaxf(b, cs[i]); }
    m1[threadIdx.x] = a; m2[threadIdx.x] = b; __syncthreads();
    for (int s = 128; s > 0; s >>= 1) {
        if (threadIdx.x < s) {
            m1[threadIdx.x] = fmaxf(m1[threadIdx.x], m1[threadIdx.x + s]);
            m2[threadIdx.x] = fmaxf(m2[threadIdx.x], m2[threadIdx.x + s]);
        }
        __syncthreads();
    }
    if (threadIdx.x == 0) scale[0] = 1.f / (m1[0] * m2[0]);
}
__global__ void pinv_init_k(const float* __restrict__ a2, const float* __restrict__ scale,
                            bf16* __restrict__ zph, bf16* __restrict__ zpl,
                            bf16* __restrict__ zth, bf16* __restrict__ ztl)
{
    long i = (long)blockIdx.x * 256 + threadIdx.x;
    if (i >= (long)HEADS * MM * MM) return;
    float s = scale[0];
    long hb = i & ~65535L;
    int r = (int)((i >> 8) & 255), c = (int)(i & 255);
    float vt = a2[i] * s;
    float vp = a2[hb + ((long)c << 8) + r] * s;
    float hi, lo;
    split_bf(vt, hi, lo); zth[i] = __float2bfloat16(hi); ztl[i] = __float2bfloat16(lo);
    split_bf(vp, hi, lo); zph[i] = __float2bfloat16(hi); zpl[i] = __float2bfloat16(lo);
}

__global__ void vT_k(const bf16* __restrict__ qh, const bf16* __restrict__ ql_,
                     bf16* __restrict__ vth, bf16* __restrict__ vtl)
{
    __shared__ bf16 tile[32][33];
    int t0 = blockIdx.x * 32;
    int head = blockIdx.y >> 1;
    int lopart = blockIdx.y & 1;
    int d0 = blockIdx.z * 32;
    const bf16* src = (lopart ? ql_ : qh) + 1024 + head * 64 + d0;
    bf16* dst = (lopart ? vtl : vth) + (long)head * 64 * NP + (long)d0 * NP;
    int tx = threadIdx.x, ty = threadIdx.y;
    #pragma unroll
    for (int i = 0; i < 4; i++)
        tile[ty + 8 * i][tx] = src[(long)(t0 + ty + 8 * i) * QKVW + tx];
    __syncthreads();
    #pragma unroll
    for (int i = 0; i < 4; i++)
        dst[(long)(ty + 8 * i) * NP + t0 + tx] = tile[tx][ty + 8 * i];
}

// split-K reduce -> a3v^T pair [head][d][m]; applies 1/rowsum
__global__ void reduce8_k(const float* __restrict__ part, const float* __restrict__ srow,
                          bf16* __restrict__ oh, bf16* __restrict__ ol)
{
    int i = blockIdx.x * 256 + threadIdx.x;
    if (i >= HEADS * MM * DH) return;
    int head = i >> 14;
    int r = i & 16383;
    int m = r >> 6, d = r & 63;
    float s = 0.f;
    #pragma unroll
    for (int k = 0; k < 8; k++) s += part[(long)((head << 3) + k) * 16384 + r];
    s *= 1.f / srow[(head << 8) + m];
    float hi, lo; split_bf(s, hi, lo);
    long o = (long)(head << 14) + d * 256 + m;
    oh[o] = __float2bfloat16(hi);
    ol[o] = __float2bfloat16(lo);
}

__global__ void conv_add_k(const bf16* __restrict__ qh, const bf16* __restrict__ ql_,
                           const float* __restrict__ rw, const float* __restrict__ attnf,
                           bf16* __restrict__ ah, bf16* __restrict__ al)
{
    int t = blockIdx.x, c = threadIdx.x;
    int hh = c >> 6;
    float acc = attnf[(long)t * C + c];
    #pragma unroll
    for (int k = 0; k < 33; k++) {
        int tt = t + k - 16;
        if ((unsigned)tt < (unsigned)NP)
            acc += pairval(qh, ql_, (long)tt * QKVW + 1024 + c) * rw[hh * 33 + k];
    }
    float hi, lo; split_bf(acc, hi, lo);
    long o = (long)t * C + c;
    ah[o] = __float2bfloat16(hi);
    al[o] = __float2bfloat16(lo);
}

__global__ void ppeg_k(const float* __restrict__ h, float* __restrict__ h2,
                       const float* __restrict__ w7, const float* __restrict__ b7,
                       const float* __restrict__ w5, const float* __restrict__ b5,
                       const float* __restrict__ w3, const float* __restrict__ b3)
{
    int x = blockIdx.x, y = blockIdx.y, c = threadIdx.x;
    if (x == 0 && y == 0) h2[c] = h[c];
    float acc = h[(long)(1 + y * HW + x) * C + c];
    #pragma unroll
    for (int ky = 0; ky < 7; ky++) {
        int yy = y + ky - 3; if (yy < 0 || yy >= HW) continue;
        #pragma unroll
        for (int kx = 0; kx < 7; kx++) {
            int xx = x + kx - 3; if (xx < 0 || xx >= HW) continue;
            acc += h[(long)(1 + yy * HW + xx) * C + c] * w7[c * 49 + ky * 7 + kx];
        }
    }
    #pragma unroll
    for (int ky = 0; ky < 5; ky++) {
        int yy = y + ky - 2; if (yy < 0 || yy >= HW) continue;
        #pragma unroll
        for (int kx = 0; kx < 5; kx++) {
            int xx = x + kx - 2; if (xx < 0 || xx >= HW) continue;
            acc += h[(long)(1 + yy * HW + xx) * C + c] * w5[c * 25 + ky * 5 + kx];
        }
    }
    #pragma unroll
    for (int ky = 0; ky < 3; ky++) {
        int yy = y + ky - 1; if (yy < 0 || yy >= HW) continue;
        #pragma unroll
        for (int kx = 0; kx < 3; kx++) {
            int xx = x + kx - 1; if (xx < 0 || xx >= HW) continue;
            acc += h[(long)(1 + yy * HW + xx) * C + c] * w3[c * 9 + ky * 3 + kx];
        }
    }
    acc += b7[c] + b5[c] + b3[c];
    h2[(long)(1 + y * HW + x) * C + c] = acc;
}

// ================= host orchestration =================
struct Ptrs {
    float *h, *h2, *S, *a2, *attn, *outl, *rowsum, *colsum, *srow, *scale;
    bf16 *xph, *xpl, *qkvh, *qkvl, *qlh, *qll, *klh, *kll, *Sh, *Sl,
         *a2h, *a2l, *zh, *zl, *zth, *ztl, *z2h, *z2l, *z2th, *z2tl,
         *xzh, *xzl, *tah, *tal, *tbh, *tbl, *vth, *vtl,
         *a3h, *a3l, *Wth, *Wtl, *ath, *atl,
         *w1ah, *w1al, *w2ah, *w2al, *w1bh, *w1bl, *w2bh, *w2bl;
};
#define GSYM(f, s) cudaGetSymbolAddress((void**)&p.f, s)
static void get_ptrs(Ptrs& p)
{
    GSYM(h, g_h); GSYM(h2, g_h2); GSYM(S, g_S); GSYM(a2, g_a2);
    GSYM(attn, g_attn); GSYM(outl, g_outl);
    GSYM(rowsum, g_rowsum); GSYM(colsum, g_colsum); GSYM(srow, g_srow); GSYM(scale, g_scale);
    GSYM(xph, g_xph); GSYM(xpl, g_xpl); GSYM(qkvh, g_qkvh); GSYM(qkvl, g_qkvl);
    GSYM(qlh, g_qlh); GSYM(qll, g_qll); GSYM(klh, g_klh); GSYM(kll, g_kll);
    GSYM(Sh, g_Shh); GSYM(Sl, g_Sll); GSYM(a2h, g_a2h); GSYM(a2l, g_a2l);
    GSYM(zh, g_zh); GSYM(zl, g_zl); GSYM(zth, g_zth); GSYM(ztl, g_ztl);
    GSYM(z2h, g_z2h); GSYM(z2l, g_z2l); GSYM(z2th, g_z2th); GSYM(z2tl, g_z2tl);
    GSYM(xzh, g_xzh); GSYM(xzl, g_xzl);
    GSYM(tah, g_tah); GSYM(tal, g_tal); GSYM(tbh, g_tbh); GSYM(tbl, g_tbl);
    GSYM(vth, g_vth); GSYM(vtl, g_vtl); GSYM(a3h, g_a3h); GSYM(a3l, g_a3l);
    GSYM(Wth, g_Wth); GSYM(Wtl, g_Wtl); GSYM(ath, g_ath); GSYM(atl, g_atl);
    GSYM(w1ah, g_w1ah); GSYM(w1al, g_w1al); GSYM(w2ah, g_w2ah); GSYM(w2al, g_w2al);
    GSYM(w1bh, g_w1bh); GSYM(w1bl, g_w1bl); GSYM(w2bh, g_w2bh); GSYM(w2bl, g_w2bl);
}

static void nystrom_layer(Ptrs& p, float* h_io,
                          const float* ln_g, const float* ln_b,
                          const bf16* w1h, const bf16* w1l,
                          const bf16* w2h, const bf16* w2l,
                          const float* b_out, const float* res_w)
{
    const long MMh = (long)MM * MM;
    const long Sst = (long)NP * MM;

    // 1) LN + pad -> xp pair
    ln_pad_k<<<NP, 256>>>(h_io, p.xph, p.xpl, ln_g, ln_b);

    // 2) qkv pair = xp @ wqkv
    { EpiOut e = epi0(); e.ph = p.qkvh; e.pl = p.qkvl; e.palpha = 1.f; e.ldp = QKVW;
      gemmP(p.xph, p.xpl, w1h, w1l, NP, QKVW, C, C, C, 0, 0, 1, 1, e); }

    // 3) landmarks
    landmarks_k<<<HEADS * MM, DH>>>(p.qkvh, p.qkvl, p.qlh, p.qll, p.klh, p.kll);

    // 4) a2 = softmax(ql @ kl^T)
    { EpiOut e = epi0(); e.f = p.a2; e.falpha = 1.f; e.ldf = MM; e.sF = MMh;
      gemmP(p.qlh, p.qll, p.klh, p.kll, MM, MM, DH, DH, DH,
            (long)MM * DH, (long)MM * DH, HEADS, 1, e); }
    softmax256_k<<<(HEADS * MM + 7) / 8, dim3(32, 8)>>>(p.a2, p.a2, p.a2h, p.a2l, HEADS * MM);

    // 5) pinv
    pinv_sums_k<<<HEADS, 256>>>(p.a2, p.rowsum, p.colsum);
    pinv_scale_k<<<1, 256>>>(p.rowsum, p.colsum, p.scale);
    pinv_init_k<<<(int)((HEADS * MMh + 255) / 256), 256>>>(p.a2, p.scale,
                                                           p.zh, p.zl, p.zth, p.ztl);
    bf16 *zch = p.zh, *zcl = p.zl, *zcth = p.zth, *zctl = p.ztl;
    bf16 *znh = p.z2h, *znl = p.z2l, *znth = p.z2th, *zntl = p.z2tl;
    for (int it = 0; it < 6; it++) {
        { EpiOut e = epi0();
          e.ph = p.xzh; e.pl = p.xzl; e.palpha = 1.f; e.ldp = MM; e.sP = MMh;
          e.th = p.tah; e.tl = p.tal; e.talpha = -1.f; e.tdiag = 7.f; e.ldt = MM; e.sT = MMh;
          gemmP(p.a2h, p.a2l, zcth, zctl, MM, MM, MM, MM, MM, MMh, MMh, HEADS, 1, e); }
        { EpiOut e = epi0();
          e.th = p.tbh; e.tl = p.tbl; e.talpha = -1.f; e.tdiag = 15.f; e.ldt = MM; e.sT = MMh;
          gemmP(p.xzh, p.xzl, p.tah, p.tal, MM, MM, MM, MM, MM, MMh, MMh, HEADS, 1, e); }
        { EpiOut e = epi0();
          e.th = p.tah; e.tl = p.tal; e.talpha = -1.f; e.tdiag = 13.f; e.ldt = MM; e.sT = MMh;
          gemmP(p.xzh, p.xzl, p.tbh, p.tbl, MM, MM, MM, MM, MM, MMh, MMh, HEADS, 1, e); }
        { EpiOut e = epi0();
          e.ph = znh; e.pl = znl; e.palpha = 0.25f; e.ldp = MM; e.sP = MMh;
          e.th = znth; e.tl = zntl; e.talpha = 0.25f; e.tdiag = 0.f; e.ldt = MM; e.sT = MMh;
          gemmP(zch, zcl, p.tah, p.tal, MM, MM, MM, MM, MM, MMh, MMh, HEADS, 1, e); }
        bf16* t;
        t = zch; zch = znh; znh = t;   t = zcl; zcl = znl; znl = t;
        t = zcth; zcth = znth; znth = t; t = zctl; zctl = zntl; zntl = t;
    }

    // 6) S3 = ql @ k^T -> fp32 ; exp-pairs + rowsum ; a3v split-K (scaled in reduce)
    { EpiOut e = epi0(); e.f = p.S; e.falpha = 1.f; e.ldf = NP; e.sF = Sst;
      gemmP(p.qlh, p.qll, p.qkvh + 512, p.qkvl + 512, MM, NP, DH,
            DH, QKVW, (long)MM * DH, 64, HEADS, 1, e); }
    softmax_long_k<<<HEADS * MM, 256>>>(p.S, p.Sh, p.Sl, p.srow, NP);
    vT_k<<<dim3(NP / 32, HEADS * 2, 2), dim3(32, 8)>>>(p.qkvh, p.qkvl, p.vth, p.vtl);
    { EpiOut e = epi0(); e.f = p.outl; e.falpha = 1.f; e.ldf = DH; e.sF = (long)MM * DH;
      gemmP(p.Sh, p.Sl, p.vth, p.vtl, MM, DH, NP, NP, NP,
            Sst, (long)DH * NP, HEADS, 8, e); }
    reduce8_k<<<(HEADS * MM * DH + 255) / 256, 256>>>(p.outl, p.srow, p.a3h, p.a3l);

    // 7) W^T pair = (z @ a3v)^T
    { EpiOut e = epi0(); e.th = p.Wth; e.tl = p.Wtl; e.talpha = 1.f; e.tdiag = 0.f;
      e.ldt = MM; e.sT = (long)DH * MM;
      gemmP(zch, zcl, p.a3h, p.a3l, MM, DH, MM, MM, MM, MMh, (long)DH * MM, HEADS, 1, e); }

    // 8) fused S1 -> softmax -> O1 -> attn fp32
    fused_attn1_k<<<dim3(NP / 64, HEADS), 128, FA_SMEM>>>(
        p.qkvh, p.qkvl, p.klh, p.kll, p.Wth, p.Wtl, p.attn);

    // 9) attn pair = attn + conv(v)
    conv_add_k<<<NP, C>>>(p.qkvh, p.qkvl, res_w, p.attn, p.ath, p.atl);

    // 10) h += attn[PADN:] @ wout + bias  (residual folded into epilogue)
    { EpiOut e = epi0(); e.f = h_io; e.falpha = 1.f; e.ldf = C;
      e.resid = h_io; e.bias = b_out;
      gemmP(p.ath + (long)PADN * C, p.atl + (long)PADN * C, w2h, w2l,
            NH, C, C, C, C, 0, 0, 1, 1, e); }
}

extern "C" void kernel_launch(void* const* d_in, const int* in_sizes, int n_in,
                              void* d_out, int out_size)
{
    const float* features = (const float*)d_in[0];
    const float* cls      = (const float*)d_in[1];
    const float* ln1_g    = (const float*)d_in[2];
    const float* ln1_b    = (const float*)d_in[3];
    const float* qkv1_w   = (const float*)d_in[4];
    const float* out1_w   = (const float*)d_in[5];
    const float* out1_b   = (const float*)d_in[6];
    const float* res1_w   = (const float*)d_in[7];
    const float* pe_w7    = (const float*)d_in[8];
    const float* pe_b7    = (const float*)d_in[9];
    const float* pe_w5    = (const float*)d_in[10];
    const float* pe_b5    = (const float*)d_in[11];
    const float* pe_w3    = (const float*)d_in[12];
    const float* pe_b3    = (const float*)d_in[13];
    const float* ln2_g    = (const float*)d_in[14];
    const float* ln2_b    = (const float*)d_in[15];
    const float* qkv2_w   = (const float*)d_in[16];
    const float* out2_w   = (const float*)d_in[17];
    const float* out2_b   = (const float*)d_in[18];
    const float* res2_w   = (const float*)d_in[19];

    cudaFuncSetAttribute(gemm_p, cudaFuncAttributeMaxDynamicSharedMemorySize, GP_SMEM);
    cudaFuncSetAttribute(fused_attn1_k, cudaFuncAttributeMaxDynamicSharedMemorySize, FA_SMEM);

    Ptrs p; get_ptrs(p);

    // launch 1
    build_h_k<<<(int)(((long)NH * C + 255) / 256), 256>>>(features, cls, p.h);
    // launches 2-4 (weight converts; #5 = ln_pad, #6 = qkv gemm -> profiled)
    wconvT_k<<<(QKVW * C + 255) / 256, 256>>>(qkv1_w, p.w1ah, p.w1al, C, QKVW);
    wconvT_k<<<(C * C + 255) / 256, 256>>>(out1_w, p.w2ah, p.w2al, C, C);
    wconvT_k<<<(QKVW * C + 255) / 256, 256>>>(qkv2_w, p.w1bh, p.w1bl, C, QKVW);

    nystrom_layer(p, p.h, ln1_g, ln1_b, p.w1ah, p.w1al, p.w2ah, p.w2al, out1_b, res1_w);

    wconvT_k<<<(C * C + 255) / 256, 256>>>(out2_w, p.w2bh, p.w2bl, C, C);

    ppeg_k<<<dim3(HW, HW), C>>>(p.h, p.h2, pe_w7, pe_b7, pe_w5, pe_b5, pe_w3, pe_b3);

    nystrom_layer(p, p.h2, ln2_g, ln2_b, p.w1bh, p.w1bl, p.w2bh, p.w2bl, out2_b, res2_w);

    cudaMemcpyAsync(d_out, p.h2, (size_t)out_size * sizeof(float),
                    cudaMemcpyDeviceToDevice);
}

// round 7
// speedup vs baseline: 2.7669x; 1.0648x over previous
#include <cuda_runtime.h>
#include <cuda_bf16.h>
#include <math.h>
#include <stdint.h>

typedef __nv_bfloat16 bf16;

// ---------------- problem constants ----------------
#define NH    22501
#define NFEAT 22400
#define HW    150
#define C     512
#define NP    22528
#define PADN  27
#define HEADS 8
#define DH    64
#define MM    256
#define LL    88
#define QKVW  1536
#define NSPLIT 8

// ---------------- fp32 scratch ----------------
__device__ float g_h   [(long)NH*C];
__device__ float g_h2  [(long)NH*C];
__device__ float g_a2  [HEADS*MM*MM];
__device__ float g_attn[(long)NP*C];
__device__ float g_outl[(long)NH*C];          // flash partials / outproj staging
__device__ float g_rowsum[HEADS*MM];
__device__ float g_colsum[HEADS*MM];
__device__ float g_fm[NSPLIT*HEADS*MM];
__device__ float g_fs[NSPLIT*HEADS*MM];
__device__ float g_scale[1];

// ---------------- bf16 hi/lo pair scratch ----------------
__device__ bf16 g_xph[(long)NP*C],     g_xpl[(long)NP*C];
__device__ bf16 g_qkvh[(long)NP*QKVW], g_qkvl[(long)NP*QKVW];
__device__ bf16 g_qlh[HEADS*MM*DH],    g_qll[HEADS*MM*DH];
__device__ bf16 g_klh[HEADS*MM*DH],    g_kll[HEADS*MM*DH];
__device__ bf16 g_a2h[HEADS*MM*MM],    g_a2l[HEADS*MM*MM];
__device__ bf16 g_zh [HEADS*MM*MM], g_zl [HEADS*MM*MM];
__device__ bf16 g_zth[HEADS*MM*MM], g_ztl[HEADS*MM*MM];
__device__ bf16 g_z2h[HEADS*MM*MM], g_z2l[HEADS*MM*MM];
__device__ bf16 g_z2th[HEADS*MM*MM], g_z2tl[HEADS*MM*MM];
__device__ bf16 g_xzh[HEADS*MM*MM], g_xzl[HEADS*MM*MM];
__device__ bf16 g_tah[HEADS*MM*MM], g_tal[HEADS*MM*MM];
__device__ bf16 g_tbh[HEADS*MM*MM], g_tbl[HEADS*MM*MM];
__device__ bf16 g_vth[(long)HEADS*DH*NP], g_vtl[(long)HEADS*DH*NP];
__device__ bf16 g_a3h[HEADS*DH*MM],    g_a3l[HEADS*DH*MM];
__device__ bf16 g_Wth[HEADS*DH*MM],    g_Wtl[HEADS*DH*MM];
__device__ bf16 g_ath[(long)NP*C],     g_atl[(long)NP*C];
__device__ bf16 g_w1ah[(long)QKVW*C],  g_w1al[(long)QKVW*C];
__device__ bf16 g_w2ah[(long)C*C],     g_w2al[(long)C*C];
__device__ bf16 g_w1bh[(long)QKVW*C],  g_w1bl[(long)QKVW*C];
__device__ bf16 g_w2bh[(long)C*C],     g_w2bl[(long)C*C];

// ---------------- small device helpers ----------------
__device__ __forceinline__ uint32_t smem_to_u32(const void* p) {
    uint32_t a;
    asm("{ .reg .u64 t; cvta.to.shared.u64 t, %1; cvt.u32.u64 %0, t; }"
        : "=r"(a) : "l"(p));
    return a;
}
__device__ __forceinline__ void ldsm4(uint32_t addr, uint32_t& r0, uint32_t& r1,
                                      uint32_t& r2, uint32_t& r3)
{
    asm volatile("ldmatrix.sync.aligned.m8n8.x4.shared.b16 {%0,%1,%2,%3}, [%4];"
                 : "=r"(r0), "=r"(r1), "=r"(r2), "=r"(r3) : "r"(addr));
}
__device__ __forceinline__ void mma_bf16(float* c, const uint32_t* a,
                                         uint32_t b0, uint32_t b1)
{
    asm volatile("mma.sync.aligned.m16n8k16.row.col.f32.bf16.bf16.f32 "
                 "{%0,%1,%2,%3},{%4,%5,%6,%7},{%8,%9},{%0,%1,%2,%3};"
                 : "+f"(c[0]), "+f"(c[1]), "+f"(c[2]), "+f"(c[3])
                 : "r"(a[0]), "r"(a[1]), "r"(a[2]), "r"(a[3]), "r"(b0), "r"(b1));
}
__device__ __forceinline__ void cpa16(uint32_t dst, const void* src, int sz)
{
    asm volatile("cp.async.cg.shared.global [%0], [%1], 16, %2;"
                 :: "r"(dst), "l"(src), "r"(sz));
}
__device__ __forceinline__ uint32_t pack2(float a, float b)   // a->low, b->high
{
    uint32_t r;
    asm("cvt.rn.bf16x2.f32 %0, %1, %2;" : "=r"(r) : "f"(b), "f"(a));
    return r;
}
__device__ __forceinline__ void split_bf(float x, float& hi, float& lo)
{
    hi = __bfloat162float(__float2bfloat16(x));
    lo = x - hi;
}
__device__ __forceinline__ float pairval(const bf16* h, const bf16* l, long i)
{
    return __bfloat162float(h[i]) + __bfloat162float(l[i]);
}

// =======================================================================
// bf16x3 GEMM, operands pre-split; B always [N,K]. cp.async 3-stage.
// Tile 128x64x32, 256 threads, 8 warps (4m x 2n).
// =======================================================================
#define RS      80
#define AH_OFF  0
#define AL_OFF  10240
#define BH_OFF  20480
#define BL_OFF  25600
#define STAGE   30720
#define GP_SMEM (3 * STAGE)

struct EpiOut {
    float* f; float falpha; int ldf; long sF;
    bf16 *ph, *pl; float palpha; int ldp; long sP;
    bf16 *th, *tl; float talpha, tdiag; int ldt; long sT;
    const float* resid;
    const float* bias;
};

__global__ void __launch_bounds__(256)
gemm_p(const bf16* __restrict__ Ah, const bf16* __restrict__ Al,
       const bf16* __restrict__ Bh, const bf16* __restrict__ Bl,
       int M, int K, int lda, int ldb, long sA, long sB,
       EpiOut ep, int ksplit)
{
    extern __shared__ __align__(16) char sm[];
    const uint32_t sb0 = smem_to_u32(sm);
    const int tid = threadIdx.x, warp = tid >> 5, lane = tid & 31;
    const int wm = warp & 3, wn = warp >> 2;

    const int z = blockIdx.z;
    const int batch = z / ksplit;
    const int split = z - batch * ksplit;
    Ah += (long)batch * sA;  Al += (long)batch * sA;
    Bh += (long)batch * sB;  Bl += (long)batch * sB;

    const int row0 = blockIdx.y * 128, col0 = blockIdx.x * 64;
    const int kchunk = K / ksplit, kbase = split * kchunk, nch = kchunk >> 5;

    float acc[2][4][4];
    #pragma unroll
    for (int i = 0; i < 2; i++)
        #pragma unroll
        for (int j = 0; j < 4; j++)
            #pragma unroll
            for (int q = 0; q < 4; q++) acc[i][j][q] = 0.f;

    auto issue = [&](int it) {
        const int stg = it % 3;
        const uint32_t sb = sb0 + stg * STAGE;
        const int kc = kbase + it * 32;
        #pragma unroll
        for (int rep = 0; rep < 2; rep++) {
            int c = tid + rep * 256;
            int row = c >> 2, seg = c & 3;
            int gm = row0 + row;
            long go = (long)gm * lda + kc + seg * 8;
            int sz = (gm < M) ? 16 : 0;
            cpa16(sb + AH_OFF + row * RS + seg * 16, Ah + go, sz);
            cpa16(sb + AL_OFF + row * RS + seg * 16, Al + go, sz);
        }
        {
            int n = tid >> 2, seg = tid & 3;
            long go = (long)(col0 + n) * ldb + kc + seg * 8;
            cpa16(sb + BH_OFF + n * RS + seg * 16, Bh + go, 16);
            cpa16(sb + BL_OFF + n * RS + seg * 16, Bl + go, 16);
        }
        asm volatile("cp.async.commit_group;");
    };

    const int rsel = (lane & 7) + ((lane >> 3) & 1) * 8;
    const int ksel = ((lane >> 4) & 1) * 16;
    auto do_mma = [&](int stg) {
        uint32_t sb = sb0 + stg * STAGE;
        #pragma unroll
        for (int kk = 0; kk < 2; kk++) {
            uint32_t ah[2][4], al[2][4], bh[4][2], bl[4][2];
            #pragma unroll
            for (int mt = 0; mt < 2; mt++) {
                uint32_t ad = sb + AH_OFF + (wm * 32 + mt * 16 + rsel) * RS + kk * 32 + ksel;
                ldsm4(ad, ah[mt][0], ah[mt][1], ah[mt][2], ah[mt][3]);
                ldsm4(ad + (AL_OFF - AH_OFF), al[mt][0], al[mt][1], al[mt][2], al[mt][3]);
            }
            #pragma unroll
            for (int np = 0; np < 2; np++) {
                uint32_t bd = sb + BH_OFF + (wn * 32 + np * 16 + rsel) * RS + kk * 32 + ksel;
                uint32_t q0, q1, q2, q3;
                ldsm4(bd, q0, q1, q2, q3);
                bh[2*np][0] = q0; bh[2*np][1] = q2;
                bh[2*np+1][0] = q1; bh[2*np+1][1] = q3;
                ldsm4(bd + (BL_OFF - BH_OFF), q0, q1, q2, q3);
                bl[2*np][0] = q0; bl[2*np][1] = q2;
                bl[2*np+1][0] = q1; bl[2*np+1][1] = q3;
            }
            #pragma unroll
            for (int mt = 0; mt < 2; mt++)
                #pragma unroll
                for (int nt = 0; nt < 4; nt++) {
                    mma_bf16(acc[mt][nt], ah[mt], bh[nt][0], bh[nt][1]);
                    mma_bf16(acc[mt][nt], ah[mt], bl[nt][0], bl[nt][1]);
                    mma_bf16(acc[mt][nt], al[mt], bh[nt][0], bh[nt][1]);
                }
        }
    };

    issue(0);
    if (nch > 1) issue(1);
    for (int it = 0; it < nch; it++) {
        if (it + 1 < nch) asm volatile("cp.async.wait_group 1;");
        else              asm volatile("cp.async.wait_group 0;");
        __syncthreads();
        if (it + 2 < nch) issue(it + 2);
        do_mma(it % 3);
    }

    // ---- epilogue ----
    const int er = lane >> 2, eq = lane & 3;
    float* F  = ep.f  ? ep.f  + (long)z     * ep.sF : (float*)0;
    bf16* Ph  = ep.ph ? ep.ph + (long)batch * ep.sP : (bf16*)0;
    bf16* Pl  = ep.pl ? ep.pl + (long)batch * ep.sP : (bf16*)0;
    bf16* Th  = ep.th ? ep.th + (long)batch * ep.sT : (bf16*)0;
    bf16* Tl  = ep.tl ? ep.tl + (long)batch * ep.sT : (bf16*)0;

    #pragma unroll
    for (int mt = 0; mt < 2; mt++)
        #pragma unroll
        for (int nt = 0; nt < 4; nt++) {
            int gr0 = row0 + wm * 32 + mt * 16 + er;
            int gc  = col0 + wn * 32 + nt * 8 + 2 * eq;
            #pragma unroll
            for (int half = 0; half < 2; half++) {
                int gr = gr0 + 8 * half;
                if (gr >= M) continue;
                float va = acc[mt][nt][2 * half], vb = acc[mt][nt][2 * half + 1];
                if (F) {
                    float o0 = ep.falpha * va, o1 = ep.falpha * vb;
                    if (ep.bias)  { o0 += ep.bias[gc]; o1 += ep.bias[gc + 1]; }
                    if (ep.resid) {
                        o0 += ep.resid[(long)gr * ep.ldf + gc];
                        o1 += ep.resid[(long)gr * ep.ldf + gc + 1];
                    }
                    *reinterpret_cast<float2*>(F + (long)gr * ep.ldf + gc) =
                        make_float2(o0, o1);
                }
                if (Ph) {
                    float s0 = ep.palpha * va, s1 = ep.palpha * vb;
                    float h0, l0, h1, l1;
                    split_bf(s0, h0, l0); split_bf(s1, h1, l1);
                    *reinterpret_cast<uint32_t*>(Ph + (long)gr * ep.ldp + gc) = pack2(h0, h1);
                    *reinterpret_cast<uint32_t*>(Pl + (long)gr * ep.ldp + gc) = pack2(l0, l1);
                }
                if (Th) {
                    #pragma unroll
                    for (int j = 0; j < 2; j++) {
                        int cc = gc + j;
                        float v = (j == 0) ? va : vb;
                        float s = ep.talpha * v + ((gr == cc) ? ep.tdiag : 0.f);
                        float hi, lo; split_bf(s, hi, lo);
                        Th[(long)cc * ep.ldt + gr] = __float2bfloat16(hi);
                        Tl[(long)cc * ep.ldt + gr] = __float2bfloat16(lo);
                    }
                }
            }
        }
}

static EpiOut epi0() { EpiOut e{}; return e; }
static void gemmP(const bf16* Ah, const bf16* Al, const bf16* Bh, const bf16* Bl,
                  int M, int N, int K, int lda, int ldb, long sA, long sB,
                  int batch, int ksplit, EpiOut ep)
{
    dim3 g(N / 64, (M + 127) / 128, batch * ksplit), b(256);
    gemm_p<<<g, b, GP_SMEM>>>(Ah, Al, Bh, Bl, M, K, lda, ldb, sA, sB, ep, ksplit);
}

// =======================================================================
// flash-fused S3 path: a3v = softmax(ql @ k^T) @ v, split over NP.
// Per CTA: 128 landmark rows, one head, one NP-split. 4 warps.
// =======================================================================
#define FL_RS   144
#define FL_QH   0
#define FL_QL   18432
#define FL_K(b) (36864 + (b) * 18432)    // hi; lo at +9216
#define FL_V(b) (73728 + (b) * 18432)    // hi; lo at +9216
#define FL_PH   110592
#define FL_PL   129024
#define FL_SMEM 147456
#define FL_NCH  ((NP / NSPLIT) / 64)     // 44

__global__ void __launch_bounds__(128)
flash3_k(const bf16* __restrict__ qlh, const bf16* __restrict__ qll,
         const bf16* __restrict__ qkvh, const bf16* __restrict__ qkvl,
         const bf16* __restrict__ vth, const bf16* __restrict__ vtl,
         float* __restrict__ pO, float* __restrict__ pm, float* __restrict__ ps)
{
    extern __shared__ __align__(16) char sm[];
    const uint32_t sb = smem_to_u32(sm);
    const int tid = threadIdx.x, warp = tid >> 5, lane = tid & 31;
    const int split = blockIdx.x, rowHalf = blockIdx.y, head = blockIdx.z;
    const int tb0 = split * (NP / NSPLIT);

    // ---- load Q tile (128 landmark rows) ----
    const bf16* Qh = qlh + ((long)head * MM + rowHalf * 128) * DH;
    const bf16* Ql = qll + ((long)head * MM + rowHalf * 128) * DH;
    #pragma unroll
    for (int i = 0; i < 8; i++) {
        int s = tid + 128 * i;            // 0..1023
        int r = s >> 3, seg = s & 7;
        long go = (long)r * DH + seg * 8;
        cpa16(sb + FL_QH + r * FL_RS + seg * 16, Qh + go, 16);
        cpa16(sb + FL_QL + r * FL_RS + seg * 16, Ql + go, 16);
    }

    const bf16* Kh = qkvh + head * DH + 512;
    const bf16* Kl = qkvl + head * DH + 512;
    const bf16* Vh = vth + (long)head * DH * NP;
    const bf16* Vl = vtl + (long)head * DH * NP;

    auto kissue = [&](int j) {
        int buf = j & 1;
        int tb = tb0 + j * 64;
        uint32_t kb = sb + FL_K(buf);
        uint32_t vb = sb + FL_V(buf);
        #pragma unroll
        for (int i = 0; i < 4; i++) {
            int s = tid + 128 * i;        // 0..511
            int r = s >> 3, seg = s & 7;
            long gk = (long)(tb + r) * QKVW + seg * 8;
            cpa16(kb + r * FL_RS + seg * 16, Kh + gk, 16);
            cpa16(kb + 9216 + r * FL_RS + seg * 16, Kl + gk, 16);
            long gv = (long)r * NP + tb + seg * 8;
            cpa16(vb + r * FL_RS + seg * 16, Vh + gv, 16);
            cpa16(vb + 9216 + r * FL_RS + seg * 16, Vl + gv, 16);
        }
        asm volatile("cp.async.commit_group;");
    };
    kissue(0);      // group0 = Q + chunk0
    kissue(1);

    const int rsel = (lane & 7) + ((lane >> 3) & 1) * 8;
    const int ksel = ((lane >> 4) & 1) * 16;
    const int er = lane >> 2, eq = lane & 3;

    float m_run[4] = {-1e30f, -1e30f, -1e30f, -1e30f};
    float s_run[4] = {0.f, 0.f, 0.f, 0.f};
    float oacc[2][8][4];
    #pragma unroll
    for (int a = 0; a < 2; a++)
        #pragma unroll
        for (int b = 0; b < 8; b++)
            #pragma unroll
            for (int c = 0; c < 4; c++) oacc[a][b][c] = 0.f;

    for (int j = 0; j < FL_NCH; j++) {
        if (j + 1 < FL_NCH) asm volatile("cp.async.wait_group 1;");
        else                asm volatile("cp.async.wait_group 0;");
        __syncthreads();
        uint32_t kb = sb + FL_K(j & 1);
        uint32_t vb = sb + FL_V(j & 1);

        // ---- S = Q @ K^T ----
        float sacc[2][8][4];
        #pragma unroll
        for (int a = 0; a < 2; a++)
            #pragma unroll
            for (int b = 0; b < 8; b++)
                #pragma unroll
                for (int c = 0; c < 4; c++) sacc[a][b][c] = 0.f;

        #pragma unroll
        for (int k16 = 0; k16 < 4; k16++) {
            uint32_t ah[2][4], al[2][4];
            #pragma unroll
            for (int mt = 0; mt < 2; mt++) {
                uint32_t ad = sb + FL_QH + (warp * 32 + mt * 16 + rsel) * FL_RS + k16 * 32 + ksel;
                ldsm4(ad, ah[mt][0], ah[mt][1], ah[mt][2], ah[mt][3]);
                ldsm4(ad + (FL_QL - FL_QH), al[mt][0], al[mt][1], al[mt][2], al[mt][3]);
            }
            #pragma unroll
            for (int n16 = 0; n16 < 4; n16++) {
                uint32_t bd = kb + (n16 * 16 + rsel) * FL_RS + k16 * 32 + ksel;
                uint32_t q0, q1, q2, q3, p0, p1, p2, p3;
                ldsm4(bd, q0, q1, q2, q3);
                ldsm4(bd + 9216, p0, p1, p2, p3);
                #pragma unroll
                for (int mt = 0; mt < 2; mt++) {
                    mma_bf16(sacc[mt][2*n16],   ah[mt], q0, q2);
                    mma_bf16(sacc[mt][2*n16],   ah[mt], p0, p2);
                    mma_bf16(sacc[mt][2*n16],   al[mt], q0, q2);
                    mma_bf16(sacc[mt][2*n16+1], ah[mt], q1, q3);
                    mma_bf16(sacc[mt][2*n16+1], ah[mt], p1, p3);
                    mma_bf16(sacc[mt][2*n16+1], al[mt], q1, q3);
                }
            }
        }

        // ---- online softmax update + P pair to smem ----
        #pragma unroll
        for (int mt = 0; mt < 2; mt++) {
            float cm0 = -1e30f, cm1 = -1e30f;
            #pragma unroll
            for (int nt = 0; nt < 8; nt++) {
                cm0 = fmaxf(cm0, fmaxf(sacc[mt][nt][0], sacc[mt][nt][1]));
                cm1 = fmaxf(cm1, fmaxf(sacc[mt][nt][2], sacc[mt][nt][3]));
            }
            #pragma unroll
            for (int o = 1; o <= 2; o <<= 1) {
                cm0 = fmaxf(cm0, __shfl_xor_sync(0xffffffffu, cm0, o));
                cm1 = fmaxf(cm1, __shfl_xor_sync(0xffffffffu, cm1, o));
            }
            float mn0 = fmaxf(m_run[2*mt],     cm0);
            float mn1 = fmaxf(m_run[2*mt + 1], cm1);
            float sc0 = __expf(m_run[2*mt]     - mn0);
            float sc1 = __expf(m_run[2*mt + 1] - mn1);
            m_run[2*mt] = mn0; m_run[2*mt + 1] = mn1;
            float ls0 = 0.f, ls1 = 0.f;
            int pr = warp * 32 + mt * 16 + er;
            #pragma unroll
            for (int nt = 0; nt < 8; nt++) {
                float e0 = __expf(sacc[mt][nt][0] - mn0);
                float e1 = __expf(sacc[mt][nt][1] - mn0);
                float e2 = __expf(sacc[mt][nt][2] - mn1);
                float e3 = __expf(sacc[mt][nt][3] - mn1);
                ls0 += e0 + e1; ls1 += e2 + e3;
                oacc[mt][nt][0] *= sc0; oacc[mt][nt][1] *= sc0;
                oacc[mt][nt][2] *= sc1; oacc[mt][nt][3] *= sc1;
                int col = nt * 8 + 2 * eq;
                float h0, l0, h1, l1;
                split_bf(e0, h0, l0); split_bf(e1, h1, l1);
                *reinterpret_cast<uint32_t*>(sm + FL_PH + pr * FL_RS + col * 2) = pack2(h0, h1);
                *reinterpret_cast<uint32_t*>(sm + FL_PL + pr * FL_RS + col * 2) = pack2(l0, l1);
                split_bf(e2, h0, l0); split_bf(e3, h1, l1);
                *reinterpret_cast<uint32_t*>(sm + FL_PH + (pr + 8) * FL_RS + col * 2) = pack2(h0, h1);
                *reinterpret_cast<uint32_t*>(sm + FL_PL + (pr + 8) * FL_RS + col * 2) = pack2(l0, l1);
            }
            #pragma unroll
            for (int o = 1; o <= 2; o <<= 1) {
                ls0 += __shfl_xor_sync(0xffffffffu, ls0, o);
                ls1 += __shfl_xor_sync(0xffffffffu, ls1, o);
            }
            s_run[2*mt]     = s_run[2*mt]     * sc0 + ls0;
            s_run[2*mt + 1] = s_run[2*mt + 1] * sc1 + ls1;
        }
        __syncthreads();   // P visible; K-phase reads done

        // ---- O += P @ V ----
        #pragma unroll
        for (int k16 = 0; k16 < 4; k16++) {
            uint32_t ph[2][4], pl[2][4];
            #pragma unroll
            for (int mt = 0; mt < 2; mt++) {
                uint32_t ad = sb + FL_PH + (warp * 32 + mt * 16 + rsel) * FL_RS + k16 * 32 + ksel;
                ldsm4(ad, ph[mt][0], ph[mt][1], ph[mt][2], ph[mt][3]);
                ldsm4(ad + (FL_PL - FL_PH), pl[mt][0], pl[mt][1], pl[mt][2], pl[mt][3]);
            }
            #pragma unroll
            for (int n16 = 0; n16 < 4; n16++) {
                uint32_t bd = vb + (n16 * 16 + rsel) * FL_RS + k16 * 32 + ksel;
                uint32_t q0, q1, q2, q3, r0, r1, r2, r3;
                ldsm4(bd, q0, q1, q2, q3);
                ldsm4(bd + 9216, r0, r1, r2, r3);
                #pragma unroll
                for (int mt = 0; mt < 2; mt++) {
                    mma_bf16(oacc[mt][2*n16],   ph[mt], q0, q2);
                    mma_bf16(oacc[mt][2*n16],   ph[mt], r0, r2);
                    mma_bf16(oacc[mt][2*n16],   pl[mt], q0, q2);
                    mma_bf16(oacc[mt][2*n16+1], ph[mt], q1, q3);
                    mma_bf16(oacc[mt][2*n16+1], ph[mt], r1, r3);
                    mma_bf16(oacc[mt][2*n16+1], pl[mt], q1, q3);
                }
            }
        }
        __syncthreads();   // V reads done before overwrite
        if (j + 2 < FL_NCH) kissue(j + 2);
    }

    // ---- write partials ----
    const int base = (split * HEADS + head) * MM + rowHalf * 128;
    #pragma unroll
    for (int mt = 0; mt < 2; mt++) {
        int r0 = base + warp * 32 + mt * 16 + er;
        #pragma unroll
        for (int nt = 0; nt < 8; nt++) {
            int d = nt * 8 + 2 * eq;
            *reinterpret_cast<float2*>(pO + (long)r0 * DH + d) =
                make_float2(oacc[mt][nt][0], oacc[mt][nt][1]);
            *reinterpret_cast<float2*>(pO + (long)(r0 + 8) * DH + d) =
                make_float2(oacc[mt][nt][2], oacc[mt][nt][3]);
        }
        if (eq == 0) {
            pm[r0] = m_run[2*mt];     ps[r0] = s_run[2*mt];
            pm[r0 + 8] = m_run[2*mt + 1]; ps[r0 + 8] = s_run[2*mt + 1];
        }
    }
}

// merge 8 splits -> a3v^T pair [head][d][m]
__global__ void flash_merge_k(const float* __restrict__ pO, const float* __restrict__ pm,
                              const float* __restrict__ ps,
                              bf16* __restrict__ oh, bf16* __restrict__ ol)
{
    int row = blockIdx.x, head = blockIdx.y, d = threadIdx.x;
    float mx = -1e30f;
    #pragma unroll
    for (int i = 0; i < NSPLIT; i++)
        mx = fmaxf(mx, pm[(i * HEADS + head) * MM + row]);
    float den = 0.f, acc = 0.f;
    #pragma unroll
    for (int i = 0; i < NSPLIT; i++) {
        int r = (i * HEADS + head) * MM + row;
        float w = __expf(pm[r] - mx);
        den += w * ps[r];
        acc += w * pO[(long)r * DH + d];
    }
    float v = acc / den;
    float hi, lo; split_bf(v, hi, lo);
    long o = ((long)head << 14) + d * MM + row;
    oh[o] = __float2bfloat16(hi);
    ol[o] = __float2bfloat16(lo);
}

// =======================================================================
// fused S1 -> softmax -> O1 (unchanged from R6)
// =======================================================================
#define FA_RS1  144
#define FA_AH   0
#define FA_AL   9216
#define FA_BH   18432
#define FA_BL   55296
#define FA_PH   0
#define FA_PL   33792
#define FA_WS   67584
#define FA_WST  10240
#define FA_SMEM 98304

__global__ void __launch_bounds__(128)
fused_attn1_k(const bf16* __restrict__ qh, const bf16* __restrict__ ql_,
              const bf16* __restrict__ klh, const bf16* __restrict__ kll,
              const bf16* __restrict__ Wth, const bf16* __restrict__ Wtl,
              float* __restrict__ attn)
{
    extern __shared__ __align__(16) char sm[];
    const uint32_t sb = smem_to_u32(sm);
    const int tid = threadIdx.x, warp = tid >> 5, lane = tid & 31;
    const int row0 = blockIdx.x * 64;
    const int head = blockIdx.y;

    const bf16* qsh = qh  + (long)row0 * QKVW + head * DH;
    const bf16* qsl = ql_ + (long)row0 * QKVW + head * DH;
    #pragma unroll
    for (int i = 0; i < 4; i++) {
        int s = tid + 128 * i;
        int r = s >> 3, seg = s & 7;
        long go = (long)r * QKVW + seg * 8;
        cpa16(sb + FA_AH + r * FA_RS1 + seg * 16, qsh + go, 16);
        cpa16(sb + FA_AL + r * FA_RS1 + seg * 16, qsl + go, 16);
    }
    const bf16* ksh = klh + (long)head * MM * DH;
    const bf16* ksl = kll + (long)head * MM * DH;
    #pragma unroll
    for (int i = 0; i < 16; i++) {
        int s = tid + 128 * i;
        int r = s >> 3, seg = s & 7;
        long go = (long)r * DH + seg * 8;
        cpa16(sb + FA_BH + r * FA_RS1 + seg * 16, ksh + go, 16);
        cpa16(sb + FA_BL + r * FA_RS1 + seg * 16, ksl + go, 16);
    }
    asm volatile("cp.async.commit_group;");
    asm volatile("cp.async.wait_group 0;");
    __syncthreads();

    const int rsel = (lane & 7) + ((lane >> 3) & 1) * 8;
    const int ksel = ((lane >> 4) & 1) * 16;
    float sacc[32][4];
    #pragma unroll
    for (int i = 0; i < 32; i++)
        #pragma unroll
        for (int j = 0; j < 4; j++) sacc[i][j] = 0.f;

    #pragma unroll
    for (int k16 = 0; k16 < 4; k16++) {
        uint32_t ah[4], al[4];
        uint32_t ad = sb + FA_AH + (warp * 16 + rsel) * FA_RS1 + k16 * 32 + ksel;
        ldsm4(ad, ah[0], ah[1], ah[2], ah[3]);
        ldsm4(ad + (FA_AL - FA_AH), al[0], al[1], al[2], al[3]);
        #pragma unroll
        for (int n16 = 0; n16 < 16; n16++) {
            uint32_t bd = sb + FA_BH + (n16 * 16 + rsel) * FA_RS1 + k16 * 32 + ksel;
            uint32_t q0, q1, q2, q3, p0, p1, p2, p3;
            ldsm4(bd, q0, q1, q2, q3);
            ldsm4(bd + (FA_BL - FA_BH), p0, p1, p2, p3);
            mma_bf16(sacc[2*n16],   ah, q0, q2);
            mma_bf16(sacc[2*n16],   ah, p0, p2);
            mma_bf16(sacc[2*n16],   al, q0, q2);
            mma_bf16(sacc[2*n16+1], ah, q1, q3);
            mma_bf16(sacc[2*n16+1], ah, p1, p3);
            mma_bf16(sacc[2*n16+1], al, q1, q3);
        }
    }

    float mx0 = -1e30f, mx1 = -1e30f;
    #pragma unroll
    for (int nt = 0; nt < 32; nt++) {
        #pragma unroll
        for (int j = 0; j < 4; j++) sacc[nt][j] *= 0.125f;
        mx0 = fmaxf(mx0, fmaxf(sacc[nt][0], sacc[nt][1]));
        mx1 = fmaxf(mx1, fmaxf(sacc[nt][2], sacc[nt][3]));
    }
    #pragma unroll
    for (int o = 1; o <= 2; o <<= 1) {
        mx0 = fmaxf(mx0, __shfl_xor_sync(0xffffffffu, mx0, o));
        mx1 = fmaxf(mx1, __shfl_xor_sync(0xffffffffu, mx1, o));
    }
    float sm0 = 0.f, sm1 = 0.f;
    #pragma unroll
    for (int nt = 0; nt < 32; nt++) {
        sacc[nt][0] = __expf(sacc[nt][0] - mx0);
        sacc[nt][1] = __expf(sacc[nt][1] - mx0);
        sacc[nt][2] = __expf(sacc[nt][2] - mx1);
        sacc[nt][3] = __expf(sacc[nt][3] - mx1);
        sm0 += sacc[nt][0] + sacc[nt][1];
        sm1 += sacc[nt][2] + sacc[nt][3];
    }
    #pragma unroll
    for (int o = 1; o <= 2; o <<= 1) {
        sm0 += __shfl_xor_sync(0xffffffffu, sm0, o);
        sm1 += __shfl_xor_sync(0xffffffffu, sm1, o);
    }
    __syncthreads();

    const bf16* Wsh = Wth + (long)head * DH * MM;
    const bf16* Wsl = Wtl + (long)head * DH * MM;
    auto wissue = [&](int it) {
        int stg = it % 3;
        uint32_t base = sb + FA_WS + stg * FA_WST;
        #pragma unroll
        for (int i = 0; i < 2; i++) {
            int s = tid + 128 * i;
            int r = s >> 2, seg = s & 3;
            long go = (long)r * MM + it * 32 + seg * 8;
            cpa16(base + r * 80 + seg * 16, Wsh + go, 16);
            cpa16(base + 5120 + r * 80 + seg * 16, Wsl + go, 16);
        }
        asm volatile("cp.async.commit_group;");
    };
    wissue(0); wissue(1);

    {
        int pr = warp * 16 + (lane >> 2);
        int pc = (lane & 3) * 2;
        #pragma unroll
        for (int nt = 0; nt < 32; nt++) {
            int col = nt * 8 + pc;
            float h0, l0, h1, l1;
            split_bf(sacc[nt][0], h0, l0); split_bf(sacc[nt][1], h1, l1);
            *reinterpret_cast<uint32_t*>(sm + FA_PH + pr * 528 + col * 2) = pack2(h0, h1);
            *reinterpret_cast<uint32_t*>(sm + FA_PL + pr * 528 + col * 2) = pack2(l0, l1);
            split_bf(sacc[nt][2], h0, l0); split_bf(sacc[nt][3], h1, l1);
            *reinterpret_cast<uint32_t*>(sm + FA_PH + (pr + 8) * 528 + col * 2) = pack2(h0, h1);
            *reinterpret_cast<uint32_t*>(sm + FA_PL + (pr + 8) * 528 + col * 2) = pack2(l0, l1);
        }
    }
    __syncthreads();

    float oacc[8][4];
    #pragma unroll
    for (int i = 0; i < 8; i++)
        #pragma unroll
        for (int j = 0; j < 4; j++) oacc[i][j] = 0.f;

    for (int it = 0; it < 8; it++) {
        if (it < 7) asm volatile("cp.async.wait_group 1;");
        else        asm volatile("cp.async.wait_group 0;");
        __syncthreads();
        if (it + 2 < 8) wissue(it + 2);
        uint32_t wb = sb + FA_WS + (it % 3) * FA_WST;
        #pragma unroll
        for (int k16 = 0; k16 < 2; k16++) {
            int gk = it * 2 + k16;
            uint32_t ph[4], pl[4];
            uint32_t ad = sb + FA_PH + (warp * 16 + rsel) * 528 + gk * 32 + ksel;
            ldsm4(ad, ph[0], ph[1], ph[2], ph[3]);
            ldsm4(ad + (FA_PL - FA_PH), pl[0], pl[1], pl[2], pl[3]);
            #pragma unroll
            for (int n16 = 0; n16 < 4; n16++) {
                uint32_t bd = wb + (n16 * 16 + rsel) * 80 + k16 * 32 + ksel;
                uint32_t q0, q1, q2, q3, r0, r1, r2, r3;
                ldsm4(bd, q0, q1, q2, q3);
                ldsm4(bd + 5120, r0, r1, r2, r3);
                mma_bf16(oacc[2*n16],   ph, q0, q2);
                mma_bf16(oacc[2*n16],   ph, r0, r2);
                mma_bf16(oacc[2*n16],   pl, q0, q2);
                mma_bf16(oacc[2*n16+1], ph, q1, q3);
                mma_bf16(oacc[2*n16+1], ph, r1, r3);
                mma_bf16(oacc[2*n16+1], pl, q1, q3);
            }
        }
    }

    float inv0 = 1.f / sm0, inv1 = 1.f / sm1;
    int orow = row0 + warp * 16 + (lane >> 2);
    int ocol = head * DH + (lane & 3) * 2;
    #pragma unroll
    for (int nt = 0; nt < 8; nt++) {
        int col = ocol + nt * 8;
        *reinterpret_cast<float2*>(attn + (long)orow * C + col) =
            make_float2(oacc[nt][0] * inv0, oacc[nt][1] * inv0);
        *reinterpret_cast<float2*>(attn + (long)(orow + 8) * C + col) =
            make_float2(oacc[nt][2] * inv1, oacc[nt][3] * inv1);
    }
}

// =======================================================================
// auxiliary kernels
// =======================================================================

__global__ void wconvT_k(const float* __restrict__ w, bf16* __restrict__ th,
                         bf16* __restrict__ tl, int K, int N)
{
    int i = blockIdx.x * 256 + threadIdx.x;
    if (i >= N * K) return;
    int n = i / K, k = i - n * K;
    float v = w[(long)k * N + n];
    float hi, lo; split_bf(v, hi, lo);
    th[i] = __float2bfloat16(hi);
    tl[i] = __float2bfloat16(lo);
}

__global__ void build_h_k(const float* __restrict__ feat, const float* __restrict__ cls,
                          float* __restrict__ h)
{
    long i = (long)blockIdx.x * 256 + threadIdx.x;
    if (i >= (long)NH * C) return;
    long t = i >> 9;
    int  c = (int)(i & 511);
    float v;
    if (t == 0) v = cls[c];
    else {
        long r = t - 1;
        if (r >= NFEAT) r -= NFEAT;
        v = feat[r * C + c];
    }
    h[i] = v;
}

__global__ void ln_pad_k(const float* __restrict__ h, bf16* __restrict__ xh,
                         bf16* __restrict__ xl,
                         const float* __restrict__ g, const float* __restrict__ b)
{
    int t = blockIdx.x, c = threadIdx.x;
    long o = (long)t * C;
    if (t < PADN) {
        *reinterpret_cast<uint32_t*>(xh + o + 2 * c) = 0u;
        *reinterpret_cast<uint32_t*>(xl + o + 2 * c) = 0u;
        return;
    }
    const float* row = h + (long)(t - PADN) * C;
    float a1 = row[2 * c], a2 = row[2 * c + 1];
    __shared__ float red[256];
    red[c] = a1 + a2; __syncthreads();
    for (int s = 128; s > 0; s >>= 1) { if (c < s) red[c] += red[c + s]; __syncthreads(); }
    float mu = red[0] * (1.f / 512.f);
    __syncthreads();
    float d1 = a1 - mu, d2 = a2 - mu;
    red[c] = d1 * d1 + d2 * d2; __syncthreads();
    for (int s = 128; s > 0; s >>= 1) { if (c < s) red[c] += red[c + s]; __syncthreads(); }
    float inv = rsqrtf(red[0] * (1.f / 512.f) + 1e-5f);
    float v1 = d1 * inv * g[2 * c] + b[2 * c];
    float v2 = d2 * inv * g[2 * c + 1] + b[2 * c + 1];
    float h1, l1, h2, l2;
    split_bf(v1, h1, l1); split_bf(v2, h2, l2);
    *reinterpret_cast<uint32_t*>(xh + o + 2 * c) = pack2(h1, h2);
    *reinterpret_cast<uint32_t*>(xl + o + 2 * c) = pack2(l1, l2);
}

__global__ void landmarks_k(const bf16* __restrict__ qh, const bf16* __restrict__ ql_,
                            bf16* __restrict__ qlh, bf16* __restrict__ qll,
                            bf16* __restrict__ klh, bf16* __restrict__ kll)
{
    int d = threadIdx.x;
    int m = blockIdx.x & 255;
    int hh = blockIdx.x >> 8;
    long base = (long)(m * LL) * QKVW + hh * DH + d;
    float sq = 0.f, sk = 0.f;
    for (int j = 0; j < LL; j++) {
        long o = base + (long)j * QKVW;
        sq += pairval(qh, ql_, o);
        sk += pairval(qh, ql_, o + 512);
    }
    float vq = sq * (0.125f / (float)LL);
    float vk = sk * (1.f / (float)LL);
    int oi = (hh * MM + m) * DH + d;
    float hi, lo;
    split_bf(vq, hi, lo); qlh[oi] = __float2bfloat16(hi); qll[oi] = __float2bfloat16(lo);
    split_bf(vk, hi, lo); klh[oi] = __float2bfloat16(hi); kll[oi] = __float2bfloat16(lo);
}

__global__ void softmax256_k(const float* __restrict__ in, float* __restrict__ fout,
                             bf16* __restrict__ ph, bf16* __restrict__ pl, long nrows)
{
    long row = (long)blockIdx.x * 8 + threadIdx.y;
    if (row >= nrows) return;
    const float* r = in + row * 256;
    int lane = threadIdx.x;
    float v[8], m = -1e30f;
    #pragma unroll
    for (int i = 0; i < 8; i++) { v[i] = r[lane + 32 * i]; m = fmaxf(m, v[i]); }
    #pragma unroll
    for (int o = 16; o; o >>= 1) m = fmaxf(m, __shfl_xor_sync(0xffffffffu, m, o));
    float s = 0.f;
    #pragma unroll
    for (int i = 0; i < 8; i++) { v[i] = __expf(v[i] - m); s += v[i]; }
    #pragma unroll
    for (int o = 16; o; o >>= 1) s += __shfl_xor_sync(0xffffffffu, s, o);
    float inv = 1.f / s;
    #pragma unroll
    for (int i = 0; i < 8; i++) {
        float val = v[i] * inv;
        long o = row * 256 + lane + 32 * i;
        if (fout) fout[o] = val;
        float hi, lo; split_bf(val, hi, lo);
        ph[o] = __float2bfloat16(hi);
        pl[o] = __float2bfloat16(lo);
    }
}

__global__ void pinv_sums_k(const float* __restrict__ a2,
                            float* __restrict__ rs, float* __restrict__ cs)
{
    int hh = blockIdx.x, j = threadIdx.x;
    const float* X = a2 + (long)hh * MM * MM;
    float r = 0.f, c = 0.f;
    for (int k = 0; k < MM; k++) { r += fabsf(X[j * MM + k]); c += fabsf(X[k * MM + j]); }
    rs[hh * MM + j] = r; cs[hh * MM + j] = c;
}
__global__ void pinv_scale_k(const float* __restrict__ rs, const float* __restrict__ cs,
                             float* __restrict__ scale)
{
    __shared__ float m1[256], m2[256];
    float a = -1e30f, b = -1e30f;
    for (int i = threadIdx.x; i < HEADS * MM; i += 256) { a = fmaxf(a, rs[i]); b = fmaxf(b, cs[i]); }
    m1[threadIdx.x] = a; m2[threadIdx.x] = b; __syncthreads();
    for (int s = 128; s > 0; s >>= 1) {
        if (threadIdx.x < s) {
            m1[threadIdx.x] = fmaxf(m1[threadIdx.x], m1[threadIdx.x + s]);
            m2[threadIdx.x] = fmaxf(m2[threadIdx.x], m2[threadIdx.x + s]);
        }
        __syncthreads();
    }
    if (threadIdx.x == 0) scale[0] = 1.f / (m1[0] * m2[0]);
}
__global__ void pinv_init_k(const float* __restrict__ a2, const float* __restrict__ scale,
                            bf16* __restrict__ zph, bf16* __restrict__ zpl,
                            bf16* __restrict__ zth, bf16* __restrict__ ztl)
{
    long i = (long)blockIdx.x * 256 + threadIdx.x;
    if (i >= (long)HEADS * MM * MM) return;
    float s = scale[0];
    long hb = i & ~65535L;
    int r = (int)((i >> 8) & 255), c = (int)(i & 255);
    float vt = a2[i] * s;
    float vp = a2[hb + ((long)c << 8) + r] * s;
    float hi, lo;
    split_bf(vt, hi, lo); zth[i] = __float2bfloat16(hi); ztl[i] = __float2bfloat16(lo);
    split_bf(vp, hi, lo); zph[i] = __float2bfloat16(hi); zpl[i] = __float2bfloat16(lo);
}

__global__ void vT_k(const bf16* __restrict__ qh, const bf16* __restrict__ ql_,
                     bf16* __restrict__ vth, bf16* __restrict__ vtl)
{
    __shared__ bf16 tile[32][33];
    int t0 = blockIdx.x * 32;
    int head = blockIdx.y >> 1;
    int lopart = blockIdx.y & 1;
    int d0 = blockIdx.z * 32;
    const bf16* src = (lopart ? ql_ : qh) + 1024 + head * 64 + d0;
    bf16* dst = (lopart ? vtl : vth) + (long)head * 64 * NP + (long)d0 * NP;
    int tx = threadIdx.x, ty = threadIdx.y;
    #pragma unroll
    for (int i = 0; i < 4; i++)
        tile[ty + 8 * i][tx] = src[(long)(t0 + ty + 8 * i) * QKVW + tx];
    __syncthreads();
    #pragma unroll
    for (int i = 0; i < 4; i++)
        dst[(long)(ty + 8 * i) * NP + t0 + tx] = tile[tx][ty + 8 * i];
}

__global__ void conv_add_k(const bf16* __restrict__ qh, const bf16* __restrict__ ql_,
                           const float* __restrict__ rw, const float* __restrict__ attnf,
                           bf16* __restrict__ ah, bf16* __restrict__ al)
{
    int t = blockIdx.x, c = threadIdx.x;
    int hh = c >> 6;
    float acc = attnf[(long)t * C + c];
    #pragma unroll
    for (int k = 0; k < 33; k++) {
        int tt = t + k - 16;
        if ((unsigned)tt < (unsigned)NP)
            acc += pairval(qh, ql_, (long)tt * QKVW + 1024 + c) * rw[hh * 33 + k];
    }
    float hi, lo; split_bf(acc, hi, lo);
    long o = (long)t * C + c;
    ah[o] = __float2bfloat16(hi);
    al[o] = __float2bfloat16(lo);
}

__global__ void ppeg_k(const float* __restrict__ h, float* __restrict__ h2,
                       const float* __restrict__ w7, const float* __restrict__ b7,
                       const float* __restrict__ w5, const float* __restrict__ b5,
                       const float* __restrict__ w3, const float* __restrict__ b3)
{
    int x = blockIdx.x, y = blockIdx.y, c = threadIdx.x;
    if (x == 0 && y == 0) h2[c] = h[c];
    float acc = h[(long)(1 + y * HW + x) * C + c];
    #pragma unroll
    for (int ky = 0; ky < 7; ky++) {
        int yy = y + ky - 3; if (yy < 0 || yy >= HW) continue;
        #pragma unroll
        for (int kx = 0; kx < 7; kx++) {
            int xx = x + kx - 3; if (xx < 0 || xx >= HW) continue;
            acc += h[(long)(1 + yy * HW + xx) * C + c] * w7[c * 49 + ky * 7 + kx];
        }
    }
    #pragma unroll
    for (int ky = 0; ky < 5; ky++) {
        int yy = y + ky - 2; if (yy < 0 || yy >= HW) continue;
        #pragma unroll
        for (int kx = 0; kx < 5; kx++) {
            int xx = x + kx - 2; if (xx < 0 || xx >= HW) continue;
            acc += h[(long)(1 + yy * HW + xx) * C + c] * w5[c * 25 + ky * 5 + kx];
        }
    }
    #pragma unroll
    for (int ky = 0; ky < 3; ky++) {
        int yy = y + ky - 1; if (yy < 0 || yy >= HW) continue;
        #pragma unroll
        for (int kx = 0; kx < 3; kx++) {
            int xx = x + kx - 1; if (xx < 0 || xx >= HW) continue;
            acc += h[(long)(1 + yy * HW + xx) * C + c] * w3[c * 9 + ky * 3 + kx];
        }
    }
    acc += b7[c] + b5[c] + b3[c];
    h2[(long)(1 + y * HW + x) * C + c] = acc;
}

// ================= host orchestration =================
struct Ptrs {
    float *h, *h2, *a2, *attn, *outl, *rowsum, *colsum, *fm, *fs, *scale;
    bf16 *xph, *xpl, *qkvh, *qkvl, *qlh, *qll, *klh, *kll,
         *a2h, *a2l, *zh, *zl, *zth, *ztl, *z2h, *z2l, *z2th, *z2tl,
         *xzh, *xzl, *tah, *tal, *tbh, *tbl, *vth, *vtl,
         *a3h, *a3l, *Wth, *Wtl, *ath, *atl,
         *w1ah, *w1al, *w2ah, *w2al, *w1bh, *w1bl, *w2bh, *w2bl;
};
#define GSYM(f, s) cudaGetSymbolAddress((void**)&p.f, s)
static void get_ptrs(Ptrs& p)
{
    GSYM(h, g_h); GSYM(h2, g_h2); GSYM(a2, g_a2);
    GSYM(attn, g_attn); GSYM(outl, g_outl);
    GSYM(rowsum, g_rowsum); GSYM(colsum, g_colsum);
    GSYM(fm, g_fm); GSYM(fs, g_fs); GSYM(scale, g_scale);
    GSYM(xph, g_xph); GSYM(xpl, g_xpl); GSYM(qkvh, g_qkvh); GSYM(qkvl, g_qkvl);
    GSYM(qlh, g_qlh); GSYM(qll, g_qll); GSYM(klh, g_klh); GSYM(kll, g_kll);
    GSYM(a2h, g_a2h); GSYM(a2l, g_a2l);
    GSYM(zh, g_zh); GSYM(zl, g_zl); GSYM(zth, g_zth); GSYM(ztl, g_ztl);
    GSYM(z2h, g_z2h); GSYM(z2l, g_z2l); GSYM(z2th, g_z2th); GSYM(z2tl, g_z2tl);
    GSYM(xzh, g_xzh); GSYM(xzl, g_xzl);
    GSYM(tah, g_tah); GSYM(tal, g_tal); GSYM(tbh, g_tbh); GSYM(tbl, g_tbl);
    GSYM(vth, g_vth); GSYM(vtl, g_vtl); GSYM(a3h, g_a3h); GSYM(a3l, g_a3l);
    GSYM(Wth, g_Wth); GSYM(Wtl, g_Wtl); GSYM(ath, g_ath); GSYM(atl, g_atl);
    GSYM(w1ah, g_w1ah); GSYM(w1al, g_w1al); GSYM(w2ah, g_w2ah); GSYM(w2al, g_w2al);
    GSYM(w1bh, g_w1bh); GSYM(w1bl, g_w1bl); GSYM(w2bh, g_w2bh); GSYM(w2bl, g_w2bl);
}

static void nystrom_layer(Ptrs& p, float* h_io,
                          const float* ln_g, const float* ln_b,
                          const bf16* w1h, const bf16* w1l,
                          const bf16* w2h, const bf16* w2l,
                          const float* b_out, const float* res_w)
{
    const long MMh = (long)MM * MM;

    // 1) LN + pad -> xp pair
    ln_pad_k<<<NP, 256>>>(h_io, p.xph, p.xpl, ln_g, ln_b);

    // 2) qkv pair = xp @ wqkv
    { EpiOut e = epi0(); e.ph = p.qkvh; e.pl = p.qkvl; e.palpha = 1.f; e.ldp = QKVW;
      gemmP(p.xph, p.xpl, w1h, w1l, NP, QKVW, C, C, C, 0, 0, 1, 1, e); }

    // 3) landmarks + vT
    landmarks_k<<<HEADS * MM, DH>>>(p.qkvh, p.qkvl, p.qlh, p.qll, p.klh, p.kll);
    vT_k<<<dim3(NP / 32, HEADS * 2, 2), dim3(32, 8)>>>(p.qkvh, p.qkvl, p.vth, p.vtl);

    // 4) a2 = softmax(ql @ kl^T)
    { EpiOut e = epi0(); e.f = p.a2; e.falpha = 1.f; e.ldf = MM; e.sF = MMh;
      gemmP(p.qlh, p.qll, p.klh, p.kll, MM, MM, DH, DH, DH,
            (long)MM * DH, (long)MM * DH, HEADS, 1, e); }
    softmax256_k<<<(HEADS * MM + 7) / 8, dim3(32, 8)>>>(p.a2, p.a2, p.a2h, p.a2l, HEADS * MM);

    // 5) pinv
    pinv_sums_k<<<HEADS, 256>>>(p.a2, p.rowsum, p.colsum);
    pinv_scale_k<<<1, 256>>>(p.rowsum, p.colsum, p.scale);
    pinv_init_k<<<(int)((HEADS * MMh + 255) / 256), 256>>>(p.a2, p.scale,
                                                           p.zh, p.zl, p.zth, p.ztl);
    bf16 *zch = p.zh, *zcl = p.zl, *zcth = p.zth, *zctl = p.ztl;
    bf16 *znh = p.z2h, *znl = p.z2l, *znth = p.z2th, *zntl = p.z2tl;
    for (int it = 0; it < 6; it++) {
        { EpiOut e = epi0();
          e.ph = p.xzh; e.pl = p.xzl; e.palpha = 1.f; e.ldp = MM; e.sP = MMh;
          e.th = p.tah; e.tl = p.tal; e.talpha = -1.f; e.tdiag = 7.f; e.ldt = MM; e.sT = MMh;
          gemmP(p.a2h, p.a2l, zcth, zctl, MM, MM, MM, MM, MM, MMh, MMh, HEADS, 1, e); }
        { EpiOut e = epi0();
          e.th = p.tbh; e.tl = p.tbl; e.talpha = -1.f; e.tdiag = 15.f; e.ldt = MM; e.sT = MMh;
          gemmP(p.xzh, p.xzl, p.tah, p.tal, MM, MM, MM, MM, MM, MMh, MMh, HEADS, 1, e); }
        { EpiOut e = epi0();
          e.th = p.tah; e.tl = p.tal; e.talpha = -1.f; e.tdiag = 13.f; e.ldt = MM; e.sT = MMh;
          gemmP(p.xzh, p.xzl, p.tbh, p.tbl, MM, MM, MM, MM, MM, MMh, MMh, HEADS, 1, e); }
        { EpiOut e = epi0();
          e.ph = znh; e.pl = znl; e.palpha = 0.25f; e.ldp = MM; e.sP = MMh;
          e.th = znth; e.tl = zntl; e.talpha = 0.25f; e.tdiag = 0.f; e.ldt = MM; e.sT = MMh;
          gemmP(zch, zcl, p.tah, p.tal, MM, MM, MM, MM, MM, MMh, MMh, HEADS, 1, e); }
        bf16* t;
        t = zch; zch = znh; znh = t;   t = zcl; zcl = znl; znl = t;
        t = zcth; zcth = znth; znth = t; t = zctl; zctl = zntl; zntl = t;
    }

    // 6) flash-fused S3 -> softmax -> a3v
    flash3_k<<<dim3(NSPLIT, 2, HEADS), 128, FL_SMEM>>>(
        p.qlh, p.qll, p.qkvh, p.qkvl, p.vth, p.vtl, p.outl, p.fm, p.fs);
    flash_merge_k<<<dim3(MM, HEADS), DH>>>(p.outl, p.fm, p.fs, p.a3h, p.a3l);

    // 7) W^T pair = (z @ a3v)^T
    { EpiOut e = epi0(); e.th = p.Wth; e.tl = p.Wtl; e.talpha = 1.f; e.tdiag = 0.f;
      e.ldt = MM; e.sT = (long)DH * MM;
      gemmP(zch, zcl, p.a3h, p.a3l, MM, DH, MM, MM, MM, MMh, (long)DH * MM, HEADS, 1, e); }

    // 8) fused S1 -> softmax -> O1 -> attn fp32
    fused_attn1_k<<<dim3(NP / 64, HEADS), 128, FA_SMEM>>>(
        p.qkvh, p.qkvl, p.klh, p.kll, p.Wth, p.Wtl, p.attn);

    // 9) attn pair = attn + conv(v)
    conv_add_k<<<NP, C>>>(p.qkvh, p.qkvl, res_w, p.attn, p.ath, p.atl);

    // 10) h += attn[PADN:] @ wout + bias
    { EpiOut e = epi0(); e.f = h_io; e.falpha = 1.f; e.ldf = C;
      e.resid = h_io; e.bias = b_out;
      gemmP(p.ath + (long)PADN * C, p.atl + (long)PADN * C, w2h, w2l,
            NH, C, C, C, C, 0, 0, 1, 1, e); }
}

extern "C" void kernel_launch(void* const* d_in, const int* in_sizes, int n_in,
                              void* d_out, int out_size)
{
    const float* features = (const float*)d_in[0];
    const float* cls      = (const float*)d_in[1];
    const float* ln1_g    = (const float*)d_in[2];
    const float* ln1_b    = (const float*)d_in[3];
    const float* qkv1_w   = (const float*)d_in[4];
    const float* out1_w   = (const float*)d_in[5];
    const float* out1_b   = (const float*)d_in[6];
    const float* res1_w   = (const float*)d_in[7];
    const float* pe_w7    = (const float*)d_in[8];
    const float* pe_b7    = (const float*)d_in[9];
    const float* pe_w5    = (const float*)d_in[10];
    const float* pe_b5    = (const float*)d_in[11];
    const float* pe_w3    = (const float*)d_in[12];
    const float* pe_b3    = (const float*)d_in[13];
    const float* ln2_g    = (const float*)d_in[14];
    const float* ln2_b    = (const float*)d_in[15];
    const float* qkv2_w   = (const float*)d_in[16];
    const float* out2_w   = (const float*)d_in[17];
    const float* out2_b   = (const float*)d_in[18];
    const float* res2_w   = (const float*)d_in[19];

    cudaFuncSetAttribute(gemm_p, cudaFuncAttributeMaxDynamicSharedMemorySize, GP_SMEM);
    cudaFuncSetAttribute(fused_attn1_k, cudaFuncAttributeMaxDynamicSharedMemorySize, FA_SMEM);
    cudaFuncSetAttribute(flash3_k, cudaFuncAttributeMaxDynamicSharedMemorySize, FL_SMEM);

    Ptrs p; get_ptrs(p);

    build_h_k<<<(int)(((long)NH * C + 255) / 256), 256>>>(features, cls, p.h);
    wconvT_k<<<(QKVW * C + 255) / 256, 256>>>(qkv1_w, p.w1ah, p.w1al, C, QKVW);
    wconvT_k<<<(C * C + 255) / 256, 256>>>(out1_w, p.w2ah, p.w2al, C, C);
    wconvT_k<<<(QKVW * C + 255) / 256, 256>>>(qkv2_w, p.w1bh, p.w1bl, C, QKVW);

    nystrom_layer(p, p.h, ln1_g, ln1_b, p.w1ah, p.w1al, p.w2ah, p.w2al, out1_b, res1_w);

    wconvT_k<<<(C * C + 255) / 256, 256>>>(out2_w, p.w2bh, p.w2bl, C, C);

    ppeg_k<<<dim3(HW, HW), C>>>(p.h, p.h2, pe_w7, pe_b7, pe_w5, pe_b5, pe_w3, pe_b3);

    nystrom_layer(p, p.h2, ln2_g, ln2_b, p.w1bh, p.w1bl, p.w2bh, p.w2bl, out2_b, res2_w);

    cudaMemcpyAsync(d_out, p.h2, (size_t)out_size * sizeof(float),
                    cudaMemcpyDeviceToDevice);
}